// round 2
// baseline (speedup 1.0000x reference)
#include <cuda_runtime.h>
#include <cuda_bf16.h>
#include <math.h>

// Problem constants
#define B_   4
#define T_   4096
#define C_   512
#define S_   1024      // T/STRIDE
#define D_   1024
#define F_   4096
#define H_   8
#define DH_  128
#define L_   4
#define NTOK (B_ * S_)          // 4096
#define WIN_ 100                // WINDOW = 400/4
#define LFW_ 20                 // LOOKFWD = 80/4

// -------------------- scratch (static device globals; no allocation) --------
__device__ float g_h  [NTOK * D_];
__device__ float g_y  [NTOK * D_];
__device__ float g_q  [NTOK * D_];
__device__ float g_k  [NTOK * D_];
__device__ float g_v  [NTOK * D_];
__device__ float g_ctx[NTOK * D_];
__device__ float g_ffn[NTOK * F_];
__device__ float g_vmean[B_ * H_ * DH_];

// -------------------- SGEMM: C = A[M,K] @ B[K,N] (+bias, epilogue modes) ----
#define EP_PLAIN 0
#define EP_PROJ  1   // out = (acc+bias) * padmask(row)
#define EP_QKV   2   // out written to [B,H,S,Dh] layout
#define EP_RESID 3   // out[m,n] += acc+bias
#define EP_SILU  4   // out = silu(acc+bias)

template <int MODE>
__global__ void __launch_bounds__(256)
sgemm_kernel(int M, int N, int K,
             const float* __restrict__ A,
             const float* __restrict__ Bm,
             const float* __restrict__ bias,
             float* __restrict__ out,
             const int* __restrict__ x_lengths)
{
    __shared__ float As[8][128];
    __shared__ float Bs[8][128];

    const int bn = blockIdx.x * 128;
    const int bm = blockIdx.y * 128;
    const int tid = threadIdx.x;
    const int tx = tid & 15;        // 0..15 -> n
    const int ty = tid >> 4;        // 0..15 -> m

    const int a_row  = tid >> 1;          // 0..127
    const int a_col4 = (tid & 1) * 4;     // 0 or 4
    const int b_row  = tid >> 5;          // 0..7
    const int b_col4 = (tid & 31) * 4;    // 0..124

    float acc[8][8];
#pragma unroll
    for (int i = 0; i < 8; i++)
#pragma unroll
        for (int j = 0; j < 8; j++) acc[i][j] = 0.f;

    for (int k0 = 0; k0 < K; k0 += 8) {
        float4 av = *(const float4*)(A + (size_t)(bm + a_row) * K + k0 + a_col4);
        As[a_col4 + 0][a_row] = av.x;
        As[a_col4 + 1][a_row] = av.y;
        As[a_col4 + 2][a_row] = av.z;
        As[a_col4 + 3][a_row] = av.w;
        float4 bv = *(const float4*)(Bm + (size_t)(k0 + b_row) * N + bn + b_col4);
        *(float4*)&Bs[b_row][b_col4] = bv;
        __syncthreads();
#pragma unroll
        for (int kk = 0; kk < 8; kk++) {
            float4 a0 = *(const float4*)&As[kk][ty * 8];
            float4 a1 = *(const float4*)&As[kk][ty * 8 + 4];
            float4 b0 = *(const float4*)&Bs[kk][tx * 8];
            float4 b1 = *(const float4*)&Bs[kk][tx * 8 + 4];
            float ra[8] = {a0.x, a0.y, a0.z, a0.w, a1.x, a1.y, a1.z, a1.w};
            float rb[8] = {b0.x, b0.y, b0.z, b0.w, b1.x, b1.y, b1.z, b1.w};
#pragma unroll
            for (int i = 0; i < 8; i++)
#pragma unroll
                for (int j = 0; j < 8; j++)
                    acc[i][j] += ra[i] * rb[j];
        }
        __syncthreads();
    }

#pragma unroll
    for (int i = 0; i < 8; i++) {
        const int m = bm + ty * 8 + i;
#pragma unroll
        for (int j = 0; j < 8; j++) {
            const int n = bn + tx * 8 + j;
            float v = acc[i][j] + bias[n];
            if (MODE == EP_PROJ) {
                int b = m >> 10;
                int s = m & 1023;
                int len = x_lengths[b] >> 2;
                out[(size_t)m * N + n] = (s < len) ? v : 0.f;
            } else if (MODE == EP_QKV) {
                int b = m >> 10, s = m & 1023;
                int hh = n >> 7, dh = n & 127;
                out[((((b << 3) | hh) << 10) | s) * 128 + dh] = v;
            } else if (MODE == EP_RESID) {
                out[(size_t)m * N + n] += v;
            } else if (MODE == EP_SILU) {
                out[(size_t)m * N + n] = v / (1.f + __expf(-v));
            } else {
                out[(size_t)m * N + n] = v;
            }
        }
    }
}

// -------------------- LayerNorm: one block per row of 1024 ------------------
__global__ void __launch_bounds__(256)
layernorm_kernel(const float* __restrict__ in, float* __restrict__ out,
                 const float* __restrict__ scale, const float* __restrict__ bias)
{
    __shared__ float sh1[8];
    __shared__ float sh2[8];
    const int row = blockIdx.x;
    const int t = threadIdx.x;
    const int lane = t & 31, w = t >> 5;
    const float* xr = in + (size_t)row * 1024;

    float vals[4];
    float s = 0.f;
#pragma unroll
    for (int r = 0; r < 4; r++) { vals[r] = xr[t + 256 * r]; s += vals[r]; }
#pragma unroll
    for (int o = 16; o; o >>= 1) s += __shfl_xor_sync(0xffffffffu, s, o);
    if (lane == 0) sh1[w] = s;
    __syncthreads();
    float tot = (t < 8) ? sh1[t] : 0.f;
    if (w == 0) {
#pragma unroll
        for (int o = 16; o; o >>= 1) tot += __shfl_xor_sync(0xffffffffu, tot, o);
        if (lane == 0) sh1[0] = tot;
    }
    __syncthreads();
    const float mean = sh1[0] * (1.f / 1024.f);

    float vs = 0.f;
#pragma unroll
    for (int r = 0; r < 4; r++) { float d = vals[r] - mean; vs += d * d; }
#pragma unroll
    for (int o = 16; o; o >>= 1) vs += __shfl_xor_sync(0xffffffffu, vs, o);
    if (lane == 0) sh2[w] = vs;
    __syncthreads();
    float vtot = (t < 8) ? sh2[t] : 0.f;
    if (w == 0) {
#pragma unroll
        for (int o = 16; o; o >>= 1) vtot += __shfl_xor_sync(0xffffffffu, vtot, o);
        if (lane == 0) sh2[0] = vtot;
    }
    __syncthreads();
    const float var = sh2[0] * (1.f / 1024.f);
    const float inv = rsqrtf(var + 1e-5f);

#pragma unroll
    for (int r = 0; r < 4; r++) {
        int d = t + 256 * r;
        out[(size_t)row * 1024 + d] = (vals[r] - mean) * inv * scale[d] + bias[d];
    }
}

// -------------------- RoPE (in-place on q and k, [B,H,S,Dh]) ----------------
__global__ void __launch_bounds__(256)
rope_kernel(float* __restrict__ q, float* __restrict__ k)
{
    const int total = B_ * H_ * S_ * 64;      // pairs per tensor
    int idx = blockIdx.x * blockDim.x + threadIdx.x;
    if (idx >= 2 * total) return;
    float* ptr = (idx < total) ? q : k;
    int id = (idx < total) ? idx : idx - total;
    int p  = id & 63;
    int s  = (id >> 6) & 1023;
    int bh = id >> 16;
    // inv_freq = 10000^(-p/64) (accurate expf, not __expf)
    float inv_freq = expf(-(float)p * (9.210340371976184f / 64.f));
    float ang = (float)s * inv_freq;
    float sn, cs;
    sincosf(ang, &sn, &cs);
    int base = (bh * 1024 + s) * 128 + p;
    float x1 = ptr[base];
    float x2 = ptr[base + 64];
    ptr[base]      = x1 * cs - x2 * sn;
    ptr[base + 64] = x1 * sn + x2 * cs;
}

// -------------------- per-(b,h) mean of V rows (for fully-masked queries) ---
__global__ void __launch_bounds__(128)
vmean_kernel(const float* __restrict__ v, float* __restrict__ vmean)
{
    const int bh = blockIdx.x;      // 0..31
    const int d  = threadIdx.x;     // 0..127
    const float* base = v + (size_t)bh * S_ * DH_ + d;
    float s = 0.f;
    for (int j = 0; j < S_; j++) s += base[j * DH_];
    vmean[bh * DH_ + d] = s * (1.f / (float)S_);
}

// -------------------- windowed flash attention: 1 warp per query ------------
// Fully-masked rows (no allowed key): reference's fp32 bias collapse makes the
// softmax exactly uniform over ALL keys -> ctx = mean of all V rows.
__global__ void __launch_bounds__(128)
attn_kernel(const float* __restrict__ q, const float* __restrict__ k,
            const float* __restrict__ v, const float* __restrict__ vmean,
            float* __restrict__ ctx, const int* __restrict__ x_lengths)
{
    const int wid  = blockIdx.x * 4 + (threadIdx.x >> 5);   // 0..32767
    const int lane = threadIdx.x & 31;
    const int i  = wid & 1023;
    const int hh = (wid >> 10) & 7;
    const int b  = wid >> 13;

    const int len = x_lengths[b] >> 2;
    int jlo = i - (WIN_ - 1); if (jlo < 0) jlo = 0;
    int jhi = i + LFW_;       if (jhi > S_ - 1) jhi = S_ - 1;
    int jh  = (len - 1 < jhi) ? (len - 1) : jhi;

    float* orow = ctx + ((size_t)(b * 1024 + i)) * 1024 + hh * 128;

    if (jh < jlo) {
        // fully masked: uniform attention over all keys == mean of V
        const float* vm = vmean + (b * 8 + hh) * 128;
#pragma unroll
        for (int r = 0; r < 4; r++) orow[lane + 32 * r] = vm[lane + 32 * r];
        return;
    }

    const size_t head = ((size_t)(b * 8 + hh)) * 1024;
    const float* qrow = q + (head + i) * 128;
    float qr[4];
#pragma unroll
    for (int r = 0; r < 4; r++) qr[r] = qrow[lane + 32 * r];

    const float scale = 0.08838834764831845f;   // 1/sqrt(128)
    float m = -1e30f, l = 0.f;
    float acc[4] = {0.f, 0.f, 0.f, 0.f};

    for (int j = jlo; j <= jh; j++) {
        const float* krow = k + (head + j) * 128;
        float s = qr[0] * krow[lane]
                + qr[1] * krow[lane + 32]
                + qr[2] * krow[lane + 64]
                + qr[3] * krow[lane + 96];
#pragma unroll
        for (int o = 16; o; o >>= 1) s += __shfl_xor_sync(0xffffffffu, s, o);
        s *= scale;
        float mnew  = fmaxf(m, s);
        float alpha = __expf(m - mnew);
        float p     = __expf(s - mnew);
        l = l * alpha + p;
        const float* vrow = v + (head + j) * 128;
#pragma unroll
        for (int r = 0; r < 4; r++)
            acc[r] = acc[r] * alpha + p * vrow[lane + 32 * r];
        m = mnew;
    }

    const float invl = 1.f / l;
#pragma unroll
    for (int r = 0; r < 4; r++) orow[lane + 32 * r] = acc[r] * invl;
}

// -------------------- launch ------------------------------------------------
extern "C" void kernel_launch(void* const* d_in, const int* in_sizes, int n_in,
                              void* d_out, int out_size)
{
    const float* x     = (const float*)d_in[0];
    const int*   xlen  = (const int*)  d_in[1];
    const float* Wp    = (const float*)d_in[2];
    const float* bp    = (const float*)d_in[3];
    const float* ln1_s = (const float*)d_in[4];
    const float* ln1_b = (const float*)d_in[5];
    const float* Wq    = (const float*)d_in[6];
    const float* bq    = (const float*)d_in[7];
    const float* Wk    = (const float*)d_in[8];
    const float* bk    = (const float*)d_in[9];
    const float* Wv    = (const float*)d_in[10];
    const float* bv    = (const float*)d_in[11];
    const float* Wo    = (const float*)d_in[12];
    const float* bo    = (const float*)d_in[13];
    const float* ln2_s = (const float*)d_in[14];
    const float* ln2_b = (const float*)d_in[15];
    const float* W1    = (const float*)d_in[16];
    const float* b1    = (const float*)d_in[17];
    const float* W2    = (const float*)d_in[18];
    const float* b2    = (const float*)d_in[19];
    const float* lnf_s = (const float*)d_in[20];
    const float* lnf_b = (const float*)d_in[21];
    float* out = (float*)d_out;

    float *h, *y, *q, *k, *v, *ctx, *ffn, *vmean;
    cudaGetSymbolAddress((void**)&h,    g_h);
    cudaGetSymbolAddress((void**)&y,    g_y);
    cudaGetSymbolAddress((void**)&q,    g_q);
    cudaGetSymbolAddress((void**)&k,    g_k);
    cudaGetSymbolAddress((void**)&v,    g_v);
    cudaGetSymbolAddress((void**)&ctx,  g_ctx);
    cudaGetSymbolAddress((void**)&ffn,  g_ffn);
    cudaGetSymbolAddress((void**)&vmean,g_vmean);

    const dim3 gDD(D_ / 128, NTOK / 128);   // N=1024
    const dim3 gDF(F_ / 128, NTOK / 128);   // N=4096
    const dim3 blk(256);

    // projector: h = (x @ Wp + bp) * pad
    sgemm_kernel<EP_PROJ><<<gDD, blk>>>(NTOK, D_, C_ * 4, x, Wp, bp, h, xlen);

    for (int l = 0; l < L_; l++) {
        const size_t oDD = (size_t)l * D_ * D_;
        const size_t oDF = (size_t)l * D_ * F_;
        const size_t oD  = (size_t)l * D_;
        const size_t oF  = (size_t)l * F_;

        layernorm_kernel<<<NTOK, blk>>>(h, y, ln1_s + oD, ln1_b + oD);

        sgemm_kernel<EP_QKV><<<gDD, blk>>>(NTOK, D_, D_, y, Wq + oDD, bq + oD, q, nullptr);
        sgemm_kernel<EP_QKV><<<gDD, blk>>>(NTOK, D_, D_, y, Wk + oDD, bk + oD, k, nullptr);
        sgemm_kernel<EP_QKV><<<gDD, blk>>>(NTOK, D_, D_, y, Wv + oDD, bv + oD, v, nullptr);

        rope_kernel<<<(2 * B_ * H_ * S_ * 64) / 256, blk>>>(q, k);

        vmean_kernel<<<B_ * H_, 128>>>(v, vmean);

        attn_kernel<<<(B_ * H_ * S_) / 4, 128>>>(q, k, v, vmean, ctx, xlen);

        sgemm_kernel<EP_RESID><<<gDD, blk>>>(NTOK, D_, D_, ctx, Wo + oDD, bo + oD, h, nullptr);

        layernorm_kernel<<<NTOK, blk>>>(h, y, ln2_s + oD, ln2_b + oD);

        sgemm_kernel<EP_SILU><<<gDF, blk>>>(NTOK, F_, D_, y, W1 + oDF, b1 + oF, ffn, nullptr);
        sgemm_kernel<EP_RESID><<<gDD, blk>>>(NTOK, D_, F_, ffn, W2 + oDF, b2 + oD, h, nullptr);
    }

    layernorm_kernel<<<NTOK, blk>>>(h, out, lnf_s, lnf_b);
}

// round 4
// speedup vs baseline: 2.1910x; 2.1910x over previous
#include <cuda_runtime.h>
#include <cuda_bf16.h>
#include <math.h>
#include <stdint.h>

// Problem constants
#define B_   4
#define S_   1024
#define D_   1024
#define F_   4096
#define H_   8
#define DH_  128
#define L_   4
#define NTOK (B_ * S_)          // 4096
#define WIN_ 100
#define LFW_ 20

// -------------------- scratch --------------------
__device__ float g_h  [NTOK * D_];
__device__ float g_y  [NTOK * D_];
__device__ float g_q  [NTOK * D_];
__device__ float g_k  [NTOK * D_];
__device__ float g_v  [NTOK * D_];
__device__ float g_ctx[NTOK * D_];
__device__ float g_ffn[NTOK * F_];
__device__ float g_vmean[B_ * H_ * DH_];

// ==================== helpers ====================
__device__ __forceinline__ uint32_t smem_u32(const void* p) {
    uint32_t a;
    asm("{ .reg .u64 t; cvta.to.shared.u64 t, %1; cvt.u32.u64 %0, t; }" : "=r"(a) : "l"(p));
    return a;
}
__device__ __forceinline__ void ldsm4(uint32_t& r0, uint32_t& r1, uint32_t& r2, uint32_t& r3,
                                      uint32_t addr) {
    asm volatile("ldmatrix.sync.aligned.m8n8.x4.shared.b16 {%0,%1,%2,%3}, [%4];"
                 : "=r"(r0), "=r"(r1), "=r"(r2), "=r"(r3) : "r"(addr));
}
__device__ __forceinline__ void ldsm4t(uint32_t& r0, uint32_t& r1, uint32_t& r2, uint32_t& r3,
                                       uint32_t addr) {
    asm volatile("ldmatrix.sync.aligned.m8n8.x4.trans.shared.b16 {%0,%1,%2,%3}, [%4];"
                 : "=r"(r0), "=r"(r1), "=r"(r2), "=r"(r3) : "r"(addr));
}
__device__ __forceinline__ void mma16816(float* d, const uint32_t* a, const uint32_t* b) {
    asm volatile(
        "mma.sync.aligned.m16n8k16.row.col.f32.bf16.bf16.f32 "
        "{%0,%1,%2,%3}, {%4,%5,%6,%7}, {%8,%9}, {%0,%1,%2,%3};"
        : "+f"(d[0]), "+f"(d[1]), "+f"(d[2]), "+f"(d[3])
        : "r"(a[0]), "r"(a[1]), "r"(a[2]), "r"(a[3]), "r"(b[0]), "r"(b[1]));
}

// ==================== bf16-split tensor-core GEMM (mma.sync) ====================
// C[M=4096, NN] = A[M,K] @ W[K,NN] (+bias, epilogue). CTA tile 128x128, K-chunk 64.
// 256 threads = 8 warps in 2(m) x 4(n) grid; warp tile 64x32.
#define EP_PROJ  1
#define EP_QKV   2
#define EP_RESID 3
#define EP_SILU  4

#define A_PITCH 144            // bytes per m-row (64 bf16 = 128B + 16B pad)
#define B_PITCH 272            // bytes per k-row (128 bf16 = 256B + 16B pad)
#define SA_HI 0
#define SA_LO (SA_HI + 128 * A_PITCH)          // 18432
#define SB_HI (SA_LO + 128 * A_PITCH)          // 36864
#define SB_LO (SB_HI + 64 * B_PITCH)           // 54272
#define GEMM_SMEM (SB_LO + 64 * B_PITCH)       // 71680

template <int MODE>
__global__ void __launch_bounds__(256)
mma_gemm(int K, int NN,
         const float* __restrict__ A,
         const float* __restrict__ W,
         const float* __restrict__ bias,
         float* __restrict__ out,
         const int* __restrict__ x_lengths)
{
    extern __shared__ char sm[];
    const uint32_t sb = smem_u32(sm);
    const int tid  = threadIdx.x;
    const int wid  = tid >> 5;
    const int lane = tid & 31;
    const int bn = blockIdx.x * 128;
    const int bm = blockIdx.y * 128;
    const int wm = wid & 1;          // 0..1  -> m offset wm*64
    const int wn = wid >> 1;         // 0..3  -> n offset wn*32

    float acc[4][4][4];
#pragma unroll
    for (int i = 0; i < 4; i++)
#pragma unroll
        for (int j = 0; j < 4; j++)
#pragma unroll
            for (int r = 0; r < 4; r++) acc[i][j][r] = 0.f;

    // lane-derived fragment addresses
    const int quad = lane >> 3;      // 0..3
    const int qr   = lane & 7;       // 0..7
    // A (non-trans): matrices (m0-7,k0-7),(m8-15,k0-7),(m0-7,k8-15),(m8-15,k8-15)
    const uint32_t aAddrH = sb + SA_HI
        + (uint32_t)(wm * 64 + (quad & 1) * 8 + qr) * A_PITCH + (quad >> 1) * 16;
    // B (trans): matrices (k0-7,nb0),(k8-15,nb0),(k0-7,nb1),(k8-15,nb1)
    const uint32_t bAddrH = sb + SB_HI
        + (uint32_t)((quad & 1) * 8 + qr) * B_PITCH + (uint32_t)(wn * 32 + (quad >> 1) * 8) * 2;

    const int nch = K >> 6;
    for (int c = 0; c < nch; c++) {
        const int k0 = c << 6;

        // ---- A tile: 128 x 64 fp32 -> bf16 hi/lo, padded rows ----
#pragma unroll
        for (int it = 0; it < 16; it++) {
            const int idx = it * 256 + tid;          // 4096 float2 slots
            const int row = idx >> 5;
            const int p   = idx & 31;
            float2 v = *(const float2*)(A + (size_t)(bm + row) * K + k0 + 2 * p);
            __nv_bfloat162 h2 = __floats2bfloat162_rn(v.x, v.y);
            float lx = v.x - __bfloat162float(h2.x);
            float ly = v.y - __bfloat162float(h2.y);
            __nv_bfloat162 l2 = __floats2bfloat162_rn(lx, ly);
            const uint32_t off = (uint32_t)row * A_PITCH + p * 4;
            *(__nv_bfloat162*)(sm + SA_HI + off) = h2;
            *(__nv_bfloat162*)(sm + SA_LO + off) = l2;
        }
        // ---- B tile: 64(k) x 128(n) fp32 -> bf16 hi/lo, [k][n] padded rows ----
#pragma unroll
        for (int it = 0; it < 16; it++) {
            const int idx = it * 256 + tid;          // 4096 float2 slots
            const int kr = idx >> 6;
            const int np = idx & 63;
            float2 v = *(const float2*)(W + (size_t)(k0 + kr) * NN + bn + 2 * np);
            __nv_bfloat162 h2 = __floats2bfloat162_rn(v.x, v.y);
            float lx = v.x - __bfloat162float(h2.x);
            float ly = v.y - __bfloat162float(h2.y);
            __nv_bfloat162 l2 = __floats2bfloat162_rn(lx, ly);
            const uint32_t off = (uint32_t)kr * B_PITCH + np * 4;
            *(__nv_bfloat162*)(sm + SB_HI + off) = h2;
            *(__nv_bfloat162*)(sm + SB_LO + off) = l2;
        }
        __syncthreads();

        // ---- compute: 4 k16 steps ----
#pragma unroll
        for (int ks = 0; ks < 4; ks++) {
            uint32_t aH[4][4], aL[4][4], bH[4][2], bL[4][2];
#pragma unroll
            for (int mi = 0; mi < 4; mi++) {
                const uint32_t ad = aAddrH + (uint32_t)mi * (16 * A_PITCH) + ks * 32;
                ldsm4(aH[mi][0], aH[mi][1], aH[mi][2], aH[mi][3], ad);
                ldsm4(aL[mi][0], aL[mi][1], aL[mi][2], aL[mi][3], ad + (SA_LO - SA_HI));
            }
#pragma unroll
            for (int bp = 0; bp < 2; bp++) {
                const uint32_t ad = bAddrH + (uint32_t)ks * (16 * B_PITCH) + bp * 32;
                uint32_t r0, r1, r2, r3;
                ldsm4t(r0, r1, r2, r3, ad);
                bH[2 * bp][0] = r0; bH[2 * bp][1] = r1;
                bH[2 * bp + 1][0] = r2; bH[2 * bp + 1][1] = r3;
                ldsm4t(r0, r1, r2, r3, ad + (SB_LO - SB_HI));
                bL[2 * bp][0] = r0; bL[2 * bp][1] = r1;
                bL[2 * bp + 1][0] = r2; bL[2 * bp + 1][1] = r3;
            }
#pragma unroll
            for (int mi = 0; mi < 4; mi++)
#pragma unroll
                for (int ni = 0; ni < 4; ni++) {
                    mma16816(acc[mi][ni], aH[mi], bH[ni]);
                    mma16816(acc[mi][ni], aH[mi], bL[ni]);
                    mma16816(acc[mi][ni], aL[mi], bH[ni]);
                }
        }
        __syncthreads();
    }

    // ---- epilogue ----
    const int grp = lane >> 2;
    const int qc  = (lane & 3) * 2;
#pragma unroll
    for (int mi = 0; mi < 4; mi++) {
        const int m0 = bm + wm * 64 + mi * 16 + grp;
#pragma unroll
        for (int ni = 0; ni < 4; ni++) {
            const int n = bn + wn * 32 + ni * 8 + qc;
            float2 bsv = *(const float2*)(bias + n);
            float2 v01, v23;
            v01.x = acc[mi][ni][0] + bsv.x;
            v01.y = acc[mi][ni][1] + bsv.y;
            v23.x = acc[mi][ni][2] + bsv.x;
            v23.y = acc[mi][ni][3] + bsv.y;
#pragma unroll
            for (int half = 0; half < 2; half++) {
                const int m = m0 + half * 8;
                float2 v = half ? v23 : v01;
                if (MODE == EP_PROJ) {
                    const int b = m >> 10, s = m & 1023;
                    const int len = x_lengths[b] >> 2;
                    if (s >= len) { v.x = 0.f; v.y = 0.f; }
                    *(float2*)(out + (size_t)m * NN + n) = v;
                } else if (MODE == EP_QKV) {
                    const int b = m >> 10, s = m & 1023;
                    const int hh = n >> 7, dh = n & 127;
                    *(float2*)(out + ((size_t)((b << 3) | hh) * 1024 + s) * 128 + dh) = v;
                } else if (MODE == EP_RESID) {
                    float2 o = *(float2*)(out + (size_t)m * NN + n);
                    o.x += v.x; o.y += v.y;
                    *(float2*)(out + (size_t)m * NN + n) = o;
                } else { // EP_SILU
                    v.x = v.x / (1.f + __expf(-v.x));
                    v.y = v.y / (1.f + __expf(-v.y));
                    *(float2*)(out + (size_t)m * NN + n) = v;
                }
            }
        }
    }
}

// -------------------- LayerNorm --------------------
__global__ void __launch_bounds__(256)
layernorm_kernel(const float* __restrict__ in, float* __restrict__ out,
                 const float* __restrict__ scale, const float* __restrict__ bias)
{
    __shared__ float sh1[8];
    __shared__ float sh2[8];
    const int row = blockIdx.x;
    const int t = threadIdx.x;
    const int lane = t & 31, w = t >> 5;
    const float* xr = in + (size_t)row * 1024;

    float vals[4];
    float s = 0.f;
#pragma unroll
    for (int r = 0; r < 4; r++) { vals[r] = xr[t + 256 * r]; s += vals[r]; }
#pragma unroll
    for (int o = 16; o; o >>= 1) s += __shfl_xor_sync(0xffffffffu, s, o);
    if (lane == 0) sh1[w] = s;
    __syncthreads();
    float tot = (t < 8) ? sh1[t] : 0.f;
    if (w == 0) {
#pragma unroll
        for (int o = 16; o; o >>= 1) tot += __shfl_xor_sync(0xffffffffu, tot, o);
        if (lane == 0) sh1[0] = tot;
    }
    __syncthreads();
    const float mean = sh1[0] * (1.f / 1024.f);

    float vs = 0.f;
#pragma unroll
    for (int r = 0; r < 4; r++) { float d = vals[r] - mean; vs += d * d; }
#pragma unroll
    for (int o = 16; o; o >>= 1) vs += __shfl_xor_sync(0xffffffffu, vs, o);
    if (lane == 0) sh2[w] = vs;
    __syncthreads();
    float vtot = (t < 8) ? sh2[t] : 0.f;
    if (w == 0) {
#pragma unroll
        for (int o = 16; o; o >>= 1) vtot += __shfl_xor_sync(0xffffffffu, vtot, o);
        if (lane == 0) sh2[0] = vtot;
    }
    __syncthreads();
    const float var = sh2[0] * (1.f / 1024.f);
    const float inv = rsqrtf(var + 1e-5f);

#pragma unroll
    for (int r = 0; r < 4; r++) {
        int d = t + 256 * r;
        out[(size_t)row * 1024 + d] = (vals[r] - mean) * inv * scale[d] + bias[d];
    }
}

// -------------------- RoPE --------------------
__global__ void __launch_bounds__(256)
rope_kernel(float* __restrict__ q, float* __restrict__ k)
{
    const int total = B_ * H_ * S_ * 64;
    int idx = blockIdx.x * blockDim.x + threadIdx.x;
    if (idx >= 2 * total) return;
    float* ptr = (idx < total) ? q : k;
    int id = (idx < total) ? idx : idx - total;
    int p  = id & 63;
    int s  = (id >> 6) & 1023;
    int bh = id >> 16;
    float inv_freq = expf(-(float)p * (9.210340371976184f / 64.f));
    float ang = (float)s * inv_freq;
    float sn, cs;
    sincosf(ang, &sn, &cs);
    int base = (bh * 1024 + s) * 128 + p;
    float x1 = ptr[base];
    float x2 = ptr[base + 64];
    ptr[base]      = x1 * cs - x2 * sn;
    ptr[base + 64] = x1 * sn + x2 * cs;
}

// -------------------- V mean (fully-masked fallback) --------------------
__global__ void __launch_bounds__(128)
vmean_kernel(const float* __restrict__ v, float* __restrict__ vmean)
{
    const int bh = blockIdx.x;
    const int d  = threadIdx.x;
    const float* base = v + (size_t)bh * S_ * DH_ + d;
    float s = 0.f;
    for (int j = 0; j < S_; j++) s += base[j * DH_];
    vmean[bh * DH_ + d] = s * (1.f / (float)S_);
}

// -------------------- windowed flash attention --------------------
__global__ void __launch_bounds__(128)
attn_kernel(const float* __restrict__ q, const float* __restrict__ k,
            const float* __restrict__ v, const float* __restrict__ vmean,
            float* __restrict__ ctx, const int* __restrict__ x_lengths)
{
    const int wid  = blockIdx.x * 4 + (threadIdx.x >> 5);
    const int lane = threadIdx.x & 31;
    const int i  = wid & 1023;
    const int hh = (wid >> 10) & 7;
    const int b  = wid >> 13;

    const int len = x_lengths[b] >> 2;
    int jlo = i - (WIN_ - 1); if (jlo < 0) jlo = 0;
    int jhi = i + LFW_;       if (jhi > S_ - 1) jhi = S_ - 1;
    int jh  = (len - 1 < jhi) ? (len - 1) : jhi;

    float* orow = ctx + ((size_t)(b * 1024 + i)) * 1024 + hh * 128;

    if (jh < jlo) {
        const float* vm = vmean + (b * 8 + hh) * 128;
#pragma unroll
        for (int r = 0; r < 4; r++) orow[lane + 32 * r] = vm[lane + 32 * r];
        return;
    }

    const size_t head = ((size_t)(b * 8 + hh)) * 1024;
    const float* qrow = q + (head + i) * 128;
    float qr[4];
#pragma unroll
    for (int r = 0; r < 4; r++) qr[r] = qrow[lane + 32 * r];

    const float scale = 0.08838834764831845f;
    float m = -1e30f, l = 0.f;
    float acc[4] = {0.f, 0.f, 0.f, 0.f};

    for (int j = jlo; j <= jh; j++) {
        const float* krow = k + (head + j) * 128;
        float s = qr[0] * krow[lane]
                + qr[1] * krow[lane + 32]
                + qr[2] * krow[lane + 64]
                + qr[3] * krow[lane + 96];
#pragma unroll
        for (int o = 16; o; o >>= 1) s += __shfl_xor_sync(0xffffffffu, s, o);
        s *= scale;
        float mnew  = fmaxf(m, s);
        float alpha = __expf(m - mnew);
        float p     = __expf(s - mnew);
        l = l * alpha + p;
        const float* vrow = v + (head + j) * 128;
#pragma unroll
        for (int r = 0; r < 4; r++)
            acc[r] = acc[r] * alpha + p * vrow[lane + 32 * r];
        m = mnew;
    }

    const float invl = 1.f / l;
#pragma unroll
    for (int r = 0; r < 4; r++) orow[lane + 32 * r] = acc[r] * invl;
}

// -------------------- launch --------------------
extern "C" void kernel_launch(void* const* d_in, const int* in_sizes, int n_in,
                              void* d_out, int out_size)
{
    const float* x     = (const float*)d_in[0];
    const int*   xlen  = (const int*)  d_in[1];
    const float* Wp    = (const float*)d_in[2];
    const float* bp    = (const float*)d_in[3];
    const float* ln1_s = (const float*)d_in[4];
    const float* ln1_b = (const float*)d_in[5];
    const float* Wq    = (const float*)d_in[6];
    const float* bq    = (const float*)d_in[7];
    const float* Wk    = (const float*)d_in[8];
    const float* bk    = (const float*)d_in[9];
    const float* Wv    = (const float*)d_in[10];
    const float* bv    = (const float*)d_in[11];
    const float* Wo    = (const float*)d_in[12];
    const float* bo    = (const float*)d_in[13];
    const float* ln2_s = (const float*)d_in[14];
    const float* ln2_b = (const float*)d_in[15];
    const float* W1    = (const float*)d_in[16];
    const float* b1    = (const float*)d_in[17];
    const float* W2    = (const float*)d_in[18];
    const float* b2    = (const float*)d_in[19];
    const float* lnf_s = (const float*)d_in[20];
    const float* lnf_b = (const float*)d_in[21];
    float* out = (float*)d_out;

    float *h, *y, *q, *k, *v, *ctx, *ffn, *vmean;
    cudaGetSymbolAddress((void**)&h,    g_h);
    cudaGetSymbolAddress((void**)&y,    g_y);
    cudaGetSymbolAddress((void**)&q,    g_q);
    cudaGetSymbolAddress((void**)&k,    g_k);
    cudaGetSymbolAddress((void**)&v,    g_v);
    cudaGetSymbolAddress((void**)&ctx,  g_ctx);
    cudaGetSymbolAddress((void**)&ffn,  g_ffn);
    cudaGetSymbolAddress((void**)&vmean,g_vmean);

    cudaFuncSetAttribute(mma_gemm<EP_PROJ>,  cudaFuncAttributeMaxDynamicSharedMemorySize, GEMM_SMEM);
    cudaFuncSetAttribute(mma_gemm<EP_QKV>,   cudaFuncAttributeMaxDynamicSharedMemorySize, GEMM_SMEM);
    cudaFuncSetAttribute(mma_gemm<EP_RESID>, cudaFuncAttributeMaxDynamicSharedMemorySize, GEMM_SMEM);
    cudaFuncSetAttribute(mma_gemm<EP_SILU>,  cudaFuncAttributeMaxDynamicSharedMemorySize, GEMM_SMEM);

    const dim3 gDD(D_ / 128, NTOK / 128);
    const dim3 gDF(F_ / 128, NTOK / 128);
    const dim3 blk(256);

    // projector: h = (x @ Wp + bp) * pad   (K = 2048)
    mma_gemm<EP_PROJ><<<gDD, blk, GEMM_SMEM>>>(2048, D_, x, Wp, bp, h, xlen);

    for (int l = 0; l < L_; l++) {
        const size_t oDD = (size_t)l * D_ * D_;
        const size_t oDF = (size_t)l * D_ * F_;
        const size_t oD  = (size_t)l * D_;
        const size_t oF  = (size_t)l * F_;

        layernorm_kernel<<<NTOK, blk>>>(h, y, ln1_s + oD, ln1_b + oD);

        mma_gemm<EP_QKV><<<gDD, blk, GEMM_SMEM>>>(D_, D_, y, Wq + oDD, bq + oD, q, nullptr);
        mma_gemm<EP_QKV><<<gDD, blk, GEMM_SMEM>>>(D_, D_, y, Wk + oDD, bk + oD, k, nullptr);
        mma_gemm<EP_QKV><<<gDD, blk, GEMM_SMEM>>>(D_, D_, y, Wv + oDD, bv + oD, v, nullptr);

        rope_kernel<<<(2 * B_ * H_ * S_ * 64) / 256, blk>>>(q, k);

        vmean_kernel<<<B_ * H_, 128>>>(v, vmean);

        attn_kernel<<<(B_ * H_ * S_) / 4, 128>>>(q, k, v, vmean, ctx, xlen);

        mma_gemm<EP_RESID><<<gDD, blk, GEMM_SMEM>>>(D_, D_, ctx, Wo + oDD, bo + oD, h, nullptr);

        layernorm_kernel<<<NTOK, blk>>>(h, y, ln2_s + oD, ln2_b + oD);

        mma_gemm<EP_SILU><<<gDF, blk, GEMM_SMEM>>>(D_, F_, y, W1 + oDF, b1 + oF, ffn, nullptr);
        mma_gemm<EP_RESID><<<gDD, blk, GEMM_SMEM>>>(F_, D_, ffn, W2 + oDF, b2 + oD, h, nullptr);
    }

    layernorm_kernel<<<NTOK, blk>>>(h, out, lnf_s, lnf_b);
}

// round 5
// speedup vs baseline: 2.4292x; 1.1087x over previous
#include <cuda_runtime.h>
#include <cuda_bf16.h>
#include <math.h>
#include <stdint.h>

// Problem constants
#define B_   4
#define S_   1024
#define D_   1024
#define F_   4096
#define H_   8
#define DH_  128
#define L_   4
#define NTOK (B_ * S_)          // 4096
#define WIN_ 100
#define LFW_ 20

typedef __nv_bfloat16  bf16;
typedef __nv_bfloat162 bf162;

// -------------------- scratch --------------------
__device__ float g_h [NTOK * D_];
__device__ float g_q [NTOK * D_];
__device__ float g_k [NTOK * D_];
__device__ float g_v [NTOK * D_];
__device__ float g_vmean[B_ * H_ * DH_];

// bf16 hi/lo activation buffers
__device__ bf16 g_xhi[NTOK * 2048],  g_xlo[NTOK * 2048];
__device__ bf16 g_yhi[NTOK * D_],    g_ylo[NTOK * D_];
__device__ bf16 g_chi[NTOK * D_],    g_clo[NTOK * D_];
__device__ bf16 g_fhi[NTOK * F_],    g_flo[NTOK * F_];

// converted weights (hi/lo), offsets in elements
#define WP_OFF   0u                         // 2048*1024
#define QKV_OFF  2097152u                   // per layer 1024*3072
#define WO_OFF   (QKV_OFF + 4u * 3145728u)  // 14680064; per layer 1024*1024
#define W1_OFF   (WO_OFF + 4u * 1048576u)   // 18874368; per layer 1024*4096
#define W2_OFF   (W1_OFF + 4u * 4194304u)   // 35651584; per layer 4096*1024
#define WTOT     (W2_OFF + 4u * 4194304u)   // 52428864
__device__ bf16 g_whi[WTOT];
__device__ bf16 g_wlo[WTOT];

// ==================== helpers ====================
__device__ __forceinline__ uint32_t smem_u32(const void* p) {
    uint32_t a;
    asm("{ .reg .u64 t; cvta.to.shared.u64 t, %1; cvt.u32.u64 %0, t; }" : "=r"(a) : "l"(p));
    return a;
}
__device__ __forceinline__ void cp16(uint32_t saddr, const void* gaddr) {
    asm volatile("cp.async.cg.shared.global [%0], [%1], 16;" :: "r"(saddr), "l"(gaddr));
}
__device__ __forceinline__ void cp_commit() {
    asm volatile("cp.async.commit_group;" ::: "memory");
}
__device__ __forceinline__ void ldsm4(uint32_t& r0, uint32_t& r1, uint32_t& r2, uint32_t& r3,
                                      uint32_t addr) {
    asm volatile("ldmatrix.sync.aligned.m8n8.x4.shared.b16 {%0,%1,%2,%3}, [%4];"
                 : "=r"(r0), "=r"(r1), "=r"(r2), "=r"(r3) : "r"(addr));
}
__device__ __forceinline__ void ldsm4t(uint32_t& r0, uint32_t& r1, uint32_t& r2, uint32_t& r3,
                                       uint32_t addr) {
    asm volatile("ldmatrix.sync.aligned.m8n8.x4.trans.shared.b16 {%0,%1,%2,%3}, [%4];"
                 : "=r"(r0), "=r"(r1), "=r"(r2), "=r"(r3) : "r"(addr));
}
__device__ __forceinline__ void mma16816(float* d, const uint32_t* a, const uint32_t* b) {
    asm volatile(
        "mma.sync.aligned.m16n8k16.row.col.f32.bf16.bf16.f32 "
        "{%0,%1,%2,%3}, {%4,%5,%6,%7}, {%8,%9}, {%0,%1,%2,%3};"
        : "+f"(d[0]), "+f"(d[1]), "+f"(d[2]), "+f"(d[3])
        : "r"(a[0]), "r"(a[1]), "r"(a[2]), "r"(a[3]), "r"(b[0]), "r"(b[1]));
}
__device__ __forceinline__ void split2(float x, float y, bf162& h, bf162& l) {
    h = __floats2bfloat162_rn(x, y);
    l = __floats2bfloat162_rn(x - __bfloat162float(h.x), y - __bfloat162float(h.y));
}

// ==================== converters ====================
__global__ void __launch_bounds__(256)
conv_split(const float* __restrict__ in, bf16* __restrict__ hi, bf16* __restrict__ lo, int n4)
{
    int i = blockIdx.x * blockDim.x + threadIdx.x;
    if (i >= n4) return;
    float4 v = ((const float4*)in)[i];
    bf162 h0, l0, h1, l1;
    split2(v.x, v.y, h0, l0);
    split2(v.z, v.w, h1, l1);
    ((bf162*)hi)[2 * i] = h0; ((bf162*)hi)[2 * i + 1] = h1;
    ((bf162*)lo)[2 * i] = l0; ((bf162*)lo)[2 * i + 1] = l1;
}

// QKV interleave: in [4096 rows, 1024] -> out rows pitch 3072 at column offset coff
__global__ void __launch_bounds__(256)
conv_split_qkv(const float* __restrict__ in, bf16* __restrict__ hi, bf16* __restrict__ lo, int coff)
{
    int i = blockIdx.x * blockDim.x + threadIdx.x;   // 0 .. 4096*256-1
    int row = i >> 8, c4 = i & 255;
    float4 v = ((const float4*)in)[i];
    bf162 h0, l0, h1, l1;
    split2(v.x, v.y, h0, l0);
    split2(v.z, v.w, h1, l1);
    size_t o2 = ((size_t)row * 3072 + coff + c4 * 4) >> 1;
    ((bf162*)hi)[o2] = h0; ((bf162*)hi)[o2 + 1] = h1;
    ((bf162*)lo)[o2] = l0; ((bf162*)lo)[o2 + 1] = l1;
}

// ==================== pipelined bf16-split GEMM (mma.sync + cp.async) =======
// C[4096, NN] = A[4096,K] @ W[K,NN], A/W given as bf16 hi+lo pairs.
// CTA 128x128, K-chunk 64, 2-stage cp.async double buffer, 8 warps (2m x 4n).
#define EP_PROJ  1
#define EP_QKV   2
#define EP_RESID 3
#define EP_SILU  4

#define A_PITCH 144
#define B_PITCH 272
#define OFF_AH 0
#define OFF_AL 18432
#define OFF_BH 36864
#define OFF_BL 54272
#define STAGE_B 71680
#define GEMM_SMEM (2 * STAGE_B)   // 143360

__device__ __forceinline__ void stage_load(
    uint32_t stb, const bf16* Ah, const bf16* Al, const bf16* Bh, const bf16* Bl,
    int k0, int bm, int bn, int K, int NN, int tid)
{
#pragma unroll
    for (int t = 0; t < 4; t++) {
        const int idx = t * 256 + tid;          // 0..1023
        const int row = idx >> 3, seg = idx & 7;
        const size_t go = (size_t)(bm + row) * K + k0 + seg * 8;
        const uint32_t so = stb + (uint32_t)row * A_PITCH + seg * 16;
        cp16(so + OFF_AH, Ah + go);
        cp16(so + OFF_AL, Al + go);
    }
#pragma unroll
    for (int t = 0; t < 4; t++) {
        const int idx = t * 256 + tid;          // 0..1023
        const int row = idx >> 4, seg = idx & 15;
        const size_t go = (size_t)(k0 + row) * NN + bn + seg * 8;
        const uint32_t so = stb + (uint32_t)row * B_PITCH + seg * 16;
        cp16(so + OFF_BH, Bh + go);
        cp16(so + OFF_BL, Bl + go);
    }
}

template <int MODE>
__global__ void __launch_bounds__(256)
mma_gemm(int K, int NN,
         const bf16* __restrict__ Ah, const bf16* __restrict__ Al,
         const bf16* __restrict__ Bh, const bf16* __restrict__ Bl,
         const float* __restrict__ bias, const float* __restrict__ bias2,
         const float* __restrict__ bias3,
         float* __restrict__ out, bf16* __restrict__ outHi, bf16* __restrict__ outLo,
         const int* __restrict__ x_lengths)
{
    extern __shared__ char sm[];
    const uint32_t sb = smem_u32(sm);
    const int tid  = threadIdx.x;
    const int wid  = tid >> 5;
    const int lane = tid & 31;
    const int bn = blockIdx.x * 128;
    const int bm = blockIdx.y * 128;
    const int wm = wid & 1;
    const int wn = wid >> 1;

    float acc[4][4][4];
#pragma unroll
    for (int i = 0; i < 4; i++)
#pragma unroll
        for (int j = 0; j < 4; j++)
#pragma unroll
            for (int r = 0; r < 4; r++) acc[i][j][r] = 0.f;

    const int quad = lane >> 3;
    const int qr   = lane & 7;
    const uint32_t aOffH = OFF_AH + (uint32_t)(wm * 64 + (quad & 1) * 8 + qr) * A_PITCH + (quad >> 1) * 16;
    const uint32_t aOffL = aOffH + (OFF_AL - OFF_AH);
    const uint32_t bOffH = OFF_BH + (uint32_t)((quad & 1) * 8 + qr) * B_PITCH
                         + (uint32_t)(wn * 32 + (quad >> 1) * 8) * 2;
    const uint32_t bOffL = bOffH + (OFF_BL - OFF_BH);

    const int nch = K >> 6;

    // prologue: stage chunk 0 (+ chunk 1)
    stage_load(sb, Ah, Al, Bh, Bl, 0, bm, bn, K, NN, tid);
    cp_commit();
    if (nch > 1) {
        stage_load(sb + STAGE_B, Ah, Al, Bh, Bl, 64, bm, bn, K, NN, tid);
        cp_commit();
    }

    for (int c = 0; c < nch; c++) {
        if (c < nch - 1) asm volatile("cp.async.wait_group 1;" ::: "memory");
        else             asm volatile("cp.async.wait_group 0;" ::: "memory");
        __syncthreads();

        const uint32_t stb = sb + (uint32_t)(c & 1) * STAGE_B;

#pragma unroll
        for (int ks = 0; ks < 4; ks++) {
            uint32_t aH[4][4], aL[4][4], bH[4][2], bL[4][2];
#pragma unroll
            for (int mi = 0; mi < 4; mi++) {
                const uint32_t ad = stb + aOffH + (uint32_t)mi * (16 * A_PITCH) + ks * 32;
                ldsm4(aH[mi][0], aH[mi][1], aH[mi][2], aH[mi][3], ad);
                ldsm4(aL[mi][0], aL[mi][1], aL[mi][2], aL[mi][3], ad + (OFF_AL - OFF_AH));
            }
#pragma unroll
            for (int bp = 0; bp < 2; bp++) {
                const uint32_t ad = stb + bOffH + (uint32_t)ks * (16 * B_PITCH) + bp * 32;
                uint32_t r0, r1, r2, r3;
                ldsm4t(r0, r1, r2, r3, ad);
                bH[2 * bp][0] = r0; bH[2 * bp][1] = r1;
                bH[2 * bp + 1][0] = r2; bH[2 * bp + 1][1] = r3;
                ldsm4t(r0, r1, r2, r3, ad + (OFF_BL - OFF_BH));
                bL[2 * bp][0] = r0; bL[2 * bp][1] = r1;
                bL[2 * bp + 1][0] = r2; bL[2 * bp + 1][1] = r3;
            }
#pragma unroll
            for (int mi = 0; mi < 4; mi++)
#pragma unroll
                for (int ni = 0; ni < 4; ni++) {
                    mma16816(acc[mi][ni], aH[mi], bH[ni]);
                    mma16816(acc[mi][ni], aH[mi], bL[ni]);
                    mma16816(acc[mi][ni], aL[mi], bH[ni]);
                }
        }
        __syncthreads();

        if (c + 2 < nch) {
            stage_load(stb, Ah, Al, Bh, Bl, (c + 2) << 6, bm, bn, K, NN, tid);
            cp_commit();
        }
    }

    // ---- epilogue ----
    const int grp = lane >> 2;
    const int qc  = (lane & 3) * 2;
#pragma unroll
    for (int mi = 0; mi < 4; mi++) {
        const int m0 = bm + wm * 64 + mi * 16 + grp;
#pragma unroll
        for (int ni = 0; ni < 4; ni++) {
            const int n = bn + wn * 32 + ni * 8 + qc;
            float2 bsv;
            if (MODE == EP_QKV) {
                const int sel = n >> 10;
                const float* bp = (sel == 0) ? bias : (sel == 1) ? bias2 : bias3;
                bsv = *(const float2*)(bp + (n & 1023));
            } else {
                bsv = *(const float2*)(bias + n);
            }
            float2 v01, v23;
            v01.x = acc[mi][ni][0] + bsv.x;
            v01.y = acc[mi][ni][1] + bsv.y;
            v23.x = acc[mi][ni][2] + bsv.x;
            v23.y = acc[mi][ni][3] + bsv.y;
#pragma unroll
            for (int half = 0; half < 2; half++) {
                const int m = m0 + half * 8;
                float2 v = half ? v23 : v01;
                if (MODE == EP_PROJ) {
                    const int b = m >> 10, s = m & 1023;
                    const int len = x_lengths[b] >> 2;
                    if (s >= len) { v.x = 0.f; v.y = 0.f; }
                    *(float2*)(out + (size_t)m * NN + n) = v;
                } else if (MODE == EP_QKV) {
                    const int sel = n >> 10;
                    const int nl = n & 1023;
                    const int b = m >> 10, s = m & 1023;
                    const int hh = nl >> 7, dh = nl & 127;
                    float* dst = (sel == 0) ? out : (sel == 1) ? (float*)outHi : (float*)outLo;
                    *(float2*)(dst + ((size_t)((b << 3) | hh) * 1024 + s) * 128 + dh) = v;
                } else if (MODE == EP_RESID) {
                    float2 o = *(float2*)(out + (size_t)m * NN + n);
                    o.x += v.x; o.y += v.y;
                    *(float2*)(out + (size_t)m * NN + n) = o;
                } else { // EP_SILU -> bf16 hi/lo
                    v.x = v.x / (1.f + __expf(-v.x));
                    v.y = v.y / (1.f + __expf(-v.y));
                    bf162 h, l;
                    split2(v.x, v.y, h, l);
                    const size_t o2 = ((size_t)m * NN + n) >> 1;
                    ((bf162*)outHi)[o2] = h;
                    ((bf162*)outLo)[o2] = l;
                }
            }
        }
    }
}

// -------------------- LayerNorm (templated output) --------------------
template <bool BFOUT>
__global__ void __launch_bounds__(256)
layernorm_kernel(const float* __restrict__ in, float* __restrict__ out,
                 bf16* __restrict__ outHi, bf16* __restrict__ outLo,
                 const float* __restrict__ scale, const float* __restrict__ bias)
{
    __shared__ float sh1[8];
    __shared__ float sh2[8];
    const int row = blockIdx.x;
    const int t = threadIdx.x;
    const int lane = t & 31, w = t >> 5;
    const float* xr = in + (size_t)row * 1024;

    float vals[4];
    float s = 0.f;
#pragma unroll
    for (int r = 0; r < 4; r++) { vals[r] = xr[t + 256 * r]; s += vals[r]; }
#pragma unroll
    for (int o = 16; o; o >>= 1) s += __shfl_xor_sync(0xffffffffu, s, o);
    if (lane == 0) sh1[w] = s;
    __syncthreads();
    float tot = (t < 8) ? sh1[t] : 0.f;
    if (w == 0) {
#pragma unroll
        for (int o = 16; o; o >>= 1) tot += __shfl_xor_sync(0xffffffffu, tot, o);
        if (lane == 0) sh1[0] = tot;
    }
    __syncthreads();
    const float mean = sh1[0] * (1.f / 1024.f);

    float vs = 0.f;
#pragma unroll
    for (int r = 0; r < 4; r++) { float d = vals[r] - mean; vs += d * d; }
#pragma unroll
    for (int o = 16; o; o >>= 1) vs += __shfl_xor_sync(0xffffffffu, vs, o);
    if (lane == 0) sh2[w] = vs;
    __syncthreads();
    float vtot = (t < 8) ? sh2[t] : 0.f;
    if (w == 0) {
#pragma unroll
        for (int o = 16; o; o >>= 1) vtot += __shfl_xor_sync(0xffffffffu, vtot, o);
        if (lane == 0) sh2[0] = vtot;
    }
    __syncthreads();
    const float var = sh2[0] * (1.f / 1024.f);
    const float inv = rsqrtf(var + 1e-5f);

#pragma unroll
    for (int r = 0; r < 4; r++) {
        int d = t + 256 * r;
        float v = (vals[r] - mean) * inv * scale[d] + bias[d];
        if (BFOUT) {
            bf16 h = __float2bfloat16(v);
            outHi[(size_t)row * 1024 + d] = h;
            outLo[(size_t)row * 1024 + d] = __float2bfloat16(v - __bfloat162float(h));
        } else {
            out[(size_t)row * 1024 + d] = v;
        }
    }
}

// -------------------- RoPE --------------------
__global__ void __launch_bounds__(256)
rope_kernel(float* __restrict__ q, float* __restrict__ k)
{
    const int total = B_ * H_ * S_ * 64;
    int idx = blockIdx.x * blockDim.x + threadIdx.x;
    if (idx >= 2 * total) return;
    float* ptr = (idx < total) ? q : k;
    int id = (idx < total) ? idx : idx - total;
    int p  = id & 63;
    int s  = (id >> 6) & 1023;
    int bh = id >> 16;
    float inv_freq = expf(-(float)p * (9.210340371976184f / 64.f));
    float ang = (float)s * inv_freq;
    float sn, cs;
    sincosf(ang, &sn, &cs);
    int base = (bh * 1024 + s) * 128 + p;
    float x1 = ptr[base];
    float x2 = ptr[base + 64];
    ptr[base]      = x1 * cs - x2 * sn;
    ptr[base + 64] = x1 * sn + x2 * cs;
}

// -------------------- V mean --------------------
__global__ void __launch_bounds__(128)
vmean_kernel(const float* __restrict__ v, float* __restrict__ vmean)
{
    const int bh = blockIdx.x;
    const int d  = threadIdx.x;
    const float* base = v + (size_t)bh * S_ * DH_ + d;
    float s = 0.f;
    for (int j = 0; j < S_; j++) s += base[j * DH_];
    vmean[bh * DH_ + d] = s * (1.f / (float)S_);
}

// -------------------- windowed flash attention (bf16 hi/lo ctx out) ---------
__global__ void __launch_bounds__(128)
attn_kernel(const float* __restrict__ q, const float* __restrict__ k,
            const float* __restrict__ v, const float* __restrict__ vmean,
            bf16* __restrict__ ctxHi, bf16* __restrict__ ctxLo,
            const int* __restrict__ x_lengths)
{
    const int wid  = blockIdx.x * 4 + (threadIdx.x >> 5);
    const int lane = threadIdx.x & 31;
    const int i  = wid & 1023;
    const int hh = (wid >> 10) & 7;
    const int b  = wid >> 13;

    const int len = x_lengths[b] >> 2;
    int jlo = i - (WIN_ - 1); if (jlo < 0) jlo = 0;
    int jhi = i + LFW_;       if (jhi > S_ - 1) jhi = S_ - 1;
    int jh  = (len - 1 < jhi) ? (len - 1) : jhi;

    const size_t obase = ((size_t)(b * 1024 + i)) * 1024 + hh * 128;

    if (jh < jlo) {
        const float* vm = vmean + (b * 8 + hh) * 128;
#pragma unroll
        for (int r = 0; r < 4; r++) {
            float f = vm[lane + 32 * r];
            bf16 h = __float2bfloat16(f);
            ctxHi[obase + lane + 32 * r] = h;
            ctxLo[obase + lane + 32 * r] = __float2bfloat16(f - __bfloat162float(h));
        }
        return;
    }

    const size_t head = ((size_t)(b * 8 + hh)) * 1024;
    const float* qrow = q + (head + i) * 128;
    float qr[4];
#pragma unroll
    for (int r = 0; r < 4; r++) qr[r] = qrow[lane + 32 * r];

    const float scale = 0.08838834764831845f;
    float m = -1e30f, l = 0.f;
    float acc[4] = {0.f, 0.f, 0.f, 0.f};

    for (int j = jlo; j <= jh; j++) {
        const float* krow = k + (head + j) * 128;
        float s = qr[0] * krow[lane]
                + qr[1] * krow[lane + 32]
                + qr[2] * krow[lane + 64]
                + qr[3] * krow[lane + 96];
#pragma unroll
        for (int o = 16; o; o >>= 1) s += __shfl_xor_sync(0xffffffffu, s, o);
        s *= scale;
        float mnew  = fmaxf(m, s);
        float alpha = __expf(m - mnew);
        float p     = __expf(s - mnew);
        l = l * alpha + p;
        const float* vrow = v + (head + j) * 128;
#pragma unroll
        for (int r = 0; r < 4; r++)
            acc[r] = acc[r] * alpha + p * vrow[lane + 32 * r];
        m = mnew;
    }

    const float invl = 1.f / l;
#pragma unroll
    for (int r = 0; r < 4; r++) {
        float f = acc[r] * invl;
        bf16 h = __float2bfloat16(f);
        ctxHi[obase + lane + 32 * r] = h;
        ctxLo[obase + lane + 32 * r] = __float2bfloat16(f - __bfloat162float(h));
    }
}

// -------------------- launch --------------------
extern "C" void kernel_launch(void* const* d_in, const int* in_sizes, int n_in,
                              void* d_out, int out_size)
{
    const float* x     = (const float*)d_in[0];
    const int*   xlen  = (const int*)  d_in[1];
    const float* Wp    = (const float*)d_in[2];
    const float* bp    = (const float*)d_in[3];
    const float* ln1_s = (const float*)d_in[4];
    const float* ln1_b = (const float*)d_in[5];
    const float* Wq    = (const float*)d_in[6];
    const float* bq    = (const float*)d_in[7];
    const float* Wk    = (const float*)d_in[8];
    const float* bk    = (const float*)d_in[9];
    const float* Wv    = (const float*)d_in[10];
    const float* bv    = (const float*)d_in[11];
    const float* Wo    = (const float*)d_in[12];
    const float* bo    = (const float*)d_in[13];
    const float* ln2_s = (const float*)d_in[14];
    const float* ln2_b = (const float*)d_in[15];
    const float* W1    = (const float*)d_in[16];
    const float* b1    = (const float*)d_in[17];
    const float* W2    = (const float*)d_in[18];
    const float* b2    = (const float*)d_in[19];
    const float* lnf_s = (const float*)d_in[20];
    const float* lnf_b = (const float*)d_in[21];
    float* out = (float*)d_out;

    float *h, *q, *k, *v, *vmean;
    bf16 *xhi, *xlo, *yhi, *ylo, *chi, *clo, *fhi, *flo, *whi, *wlo;
    cudaGetSymbolAddress((void**)&h,    g_h);
    cudaGetSymbolAddress((void**)&q,    g_q);
    cudaGetSymbolAddress((void**)&k,    g_k);
    cudaGetSymbolAddress((void**)&v,    g_v);
    cudaGetSymbolAddress((void**)&vmean,g_vmean);
    cudaGetSymbolAddress((void**)&xhi,  g_xhi);
    cudaGetSymbolAddress((void**)&xlo,  g_xlo);
    cudaGetSymbolAddress((void**)&yhi,  g_yhi);
    cudaGetSymbolAddress((void**)&ylo,  g_ylo);
    cudaGetSymbolAddress((void**)&chi,  g_chi);
    cudaGetSymbolAddress((void**)&clo,  g_clo);
    cudaGetSymbolAddress((void**)&fhi,  g_fhi);
    cudaGetSymbolAddress((void**)&flo,  g_flo);
    cudaGetSymbolAddress((void**)&whi,  g_whi);
    cudaGetSymbolAddress((void**)&wlo,  g_wlo);

    cudaFuncSetAttribute(mma_gemm<EP_PROJ>,  cudaFuncAttributeMaxDynamicSharedMemorySize, GEMM_SMEM);
    cudaFuncSetAttribute(mma_gemm<EP_QKV>,   cudaFuncAttributeMaxDynamicSharedMemorySize, GEMM_SMEM);
    cudaFuncSetAttribute(mma_gemm<EP_RESID>, cudaFuncAttributeMaxDynamicSharedMemorySize, GEMM_SMEM);
    cudaFuncSetAttribute(mma_gemm<EP_SILU>,  cudaFuncAttributeMaxDynamicSharedMemorySize, GEMM_SMEM);

    const dim3 blk(256);

    // ---- converters (every call; deterministic) ----
    conv_split<<<(NTOK * 2048 / 4 + 255) / 256, blk>>>(x, xhi, xlo, NTOK * 2048 / 4);
    conv_split<<<(2048 * 1024 / 4 + 255) / 256, blk>>>(Wp, whi + WP_OFF, wlo + WP_OFF, 2048 * 1024 / 4);
    conv_split_qkv<<<4096, blk>>>(Wq, whi + QKV_OFF, wlo + QKV_OFF, 0);
    conv_split_qkv<<<4096, blk>>>(Wk, whi + QKV_OFF, wlo + QKV_OFF, 1024);
    conv_split_qkv<<<4096, blk>>>(Wv, whi + QKV_OFF, wlo + QKV_OFF, 2048);
    conv_split<<<(4 * 1048576 / 4 + 255) / 256, blk>>>(Wo, whi + WO_OFF, wlo + WO_OFF, 4 * 1048576 / 4);
    conv_split<<<(4 * 4194304 / 4 + 255) / 256, blk>>>(W1, whi + W1_OFF, wlo + W1_OFF, 4 * 4194304 / 4);
    conv_split<<<(4 * 4194304 / 4 + 255) / 256, blk>>>(W2, whi + W2_OFF, wlo + W2_OFF, 4 * 4194304 / 4);

    // projector: h = (x @ Wp + bp) * pad   (K=2048, NN=1024)
    mma_gemm<EP_PROJ><<<dim3(8, 32), blk, GEMM_SMEM>>>(
        2048, 1024, xhi, xlo, whi + WP_OFF, wlo + WP_OFF,
        bp, nullptr, nullptr, h, nullptr, nullptr, xlen);

    for (int l = 0; l < L_; l++) {
        const size_t oD  = (size_t)l * D_;
        const size_t oF  = (size_t)l * F_;
        const uint32_t oQKV = QKV_OFF + (uint32_t)l * 3145728u;
        const uint32_t oWO  = WO_OFF  + (uint32_t)l * 1048576u;
        const uint32_t oW1  = W1_OFF  + (uint32_t)l * 4194304u;
        const uint32_t oW2  = W2_OFF  + (uint32_t)l * 4194304u;

        layernorm_kernel<true><<<NTOK, blk>>>(h, nullptr, yhi, ylo, ln1_s + oD, ln1_b + oD);

        // fused QKV GEMM: NN=3072; outputs q,k,v (fp32 [B,H,S,Dh])
        mma_gemm<EP_QKV><<<dim3(24, 32), blk, GEMM_SMEM>>>(
            1024, 3072, yhi, ylo, whi + oQKV, wlo + oQKV,
            bq + oD, bk + oD, bv + oD, q, (bf16*)k, (bf16*)v, nullptr);

        rope_kernel<<<(2 * B_ * H_ * S_ * 64) / 256, blk>>>(q, k);
        vmean_kernel<<<B_ * H_, 128>>>(v, vmean);
        attn_kernel<<<(B_ * H_ * S_) / 4, 128>>>(q, k, v, vmean, chi, clo, xlen);

        mma_gemm<EP_RESID><<<dim3(8, 32), blk, GEMM_SMEM>>>(
            1024, 1024, chi, clo, whi + oWO, wlo + oWO,
            bo + oD, nullptr, nullptr, h, nullptr, nullptr, nullptr);

        layernorm_kernel<true><<<NTOK, blk>>>(h, nullptr, yhi, ylo, ln2_s + oD, ln2_b + oD);

        mma_gemm<EP_SILU><<<dim3(32, 32), blk, GEMM_SMEM>>>(
            1024, 4096, yhi, ylo, whi + oW1, wlo + oW1,
            b1 + oF, nullptr, nullptr, nullptr, fhi, flo, nullptr);

        mma_gemm<EP_RESID><<<dim3(8, 32), blk, GEMM_SMEM>>>(
            4096, 1024, fhi, flo, whi + oW2, wlo + oW2,
            b2 + oD, nullptr, nullptr, h, nullptr, nullptr, nullptr);
    }

    layernorm_kernel<false><<<NTOK, blk>>>(h, out, nullptr, nullptr, lnf_s, lnf_b);
}

// round 6
// speedup vs baseline: 3.7259x; 1.5338x over previous
#include <cuda_runtime.h>
#include <cuda_fp16.h>
#include <math.h>
#include <stdint.h>

// Problem constants
#define B_   4
#define S_   1024
#define D_   1024
#define F_   4096
#define H_   8
#define DH_  128
#define L_   4
#define NTOK (B_ * S_)          // 4096
#define WIN_ 100
#define LFW_ 20

typedef __half  hf;
typedef __half2 hf2;

// -------------------- scratch --------------------
__device__ float g_h [NTOK * D_];
__device__ float g_q [NTOK * D_];
__device__ float g_k [NTOK * D_];
__device__ float g_v [NTOK * D_];
__device__ float g_vmean[B_ * H_ * DH_];

// fp16 hi/lo activation buffers
__device__ hf g_xhi[NTOK * 2048], g_xlo[NTOK * 2048];
__device__ hf g_yhi[NTOK * D_],   g_ylo[NTOK * D_];
__device__ hf g_chi[NTOK * D_],   g_clo[NTOK * D_];
__device__ hf g_fhi[NTOK * F_],   g_flo[NTOK * F_];

// converted weights (single fp16), offsets in elements
#define WP_OFF   0u
#define QKV_OFF  2097152u
#define WO_OFF   (QKV_OFF + 4u * 3145728u)
#define W1_OFF   (WO_OFF + 4u * 1048576u)
#define W2_OFF   (W1_OFF + 4u * 4194304u)
#define WTOT     (W2_OFF + 4u * 4194304u)
__device__ hf g_w[WTOT];

// ==================== helpers ====================
__device__ __forceinline__ uint32_t smem_u32(const void* p) {
    uint32_t a;
    asm("{ .reg .u64 t; cvta.to.shared.u64 t, %1; cvt.u32.u64 %0, t; }" : "=r"(a) : "l"(p));
    return a;
}
__device__ __forceinline__ void cp16(uint32_t saddr, const void* gaddr) {
    asm volatile("cp.async.cg.shared.global [%0], [%1], 16;" :: "r"(saddr), "l"(gaddr));
}
__device__ __forceinline__ void cp_commit() {
    asm volatile("cp.async.commit_group;" ::: "memory");
}
__device__ __forceinline__ void ldsm4(uint32_t& r0, uint32_t& r1, uint32_t& r2, uint32_t& r3,
                                      uint32_t addr) {
    asm volatile("ldmatrix.sync.aligned.m8n8.x4.shared.b16 {%0,%1,%2,%3}, [%4];"
                 : "=r"(r0), "=r"(r1), "=r"(r2), "=r"(r3) : "r"(addr));
}
__device__ __forceinline__ void ldsm4t(uint32_t& r0, uint32_t& r1, uint32_t& r2, uint32_t& r3,
                                       uint32_t addr) {
    asm volatile("ldmatrix.sync.aligned.m8n8.x4.trans.shared.b16 {%0,%1,%2,%3}, [%4];"
                 : "=r"(r0), "=r"(r1), "=r"(r2), "=r"(r3) : "r"(addr));
}
__device__ __forceinline__ void mma16816(float* d, const uint32_t* a, const uint32_t* b) {
    asm volatile(
        "mma.sync.aligned.m16n8k16.row.col.f32.f16.f16.f32 "
        "{%0,%1,%2,%3}, {%4,%5,%6,%7}, {%8,%9}, {%0,%1,%2,%3};"
        : "+f"(d[0]), "+f"(d[1]), "+f"(d[2]), "+f"(d[3])
        : "r"(a[0]), "r"(a[1]), "r"(a[2]), "r"(a[3]), "r"(b[0]), "r"(b[1]));
}
__device__ __forceinline__ void split2h(float x, float y, hf2& h, hf2& l) {
    h = __floats2half2_rn(x, y);
    float2 hfv = __half22float2(h);
    l = __floats2half2_rn(x - hfv.x, y - hfv.y);
}

// ==================== converters ====================
// activations: fp32 -> fp16 hi/lo
__global__ void __launch_bounds__(256)
conv_split(const float* __restrict__ in, hf* __restrict__ hi, hf* __restrict__ lo, int n4)
{
    int i = blockIdx.x * blockDim.x + threadIdx.x;
    if (i >= n4) return;
    float4 v = ((const float4*)in)[i];
    hf2 h0, l0, h1, l1;
    split2h(v.x, v.y, h0, l0);
    split2h(v.z, v.w, h1, l1);
    ((hf2*)hi)[2 * i] = h0; ((hf2*)hi)[2 * i + 1] = h1;
    ((hf2*)lo)[2 * i] = l0; ((hf2*)lo)[2 * i + 1] = l1;
}
// weights: fp32 -> single fp16
__global__ void __launch_bounds__(256)
conv_w(const float* __restrict__ in, hf* __restrict__ w, int n4)
{
    int i = blockIdx.x * blockDim.x + threadIdx.x;
    if (i >= n4) return;
    float4 v = ((const float4*)in)[i];
    ((hf2*)w)[2 * i]     = __floats2half2_rn(v.x, v.y);
    ((hf2*)w)[2 * i + 1] = __floats2half2_rn(v.z, v.w);
}
// QKV weight interleave: in [1024*? rows,1024] -> pitch 3072 at column offset coff
__global__ void __launch_bounds__(256)
conv_w_qkv(const float* __restrict__ in, hf* __restrict__ w, int coff)
{
    int i = blockIdx.x * blockDim.x + threadIdx.x;   // 0 .. 1024*256-1 per 4 rows... grid covers all
    int row = i >> 8, c4 = i & 255;
    float4 v = ((const float4*)in)[i];
    size_t o2 = ((size_t)row * 3072 + coff + c4 * 4) >> 1;
    ((hf2*)w)[o2]     = __floats2half2_rn(v.x, v.y);
    ((hf2*)w)[o2 + 1] = __floats2half2_rn(v.z, v.w);
}

// ==================== pipelined fp16-split GEMM (mma.sync + cp.async) =======
// C[4096, NN] = A[4096,K] @ W[K,NN]; A as fp16 hi+lo, W single fp16.
// CTA 128x128, K-chunk 64, 2-stage, 8 warps (2m x 4n), 2 CTAs/SM.
#define EP_PROJ  1
#define EP_QKV   2
#define EP_RESID 3
#define EP_SILU  4

#define A_PITCH 144
#define B_PITCH 272
#define OFF_AH 0
#define OFF_AL 18432
#define OFF_B  36864
#define STAGE_B 54272
#define GEMM_SMEM (2 * STAGE_B)   // 108544

__device__ __forceinline__ void stage_load(
    uint32_t stb, const hf* Ah, const hf* Al, const hf* Bw,
    int k0, int bm, int bn, int K, int NN, int tid)
{
#pragma unroll
    for (int t = 0; t < 4; t++) {
        const int idx = t * 256 + tid;          // 0..1023
        const int row = idx >> 3, seg = idx & 7;
        const size_t go = (size_t)(bm + row) * K + k0 + seg * 8;
        const uint32_t so = stb + (uint32_t)row * A_PITCH + seg * 16;
        cp16(so + OFF_AH, Ah + go);
        cp16(so + OFF_AL, Al + go);
    }
#pragma unroll
    for (int t = 0; t < 4; t++) {
        const int idx = t * 256 + tid;          // 0..1023
        const int row = idx >> 4, seg = idx & 15;
        const size_t go = (size_t)(k0 + row) * NN + bn + seg * 8;
        const uint32_t so = stb + (uint32_t)row * B_PITCH + seg * 16;
        cp16(so + OFF_B, Bw + go);
    }
}

template <int MODE>
__global__ void __launch_bounds__(256, 2)
mma_gemm(int K, int NN,
         const hf* __restrict__ Ah, const hf* __restrict__ Al,
         const hf* __restrict__ Bw,
         const float* __restrict__ bias, const float* __restrict__ bias2,
         const float* __restrict__ bias3,
         float* __restrict__ out, hf* __restrict__ outHi, hf* __restrict__ outLo,
         const int* __restrict__ x_lengths)
{
    extern __shared__ char sm[];
    const uint32_t sb = smem_u32(sm);
    const int tid  = threadIdx.x;
    const int wid  = tid >> 5;
    const int lane = tid & 31;
    const int bn = blockIdx.x * 128;
    const int bm = blockIdx.y * 128;
    const int wm = wid & 1;
    const int wn = wid >> 1;

    float acc[4][4][4];
#pragma unroll
    for (int i = 0; i < 4; i++)
#pragma unroll
        for (int j = 0; j < 4; j++)
#pragma unroll
            for (int r = 0; r < 4; r++) acc[i][j][r] = 0.f;

    const int quad = lane >> 3;
    const int qr   = lane & 7;
    const uint32_t aOffH = OFF_AH + (uint32_t)(wm * 64 + (quad & 1) * 8 + qr) * A_PITCH + (quad >> 1) * 16;
    const uint32_t bOff  = OFF_B + (uint32_t)((quad & 1) * 8 + qr) * B_PITCH
                         + (uint32_t)(wn * 32 + (quad >> 1) * 8) * 2;

    const int nch = K >> 6;

    stage_load(sb, Ah, Al, Bw, 0, bm, bn, K, NN, tid);
    cp_commit();
    if (nch > 1) {
        stage_load(sb + STAGE_B, Ah, Al, Bw, 64, bm, bn, K, NN, tid);
        cp_commit();
    }

    for (int c = 0; c < nch; c++) {
        if (c < nch - 1) asm volatile("cp.async.wait_group 1;" ::: "memory");
        else             asm volatile("cp.async.wait_group 0;" ::: "memory");
        __syncthreads();

        const uint32_t stb = sb + (uint32_t)(c & 1) * STAGE_B;

#pragma unroll
        for (int ks = 0; ks < 4; ks++) {
            uint32_t aH[4][4], aL[4][4], bF[4][2];
#pragma unroll
            for (int mi = 0; mi < 4; mi++) {
                const uint32_t ad = stb + aOffH + (uint32_t)mi * (16 * A_PITCH) + ks * 32;
                ldsm4(aH[mi][0], aH[mi][1], aH[mi][2], aH[mi][3], ad);
                ldsm4(aL[mi][0], aL[mi][1], aL[mi][2], aL[mi][3], ad + (OFF_AL - OFF_AH));
            }
#pragma unroll
            for (int bp = 0; bp < 2; bp++) {
                const uint32_t ad = stb + bOff + (uint32_t)ks * (16 * B_PITCH) + bp * 32;
                uint32_t r0, r1, r2, r3;
                ldsm4t(r0, r1, r2, r3, ad);
                bF[2 * bp][0] = r0; bF[2 * bp][1] = r1;
                bF[2 * bp + 1][0] = r2; bF[2 * bp + 1][1] = r3;
            }
#pragma unroll
            for (int mi = 0; mi < 4; mi++)
#pragma unroll
                for (int ni = 0; ni < 4; ni++) {
                    mma16816(acc[mi][ni], aH[mi], bF[ni]);
                    mma16816(acc[mi][ni], aL[mi], bF[ni]);
                }
        }
        __syncthreads();

        if (c + 2 < nch) {
            stage_load(stb, Ah, Al, Bw, (c + 2) << 6, bm, bn, K, NN, tid);
            cp_commit();
        }
    }

    // ---- epilogue ----
    const int grp = lane >> 2;
    const int qc  = (lane & 3) * 2;
#pragma unroll
    for (int mi = 0; mi < 4; mi++) {
        const int m0 = bm + wm * 64 + mi * 16 + grp;
#pragma unroll
        for (int ni = 0; ni < 4; ni++) {
            const int n = bn + wn * 32 + ni * 8 + qc;
            float2 bsv;
            if (MODE == EP_QKV) {
                const int sel = n >> 10;
                const float* bp = (sel == 0) ? bias : (sel == 1) ? bias2 : bias3;
                bsv = *(const float2*)(bp + (n & 1023));
            } else {
                bsv = *(const float2*)(bias + n);
            }
            float2 v01, v23;
            v01.x = acc[mi][ni][0] + bsv.x;
            v01.y = acc[mi][ni][1] + bsv.y;
            v23.x = acc[mi][ni][2] + bsv.x;
            v23.y = acc[mi][ni][3] + bsv.y;
#pragma unroll
            for (int half = 0; half < 2; half++) {
                const int m = m0 + half * 8;
                float2 v = half ? v23 : v01;
                if (MODE == EP_PROJ) {
                    const int b = m >> 10, s = m & 1023;
                    const int len = x_lengths[b] >> 2;
                    if (s >= len) { v.x = 0.f; v.y = 0.f; }
                    *(float2*)(out + (size_t)m * NN + n) = v;
                } else if (MODE == EP_QKV) {
                    const int sel = n >> 10;
                    const int nl = n & 1023;
                    const int b = m >> 10, s = m & 1023;
                    const int hh = nl >> 7, dh = nl & 127;
                    float* dst = (sel == 0) ? out : (sel == 1) ? (float*)outHi : (float*)outLo;
                    *(float2*)(dst + ((size_t)((b << 3) | hh) * 1024 + s) * 128 + dh) = v;
                } else if (MODE == EP_RESID) {
                    float2 o = *(float2*)(out + (size_t)m * NN + n);
                    o.x += v.x; o.y += v.y;
                    *(float2*)(out + (size_t)m * NN + n) = o;
                } else { // EP_SILU -> fp16 hi/lo
                    v.x = v.x / (1.f + __expf(-v.x));
                    v.y = v.y / (1.f + __expf(-v.y));
                    hf2 h, l;
                    split2h(v.x, v.y, h, l);
                    const size_t o2 = ((size_t)m * NN + n) >> 1;
                    ((hf2*)outHi)[o2] = h;
                    ((hf2*)outLo)[o2] = l;
                }
            }
        }
    }
}

// -------------------- LayerNorm --------------------
template <bool HFOUT>
__global__ void __launch_bounds__(256)
layernorm_kernel(const float* __restrict__ in, float* __restrict__ out,
                 hf* __restrict__ outHi, hf* __restrict__ outLo,
                 const float* __restrict__ scale, const float* __restrict__ bias)
{
    __shared__ float sh1[8];
    __shared__ float sh2[8];
    const int row = blockIdx.x;
    const int t = threadIdx.x;
    const int lane = t & 31, w = t >> 5;
    const float* xr = in + (size_t)row * 1024;

    float vals[4];
    float s = 0.f;
#pragma unroll
    for (int r = 0; r < 4; r++) { vals[r] = xr[t + 256 * r]; s += vals[r]; }
#pragma unroll
    for (int o = 16; o; o >>= 1) s += __shfl_xor_sync(0xffffffffu, s, o);
    if (lane == 0) sh1[w] = s;
    __syncthreads();
    float tot = (t < 8) ? sh1[t] : 0.f;
    if (w == 0) {
#pragma unroll
        for (int o = 16; o; o >>= 1) tot += __shfl_xor_sync(0xffffffffu, tot, o);
        if (lane == 0) sh1[0] = tot;
    }
    __syncthreads();
    const float mean = sh1[0] * (1.f / 1024.f);

    float vs = 0.f;
#pragma unroll
    for (int r = 0; r < 4; r++) { float d = vals[r] - mean; vs += d * d; }
#pragma unroll
    for (int o = 16; o; o >>= 1) vs += __shfl_xor_sync(0xffffffffu, vs, o);
    if (lane == 0) sh2[w] = vs;
    __syncthreads();
    float vtot = (t < 8) ? sh2[t] : 0.f;
    if (w == 0) {
#pragma unroll
        for (int o = 16; o; o >>= 1) vtot += __shfl_xor_sync(0xffffffffu, vtot, o);
        if (lane == 0) sh2[0] = vtot;
    }
    __syncthreads();
    const float var = sh2[0] * (1.f / 1024.f);
    const float inv = rsqrtf(var + 1e-5f);

#pragma unroll
    for (int r = 0; r < 4; r++) {
        int d = t + 256 * r;
        float v = (vals[r] - mean) * inv * scale[d] + bias[d];
        if (HFOUT) {
            hf h = __float2half_rn(v);
            outHi[(size_t)row * 1024 + d] = h;
            outLo[(size_t)row * 1024 + d] = __float2half_rn(v - __half2float(h));
        } else {
            out[(size_t)row * 1024 + d] = v;
        }
    }
}

// -------------------- RoPE --------------------
__global__ void __launch_bounds__(256)
rope_kernel(float* __restrict__ q, float* __restrict__ k)
{
    const int total = B_ * H_ * S_ * 64;
    int idx = blockIdx.x * blockDim.x + threadIdx.x;
    if (idx >= 2 * total) return;
    float* ptr = (idx < total) ? q : k;
    int id = (idx < total) ? idx : idx - total;
    int p  = id & 63;
    int s  = (id >> 6) & 1023;
    int bh = id >> 16;
    float inv_freq = expf(-(float)p * (9.210340371976184f / 64.f));
    float ang = (float)s * inv_freq;
    float sn, cs;
    sincosf(ang, &sn, &cs);
    int base = (bh * 1024 + s) * 128 + p;
    float x1 = ptr[base];
    float x2 = ptr[base + 64];
    ptr[base]      = x1 * cs - x2 * sn;
    ptr[base + 64] = x1 * sn + x2 * cs;
}

// -------------------- V mean --------------------
__global__ void __launch_bounds__(128)
vmean_kernel(const float* __restrict__ v, float* __restrict__ vmean)
{
    const int bh = blockIdx.x;
    const int d  = threadIdx.x;
    const float* base = v + (size_t)bh * S_ * DH_ + d;
    float s = 0.f;
    for (int j = 0; j < S_; j++) s += base[j * DH_];
    vmean[bh * DH_ + d] = s * (1.f / (float)S_);
}

// -------------------- windowed flash attention (fp16 hi/lo ctx out) ---------
__global__ void __launch_bounds__(128)
attn_kernel(const float* __restrict__ q, const float* __restrict__ k,
            const float* __restrict__ v, const float* __restrict__ vmean,
            hf* __restrict__ ctxHi, hf* __restrict__ ctxLo,
            const int* __restrict__ x_lengths)
{
    const int wid  = blockIdx.x * 4 + (threadIdx.x >> 5);
    const int lane = threadIdx.x & 31;
    const int i  = wid & 1023;
    const int hh = (wid >> 10) & 7;
    const int b  = wid >> 13;

    const int len = x_lengths[b] >> 2;
    int jlo = i - (WIN_ - 1); if (jlo < 0) jlo = 0;
    int jhi = i + LFW_;       if (jhi > S_ - 1) jhi = S_ - 1;
    int jh  = (len - 1 < jhi) ? (len - 1) : jhi;

    const size_t obase = ((size_t)(b * 1024 + i)) * 1024 + hh * 128;

    if (jh < jlo) {
        const float* vm = vmean + (b * 8 + hh) * 128;
#pragma unroll
        for (int r = 0; r < 4; r++) {
            float f = vm[lane + 32 * r];
            hf h = __float2half_rn(f);
            ctxHi[obase + lane + 32 * r] = h;
            ctxLo[obase + lane + 32 * r] = __float2half_rn(f - __half2float(h));
        }
        return;
    }

    const size_t head = ((size_t)(b * 8 + hh)) * 1024;
    const float* qrow = q + (head + i) * 128;
    float qr[4];
#pragma unroll
    for (int r = 0; r < 4; r++) qr[r] = qrow[lane + 32 * r];

    const float scale = 0.08838834764831845f;
    float m = -1e30f, l = 0.f;
    float acc[4] = {0.f, 0.f, 0.f, 0.f};

    for (int j = jlo; j <= jh; j++) {
        const float* krow = k + (head + j) * 128;
        float s = qr[0] * krow[lane]
                + qr[1] * krow[lane + 32]
                + qr[2] * krow[lane + 64]
                + qr[3] * krow[lane + 96];
#pragma unroll
        for (int o = 16; o; o >>= 1) s += __shfl_xor_sync(0xffffffffu, s, o);
        s *= scale;
        float mnew  = fmaxf(m, s);
        float alpha = __expf(m - mnew);
        float p     = __expf(s - mnew);
        l = l * alpha + p;
        const float* vrow = v + (head + j) * 128;
#pragma unroll
        for (int r = 0; r < 4; r++)
            acc[r] = acc[r] * alpha + p * vrow[lane + 32 * r];
        m = mnew;
    }

    const float invl = 1.f / l;
#pragma unroll
    for (int r = 0; r < 4; r++) {
        float f = acc[r] * invl;
        hf h = __float2half_rn(f);
        ctxHi[obase + lane + 32 * r] = h;
        ctxLo[obase + lane + 32 * r] = __float2half_rn(f - __half2float(h));
    }
}

// -------------------- launch --------------------
extern "C" void kernel_launch(void* const* d_in, const int* in_sizes, int n_in,
                              void* d_out, int out_size)
{
    const float* x     = (const float*)d_in[0];
    const int*   xlen  = (const int*)  d_in[1];
    const float* Wp    = (const float*)d_in[2];
    const float* bp    = (const float*)d_in[3];
    const float* ln1_s = (const float*)d_in[4];
    const float* ln1_b = (const float*)d_in[5];
    const float* Wq    = (const float*)d_in[6];
    const float* bq    = (const float*)d_in[7];
    const float* Wk    = (const float*)d_in[8];
    const float* bk    = (const float*)d_in[9];
    const float* Wv    = (const float*)d_in[10];
    const float* bv    = (const float*)d_in[11];
    const float* Wo    = (const float*)d_in[12];
    const float* bo    = (const float*)d_in[13];
    const float* ln2_s = (const float*)d_in[14];
    const float* ln2_b = (const float*)d_in[15];
    const float* W1    = (const float*)d_in[16];
    const float* b1    = (const float*)d_in[17];
    const float* W2    = (const float*)d_in[18];
    const float* b2    = (const float*)d_in[19];
    const float* lnf_s = (const float*)d_in[20];
    const float* lnf_b = (const float*)d_in[21];
    float* out = (float*)d_out;

    float *h, *q, *k, *v, *vmean;
    hf *xhi, *xlo, *yhi, *ylo, *chi, *clo, *fhi, *flo, *w;
    cudaGetSymbolAddress((void**)&h,    g_h);
    cudaGetSymbolAddress((void**)&q,    g_q);
    cudaGetSymbolAddress((void**)&k,    g_k);
    cudaGetSymbolAddress((void**)&v,    g_v);
    cudaGetSymbolAddress((void**)&vmean,g_vmean);
    cudaGetSymbolAddress((void**)&xhi,  g_xhi);
    cudaGetSymbolAddress((void**)&xlo,  g_xlo);
    cudaGetSymbolAddress((void**)&yhi,  g_yhi);
    cudaGetSymbolAddress((void**)&ylo,  g_ylo);
    cudaGetSymbolAddress((void**)&chi,  g_chi);
    cudaGetSymbolAddress((void**)&clo,  g_clo);
    cudaGetSymbolAddress((void**)&fhi,  g_fhi);
    cudaGetSymbolAddress((void**)&flo,  g_flo);
    cudaGetSymbolAddress((void**)&w,    g_w);

    cudaFuncSetAttribute(mma_gemm<EP_PROJ>,  cudaFuncAttributeMaxDynamicSharedMemorySize, GEMM_SMEM);
    cudaFuncSetAttribute(mma_gemm<EP_QKV>,   cudaFuncAttributeMaxDynamicSharedMemorySize, GEMM_SMEM);
    cudaFuncSetAttribute(mma_gemm<EP_RESID>, cudaFuncAttributeMaxDynamicSharedMemorySize, GEMM_SMEM);
    cudaFuncSetAttribute(mma_gemm<EP_SILU>,  cudaFuncAttributeMaxDynamicSharedMemorySize, GEMM_SMEM);

    const dim3 blk(256);

    // ---- converters ----
    conv_split<<<(NTOK * 2048 / 4 + 255) / 256, blk>>>(x, xhi, xlo, NTOK * 2048 / 4);
    conv_w<<<(2048 * 1024 / 4 + 255) / 256, blk>>>(Wp, w + WP_OFF, 2048 * 1024 / 4);
    conv_w_qkv<<<4096, blk>>>(Wq, w + QKV_OFF, 0);
    conv_w_qkv<<<4096, blk>>>(Wk, w + QKV_OFF, 1024);
    conv_w_qkv<<<4096, blk>>>(Wv, w + QKV_OFF, 2048);
    conv_w<<<(4 * 1048576 / 4 + 255) / 256, blk>>>(Wo, w + WO_OFF, 4 * 1048576 / 4);
    conv_w<<<(4 * 4194304 / 4 + 255) / 256, blk>>>(W1, w + W1_OFF, 4 * 4194304 / 4);
    conv_w<<<(4 * 4194304 / 4 + 255) / 256, blk>>>(W2, w + W2_OFF, 4 * 4194304 / 4);

    // projector: h = (x @ Wp + bp) * pad   (K=2048, NN=1024)
    mma_gemm<EP_PROJ><<<dim3(8, 32), blk, GEMM_SMEM>>>(
        2048, 1024, xhi, xlo, w + WP_OFF,
        bp, nullptr, nullptr, h, nullptr, nullptr, xlen);

    for (int l = 0; l < L_; l++) {
        const size_t oD  = (size_t)l * D_;
        const size_t oF  = (size_t)l * F_;
        const uint32_t oQKV = QKV_OFF + (uint32_t)l * 3145728u;
        const uint32_t oWO  = WO_OFF  + (uint32_t)l * 1048576u;
        const uint32_t oW1  = W1_OFF  + (uint32_t)l * 4194304u;
        const uint32_t oW2  = W2_OFF  + (uint32_t)l * 4194304u;

        layernorm_kernel<true><<<NTOK, blk>>>(h, nullptr, yhi, ylo, ln1_s + oD, ln1_b + oD);

        mma_gemm<EP_QKV><<<dim3(24, 32), blk, GEMM_SMEM>>>(
            1024, 3072, yhi, ylo, w + oQKV,
            bq + oD, bk + oD, bv + oD, q, (hf*)k, (hf*)v, nullptr);

        rope_kernel<<<(2 * B_ * H_ * S_ * 64) / 256, blk>>>(q, k);
        vmean_kernel<<<B_ * H_, 128>>>(v, vmean);
        attn_kernel<<<(B_ * H_ * S_) / 4, 128>>>(q, k, v, vmean, chi, clo, xlen);

        mma_gemm<EP_RESID><<<dim3(8, 32), blk, GEMM_SMEM>>>(
            1024, 1024, chi, clo, w + oWO,
            bo + oD, nullptr, nullptr, h, nullptr, nullptr, nullptr);

        layernorm_kernel<true><<<NTOK, blk>>>(h, nullptr, yhi, ylo, ln2_s + oD, ln2_b + oD);

        mma_gemm<EP_SILU><<<dim3(32, 32), blk, GEMM_SMEM>>>(
            1024, 4096, yhi, ylo, w + oW1,
            b1 + oF, nullptr, nullptr, nullptr, fhi, flo, nullptr);

        mma_gemm<EP_RESID><<<dim3(8, 32), blk, GEMM_SMEM>>>(
            4096, 1024, fhi, flo, w + oW2,
            b2 + oD, nullptr, nullptr, h, nullptr, nullptr, nullptr);
    }

    layernorm_kernel<false><<<NTOK, blk>>>(h, out, nullptr, nullptr, lnf_s, lnf_b);
}

// round 7
// speedup vs baseline: 3.7264x; 1.0001x over previous
#include <cuda_runtime.h>
#include <cuda_fp16.h>
#include <math.h>
#include <stdint.h>

// Problem constants
#define B_   4
#define S_   1024
#define D_   1024
#define F_   4096
#define H_   8
#define DH_  128
#define L_   4
#define NTOK (B_ * S_)          // 4096
#define WIN_ 100
#define LFW_ 20

typedef __half  hf;
typedef __half2 hf2;

// -------------------- scratch --------------------
__device__ float g_h [NTOK * D_];
__device__ float g_q [NTOK * D_];
__device__ float g_k [NTOK * D_];
__device__ float g_v [NTOK * D_];
__device__ float g_vmean[B_ * H_ * DH_];
__device__ float g_rcos[S_ * 64];
__device__ float g_rsin[S_ * 64];

// fp16 hi/lo activation buffers
__device__ hf g_xhi[NTOK * 2048], g_xlo[NTOK * 2048];
__device__ hf g_yhi[NTOK * D_],   g_ylo[NTOK * D_];
__device__ hf g_chi[NTOK * D_],   g_clo[NTOK * D_];
__device__ hf g_fhi[NTOK * F_],   g_flo[NTOK * F_];

// converted weights (single fp16), offsets in elements
#define WP_OFF   0u
#define QKV_OFF  2097152u
#define WO_OFF   (QKV_OFF + 4u * 3145728u)
#define W1_OFF   (WO_OFF + 4u * 1048576u)
#define W2_OFF   (W1_OFF + 4u * 4194304u)
#define WTOT     (W2_OFF + 4u * 4194304u)
__device__ hf g_w[WTOT];

// ==================== helpers ====================
__device__ __forceinline__ uint32_t smem_u32(const void* p) {
    uint32_t a;
    asm("{ .reg .u64 t; cvta.to.shared.u64 t, %1; cvt.u32.u64 %0, t; }" : "=r"(a) : "l"(p));
    return a;
}
__device__ __forceinline__ void cp16(uint32_t saddr, const void* gaddr) {
    asm volatile("cp.async.cg.shared.global [%0], [%1], 16;" :: "r"(saddr), "l"(gaddr));
}
__device__ __forceinline__ void cp_commit() {
    asm volatile("cp.async.commit_group;" ::: "memory");
}
__device__ __forceinline__ void ldsm4(uint32_t& r0, uint32_t& r1, uint32_t& r2, uint32_t& r3,
                                      uint32_t addr) {
    asm volatile("ldmatrix.sync.aligned.m8n8.x4.shared.b16 {%0,%1,%2,%3}, [%4];"
                 : "=r"(r0), "=r"(r1), "=r"(r2), "=r"(r3) : "r"(addr));
}
__device__ __forceinline__ void ldsm4t(uint32_t& r0, uint32_t& r1, uint32_t& r2, uint32_t& r3,
                                       uint32_t addr) {
    asm volatile("ldmatrix.sync.aligned.m8n8.x4.trans.shared.b16 {%0,%1,%2,%3}, [%4];"
                 : "=r"(r0), "=r"(r1), "=r"(r2), "=r"(r3) : "r"(addr));
}
__device__ __forceinline__ void mma16816(float* d, const uint32_t* a, const uint32_t* b) {
    asm volatile(
        "mma.sync.aligned.m16n8k16.row.col.f32.f16.f16.f32 "
        "{%0,%1,%2,%3}, {%4,%5,%6,%7}, {%8,%9}, {%0,%1,%2,%3};"
        : "+f"(d[0]), "+f"(d[1]), "+f"(d[2]), "+f"(d[3])
        : "r"(a[0]), "r"(a[1]), "r"(a[2]), "r"(a[3]), "r"(b[0]), "r"(b[1]));
}
__device__ __forceinline__ void split2h(float x, float y, hf2& h, hf2& l) {
    h = __floats2half2_rn(x, y);
    float2 hfv = __half22float2(h);
    l = __floats2half2_rn(x - hfv.x, y - hfv.y);
}

// ==================== converters ====================
__global__ void __launch_bounds__(256)
conv_split(const float* __restrict__ in, hf* __restrict__ hi, hf* __restrict__ lo, int n4)
{
    int i = blockIdx.x * blockDim.x + threadIdx.x;
    if (i >= n4) return;
    float4 v = ((const float4*)in)[i];
    hf2 h0, l0, h1, l1;
    split2h(v.x, v.y, h0, l0);
    split2h(v.z, v.w, h1, l1);
    ((hf2*)hi)[2 * i] = h0; ((hf2*)hi)[2 * i + 1] = h1;
    ((hf2*)lo)[2 * i] = l0; ((hf2*)lo)[2 * i + 1] = l1;
}
__global__ void __launch_bounds__(256)
conv_w(const float* __restrict__ in, hf* __restrict__ w, int n4)
{
    int i = blockIdx.x * blockDim.x + threadIdx.x;
    if (i >= n4) return;
    float4 v = ((const float4*)in)[i];
    ((hf2*)w)[2 * i]     = __floats2half2_rn(v.x, v.y);
    ((hf2*)w)[2 * i + 1] = __floats2half2_rn(v.z, v.w);
}
__global__ void __launch_bounds__(256)
conv_w_qkv(const float* __restrict__ in, hf* __restrict__ w, int coff)
{
    int i = blockIdx.x * blockDim.x + threadIdx.x;
    int row = i >> 8, c4 = i & 255;
    float4 v = ((const float4*)in)[i];
    size_t o2 = ((size_t)row * 3072 + coff + c4 * 4) >> 1;
    ((hf2*)w)[o2]     = __floats2half2_rn(v.x, v.y);
    ((hf2*)w)[o2 + 1] = __floats2half2_rn(v.z, v.w);
}

// ==================== pipelined fp16-split GEMM ====================
#define EP_PROJ  1
#define EP_QKV   2
#define EP_RESID 3
#define EP_SILU  4

#define A_PITCH 144
#define B_PITCH 272
#define OFF_AH 0
#define OFF_AL 18432
#define OFF_B  36864
#define STAGE_B 54272
#define GEMM_SMEM (2 * STAGE_B)   // 108544

__device__ __forceinline__ void stage_load(
    uint32_t stb, const hf* Ah, const hf* Al, const hf* Bw,
    int k0, int bm, int bn, int K, int NN, int tid)
{
#pragma unroll
    for (int t = 0; t < 4; t++) {
        const int idx = t * 256 + tid;
        const int row = idx >> 3, seg = idx & 7;
        const size_t go = (size_t)(bm + row) * K + k0 + seg * 8;
        const uint32_t so = stb + (uint32_t)row * A_PITCH + seg * 16;
        cp16(so + OFF_AH, Ah + go);
        cp16(so + OFF_AL, Al + go);
    }
#pragma unroll
    for (int t = 0; t < 4; t++) {
        const int idx = t * 256 + tid;
        const int row = idx >> 4, seg = idx & 15;
        const size_t go = (size_t)(k0 + row) * NN + bn + seg * 8;
        const uint32_t so = stb + (uint32_t)row * B_PITCH + seg * 16;
        cp16(so + OFF_B, Bw + go);
    }
}

template <int MODE>
__global__ void __launch_bounds__(256, 2)
mma_gemm(int K, int NN,
         const hf* __restrict__ Ah, const hf* __restrict__ Al,
         const hf* __restrict__ Bw,
         const float* __restrict__ bias, const float* __restrict__ bias2,
         const float* __restrict__ bias3,
         float* __restrict__ out, hf* __restrict__ outHi, hf* __restrict__ outLo,
         const int* __restrict__ x_lengths)
{
    extern __shared__ char sm[];
    const uint32_t sb = smem_u32(sm);
    const int tid  = threadIdx.x;
    const int wid  = tid >> 5;
    const int lane = tid & 31;
    const int bn = blockIdx.x * 128;
    const int bm = blockIdx.y * 128;
    const int wm = wid & 1;
    const int wn = wid >> 1;

    float acc[4][4][4];
#pragma unroll
    for (int i = 0; i < 4; i++)
#pragma unroll
        for (int j = 0; j < 4; j++)
#pragma unroll
            for (int r = 0; r < 4; r++) acc[i][j][r] = 0.f;

    const int quad = lane >> 3;
    const int qr   = lane & 7;
    const uint32_t aOffH = OFF_AH + (uint32_t)(wm * 64 + (quad & 1) * 8 + qr) * A_PITCH + (quad >> 1) * 16;
    const uint32_t bOff  = OFF_B + (uint32_t)((quad & 1) * 8 + qr) * B_PITCH
                         + (uint32_t)(wn * 32 + (quad >> 1) * 8) * 2;

    const int nch = K >> 6;

    stage_load(sb, Ah, Al, Bw, 0, bm, bn, K, NN, tid);
    cp_commit();
    if (nch > 1) {
        stage_load(sb + STAGE_B, Ah, Al, Bw, 64, bm, bn, K, NN, tid);
        cp_commit();
    }

    for (int c = 0; c < nch; c++) {
        if (c < nch - 1) asm volatile("cp.async.wait_group 1;" ::: "memory");
        else             asm volatile("cp.async.wait_group 0;" ::: "memory");
        __syncthreads();

        const uint32_t stb = sb + (uint32_t)(c & 1) * STAGE_B;

#pragma unroll
        for (int ks = 0; ks < 4; ks++) {
            uint32_t aH[4][4], aL[4][4], bF[4][2];
#pragma unroll
            for (int mi = 0; mi < 4; mi++) {
                const uint32_t ad = stb + aOffH + (uint32_t)mi * (16 * A_PITCH) + ks * 32;
                ldsm4(aH[mi][0], aH[mi][1], aH[mi][2], aH[mi][3], ad);
                ldsm4(aL[mi][0], aL[mi][1], aL[mi][2], aL[mi][3], ad + (OFF_AL - OFF_AH));
            }
#pragma unroll
            for (int bp = 0; bp < 2; bp++) {
                const uint32_t ad = stb + bOff + (uint32_t)ks * (16 * B_PITCH) + bp * 32;
                uint32_t r0, r1, r2, r3;
                ldsm4t(r0, r1, r2, r3, ad);
                bF[2 * bp][0] = r0; bF[2 * bp][1] = r1;
                bF[2 * bp + 1][0] = r2; bF[2 * bp + 1][1] = r3;
            }
#pragma unroll
            for (int mi = 0; mi < 4; mi++)
#pragma unroll
                for (int ni = 0; ni < 4; ni++) {
                    mma16816(acc[mi][ni], aH[mi], bF[ni]);
                    mma16816(acc[mi][ni], aL[mi], bF[ni]);
                }
        }
        __syncthreads();

        if (c + 2 < nch) {
            stage_load(stb, Ah, Al, Bw, (c + 2) << 6, bm, bn, K, NN, tid);
            cp_commit();
        }
    }

    // ---- epilogue ----
    const int grp = lane >> 2;
    const int qc  = (lane & 3) * 2;
#pragma unroll
    for (int mi = 0; mi < 4; mi++) {
        const int m0 = bm + wm * 64 + mi * 16 + grp;
#pragma unroll
        for (int ni = 0; ni < 4; ni++) {
            const int n = bn + wn * 32 + ni * 8 + qc;
            float2 bsv;
            if (MODE == EP_QKV) {
                const int sel = n >> 10;
                const float* bp = (sel == 0) ? bias : (sel == 1) ? bias2 : bias3;
                bsv = *(const float2*)(bp + (n & 1023));
            } else {
                bsv = *(const float2*)(bias + n);
            }
            float2 v01, v23;
            v01.x = acc[mi][ni][0] + bsv.x;
            v01.y = acc[mi][ni][1] + bsv.y;
            v23.x = acc[mi][ni][2] + bsv.x;
            v23.y = acc[mi][ni][3] + bsv.y;
#pragma unroll
            for (int half = 0; half < 2; half++) {
                const int m = m0 + half * 8;
                float2 v = half ? v23 : v01;
                if (MODE == EP_PROJ) {
                    const int b = m >> 10, s = m & 1023;
                    const int len = x_lengths[b] >> 2;
                    if (s >= len) { v.x = 0.f; v.y = 0.f; }
                    *(float2*)(out + (size_t)m * NN + n) = v;
                } else if (MODE == EP_QKV) {
                    const int sel = n >> 10;
                    const int nl = n & 1023;
                    const int b = m >> 10, s = m & 1023;
                    const int hh = nl >> 7, dh = nl & 127;
                    float* dst = (sel == 0) ? out : (sel == 1) ? (float*)outHi : (float*)outLo;
                    *(float2*)(dst + ((size_t)((b << 3) | hh) * 1024 + s) * 128 + dh) = v;
                } else if (MODE == EP_RESID) {
                    float2 o = *(float2*)(out + (size_t)m * NN + n);
                    o.x += v.x; o.y += v.y;
                    *(float2*)(out + (size_t)m * NN + n) = o;
                } else { // EP_SILU -> fp16 hi/lo
                    v.x = v.x / (1.f + __expf(-v.x));
                    v.y = v.y / (1.f + __expf(-v.y));
                    hf2 h, l;
                    split2h(v.x, v.y, h, l);
                    const size_t o2 = ((size_t)m * NN + n) >> 1;
                    ((hf2*)outHi)[o2] = h;
                    ((hf2*)outLo)[o2] = l;
                }
            }
        }
    }
}

// -------------------- LayerNorm --------------------
template <bool HFOUT>
__global__ void __launch_bounds__(256)
layernorm_kernel(const float* __restrict__ in, float* __restrict__ out,
                 hf* __restrict__ outHi, hf* __restrict__ outLo,
                 const float* __restrict__ scale, const float* __restrict__ bias)
{
    __shared__ float sh1[8];
    __shared__ float sh2[8];
    const int row = blockIdx.x;
    const int t = threadIdx.x;
    const int lane = t & 31, w = t >> 5;
    const float* xr = in + (size_t)row * 1024;

    float vals[4];
    float s = 0.f;
#pragma unroll
    for (int r = 0; r < 4; r++) { vals[r] = xr[t + 256 * r]; s += vals[r]; }
#pragma unroll
    for (int o = 16; o; o >>= 1) s += __shfl_xor_sync(0xffffffffu, s, o);
    if (lane == 0) sh1[w] = s;
    __syncthreads();
    float tot = (t < 8) ? sh1[t] : 0.f;
    if (w == 0) {
#pragma unroll
        for (int o = 16; o; o >>= 1) tot += __shfl_xor_sync(0xffffffffu, tot, o);
        if (lane == 0) sh1[0] = tot;
    }
    __syncthreads();
    const float mean = sh1[0] * (1.f / 1024.f);

    float vs = 0.f;
#pragma unroll
    for (int r = 0; r < 4; r++) { float d = vals[r] - mean; vs += d * d; }
#pragma unroll
    for (int o = 16; o; o >>= 1) vs += __shfl_xor_sync(0xffffffffu, vs, o);
    if (lane == 0) sh2[w] = vs;
    __syncthreads();
    float vtot = (t < 8) ? sh2[t] : 0.f;
    if (w == 0) {
#pragma unroll
        for (int o = 16; o; o >>= 1) vtot += __shfl_xor_sync(0xffffffffu, vtot, o);
        if (lane == 0) sh2[0] = vtot;
    }
    __syncthreads();
    const float var = sh2[0] * (1.f / 1024.f);
    const float inv = rsqrtf(var + 1e-5f);

#pragma unroll
    for (int r = 0; r < 4; r++) {
        int d = t + 256 * r;
        float v = (vals[r] - mean) * inv * scale[d] + bias[d];
        if (HFOUT) {
            hf h = __float2half_rn(v);
            outHi[(size_t)row * 1024 + d] = h;
            outLo[(size_t)row * 1024 + d] = __float2half_rn(v - __half2float(h));
        } else {
            out[(size_t)row * 1024 + d] = v;
        }
    }
}

// -------------------- RoPE table + apply --------------------
__global__ void __launch_bounds__(256)
rope_table_kernel(float* __restrict__ rc, float* __restrict__ rs)
{
    int idx = blockIdx.x * blockDim.x + threadIdx.x;   // 0..65535
    int p = idx & 63;
    int s = idx >> 6;
    float inv_freq = expf(-(float)p * (9.210340371976184f / 64.f));
    float ang = (float)s * inv_freq;
    float sn, cs;
    sincosf(ang, &sn, &cs);
    rc[idx] = cs;
    rs[idx] = sn;
}

__global__ void __launch_bounds__(256)
rope_kernel(float* __restrict__ q, float* __restrict__ k,
            const float* __restrict__ rc, const float* __restrict__ rs)
{
    const int total = B_ * H_ * S_ * 64;
    int idx = blockIdx.x * blockDim.x + threadIdx.x;
    if (idx >= 2 * total) return;
    float* ptr = (idx < total) ? q : k;
    int id = (idx < total) ? idx : idx - total;
    int p  = id & 63;
    int s  = (id >> 6) & 1023;
    int bh = id >> 16;
    int tix = (s << 6) | p;
    float cs = rc[tix], sn = rs[tix];
    int base = (bh * 1024 + s) * 128 + p;
    float x1 = ptr[base];
    float x2 = ptr[base + 64];
    ptr[base]      = x1 * cs - x2 * sn;
    ptr[base + 64] = x1 * sn + x2 * cs;
}

// -------------------- V mean (parallel) --------------------
__global__ void __launch_bounds__(1024)
vmean_kernel(const float* __restrict__ v, float* __restrict__ vmean)
{
    __shared__ float partial[8][128];
    const int bh = blockIdx.x;
    const int d  = threadIdx.x & 127;
    const int sl = threadIdx.x >> 7;      // 0..7
    const float* base = v + (size_t)bh * S_ * DH_ + (size_t)sl * 128 * DH_ + d;
    float s = 0.f;
#pragma unroll 4
    for (int j = 0; j < 128; j++) s += base[j * DH_];
    partial[sl][d] = s;
    __syncthreads();
    if (sl == 0) {
        float t = 0.f;
#pragma unroll
        for (int r = 0; r < 8; r++) t += partial[r][d];
        vmean[bh * DH_ + d] = t * (1.f / (float)S_);
    }
}

// -------------------- windowed attention v2 (two-phase, float4) -------------
__global__ void __launch_bounds__(128)
attn_kernel(const float* __restrict__ q, const float* __restrict__ k,
            const float* __restrict__ v, const float* __restrict__ vmean,
            hf* __restrict__ ctxHi, hf* __restrict__ ctxLo,
            const int* __restrict__ x_lengths)
{
    const int wid  = blockIdx.x * 4 + (threadIdx.x >> 5);
    const int lane = threadIdx.x & 31;
    const int i  = wid & 1023;
    const int hh = (wid >> 10) & 7;
    const int b  = wid >> 13;

    const int len = x_lengths[b] >> 2;
    int jlo = i - (WIN_ - 1); if (jlo < 0) jlo = 0;
    int jhi = i + LFW_;       if (jhi > S_ - 1) jhi = S_ - 1;
    int jh  = (len - 1 < jhi) ? (len - 1) : jhi;

    const size_t obase = ((size_t)(b * 1024 + i)) * 1024 + hh * 128 + lane * 4;

    if (jh < jlo) {
        const float4 vm = *(const float4*)(vmean + (b * 8 + hh) * 128 + lane * 4);
        hf2 h0, l0, h1, l1;
        split2h(vm.x, vm.y, h0, l0);
        split2h(vm.z, vm.w, h1, l1);
        *(hf2*)(ctxHi + obase)     = h0; *(hf2*)(ctxHi + obase + 2) = h1;
        *(hf2*)(ctxLo + obase)     = l0; *(hf2*)(ctxLo + obase + 2) = l1;
        return;
    }

    const size_t head = ((size_t)(b * 8 + hh)) * 1024;
    const float4 qv = *(const float4*)(q + (head + i) * 128 + lane * 4);
    const float scale = 0.08838834764831845f;   // 1/sqrt(128)

    // ---- phase 1: scores, distributed 4 per lane ----
    float sc[4] = {-1e30f, -1e30f, -1e30f, -1e30f};
#pragma unroll
    for (int slot = 0; slot < 4; slot++) {
        const int jbase = jlo + slot * 32;
        if (jbase > jh) break;
        for (int t = 0; t < 32; t++) {
            const int j = jbase + t;
            if (j > jh) break;
            float4 kv = *(const float4*)(k + (head + j) * 128 + lane * 4);
            float s = qv.x * kv.x + qv.y * kv.y + qv.z * kv.z + qv.w * kv.w;
#pragma unroll
            for (int o = 16; o; o >>= 1) s += __shfl_xor_sync(0xffffffffu, s, o);
            if (t == lane) sc[slot] = s * scale;
        }
    }

    // ---- warp max ----
    float m = fmaxf(fmaxf(sc[0], sc[1]), fmaxf(sc[2], sc[3]));
#pragma unroll
    for (int o = 16; o; o >>= 1) m = fmaxf(m, __shfl_xor_sync(0xffffffffu, m, o));

    // ---- exp (4 MUFU per warp) + sum ----
    float p0 = __expf(sc[0] - m);
    float p1 = __expf(sc[1] - m);
    float p2 = __expf(sc[2] - m);
    float p3 = __expf(sc[3] - m);
    float l = p0 + p1 + p2 + p3;
#pragma unroll
    for (int o = 16; o; o >>= 1) l += __shfl_xor_sync(0xffffffffu, l, o);

    // ---- phase 2: P @ V ----
    float4 acc = {0.f, 0.f, 0.f, 0.f};
#pragma unroll
    for (int slot = 0; slot < 4; slot++) {
        const int jbase = jlo + slot * 32;
        if (jbase > jh) break;
        const float ps = (slot == 0) ? p0 : (slot == 1) ? p1 : (slot == 2) ? p2 : p3;
        for (int t = 0; t < 32; t++) {
            const int j = jbase + t;
            if (j > jh) break;
            const float pj = __shfl_sync(0xffffffffu, ps, t);
            float4 vv = *(const float4*)(v + (head + j) * 128 + lane * 4);
            acc.x += pj * vv.x;
            acc.y += pj * vv.y;
            acc.z += pj * vv.z;
            acc.w += pj * vv.w;
        }
    }

    const float invl = 1.f / l;
    hf2 h0, l0h, h1, l1h;
    split2h(acc.x * invl, acc.y * invl, h0, l0h);
    split2h(acc.z * invl, acc.w * invl, h1, l1h);
    *(hf2*)(ctxHi + obase)     = h0; *(hf2*)(ctxHi + obase + 2) = h1;
    *(hf2*)(ctxLo + obase)     = l0h; *(hf2*)(ctxLo + obase + 2) = l1h;
}

// -------------------- launch --------------------
extern "C" void kernel_launch(void* const* d_in, const int* in_sizes, int n_in,
                              void* d_out, int out_size)
{
    const float* x     = (const float*)d_in[0];
    const int*   xlen  = (const int*)  d_in[1];
    const float* Wp    = (const float*)d_in[2];
    const float* bp    = (const float*)d_in[3];
    const float* ln1_s = (const float*)d_in[4];
    const float* ln1_b = (const float*)d_in[5];
    const float* Wq    = (const float*)d_in[6];
    const float* bq    = (const float*)d_in[7];
    const float* Wk    = (const float*)d_in[8];
    const float* bk    = (const float*)d_in[9];
    const float* Wv    = (const float*)d_in[10];
    const float* bv    = (const float*)d_in[11];
    const float* Wo    = (const float*)d_in[12];
    const float* bo    = (const float*)d_in[13];
    const float* ln2_s = (const float*)d_in[14];
    const float* ln2_b = (const float*)d_in[15];
    const float* W1    = (const float*)d_in[16];
    const float* b1    = (const float*)d_in[17];
    const float* W2    = (const float*)d_in[18];
    const float* b2    = (const float*)d_in[19];
    const float* lnf_s = (const float*)d_in[20];
    const float* lnf_b = (const float*)d_in[21];
    float* out = (float*)d_out;

    float *h, *q, *k, *v, *vmean, *rc, *rs;
    hf *xhi, *xlo, *yhi, *ylo, *chi, *clo, *fhi, *flo, *w;
    cudaGetSymbolAddress((void**)&h,    g_h);
    cudaGetSymbolAddress((void**)&q,    g_q);
    cudaGetSymbolAddress((void**)&k,    g_k);
    cudaGetSymbolAddress((void**)&v,    g_v);
    cudaGetSymbolAddress((void**)&vmean,g_vmean);
    cudaGetSymbolAddress((void**)&rc,   g_rcos);
    cudaGetSymbolAddress((void**)&rs,   g_rsin);
    cudaGetSymbolAddress((void**)&xhi,  g_xhi);
    cudaGetSymbolAddress((void**)&xlo,  g_xlo);
    cudaGetSymbolAddress((void**)&yhi,  g_yhi);
    cudaGetSymbolAddress((void**)&ylo,  g_ylo);
    cudaGetSymbolAddress((void**)&chi,  g_chi);
    cudaGetSymbolAddress((void**)&clo,  g_clo);
    cudaGetSymbolAddress((void**)&fhi,  g_fhi);
    cudaGetSymbolAddress((void**)&flo,  g_flo);
    cudaGetSymbolAddress((void**)&w,    g_w);

    cudaFuncSetAttribute(mma_gemm<EP_PROJ>,  cudaFuncAttributeMaxDynamicSharedMemorySize, GEMM_SMEM);
    cudaFuncSetAttribute(mma_gemm<EP_QKV>,   cudaFuncAttributeMaxDynamicSharedMemorySize, GEMM_SMEM);
    cudaFuncSetAttribute(mma_gemm<EP_RESID>, cudaFuncAttributeMaxDynamicSharedMemorySize, GEMM_SMEM);
    cudaFuncSetAttribute(mma_gemm<EP_SILU>,  cudaFuncAttributeMaxDynamicSharedMemorySize, GEMM_SMEM);

    const dim3 blk(256);

    // ---- converters + rope table ----
    rope_table_kernel<<<256, blk>>>(rc, rs);
    conv_split<<<(NTOK * 2048 / 4 + 255) / 256, blk>>>(x, xhi, xlo, NTOK * 2048 / 4);
    conv_w<<<(2048 * 1024 / 4 + 255) / 256, blk>>>(Wp, w + WP_OFF, 2048 * 1024 / 4);
    conv_w_qkv<<<4096, blk>>>(Wq, w + QKV_OFF, 0);
    conv_w_qkv<<<4096, blk>>>(Wk, w + QKV_OFF, 1024);
    conv_w_qkv<<<4096, blk>>>(Wv, w + QKV_OFF, 2048);
    conv_w<<<(4 * 1048576 / 4 + 255) / 256, blk>>>(Wo, w + WO_OFF, 4 * 1048576 / 4);
    conv_w<<<(4 * 4194304 / 4 + 255) / 256, blk>>>(W1, w + W1_OFF, 4 * 4194304 / 4);
    conv_w<<<(4 * 4194304 / 4 + 255) / 256, blk>>>(W2, w + W2_OFF, 4 * 4194304 / 4);

    // projector
    mma_gemm<EP_PROJ><<<dim3(8, 32), blk, GEMM_SMEM>>>(
        2048, 1024, xhi, xlo, w + WP_OFF,
        bp, nullptr, nullptr, h, nullptr, nullptr, xlen);

    for (int l = 0; l < L_; l++) {
        const size_t oD  = (size_t)l * D_;
        const size_t oF  = (size_t)l * F_;
        const uint32_t oQKV = QKV_OFF + (uint32_t)l * 3145728u;
        const uint32_t oWO  = WO_OFF  + (uint32_t)l * 1048576u;
        const uint32_t oW1  = W1_OFF  + (uint32_t)l * 4194304u;
        const uint32_t oW2  = W2_OFF  + (uint32_t)l * 4194304u;

        layernorm_kernel<true><<<NTOK, blk>>>(h, nullptr, yhi, ylo, ln1_s + oD, ln1_b + oD);

        mma_gemm<EP_QKV><<<dim3(24, 32), blk, GEMM_SMEM>>>(
            1024, 3072, yhi, ylo, w + oQKV,
            bq + oD, bk + oD, bv + oD, q, (hf*)k, (hf*)v, nullptr);

        rope_kernel<<<(2 * B_ * H_ * S_ * 64) / 256, blk>>>(q, k, rc, rs);
        vmean_kernel<<<B_ * H_, 1024>>>(v, vmean);
        attn_kernel<<<(B_ * H_ * S_) / 4, 128>>>(q, k, v, vmean, chi, clo, xlen);

        mma_gemm<EP_RESID><<<dim3(8, 32), blk, GEMM_SMEM>>>(
            1024, 1024, chi, clo, w + oWO,
            bo + oD, nullptr, nullptr, h, nullptr, nullptr, nullptr);

        layernorm_kernel<true><<<NTOK, blk>>>(h, nullptr, yhi, ylo, ln2_s + oD, ln2_b + oD);

        mma_gemm<EP_SILU><<<dim3(32, 32), blk, GEMM_SMEM>>>(
            1024, 4096, yhi, ylo, w + oW1,
            b1 + oF, nullptr, nullptr, nullptr, fhi, flo, nullptr);

        mma_gemm<EP_RESID><<<dim3(8, 32), blk, GEMM_SMEM>>>(
            4096, 1024, fhi, flo, w + oW2,
            b2 + oD, nullptr, nullptr, h, nullptr, nullptr, nullptr);
    }

    layernorm_kernel<false><<<NTOK, blk>>>(h, out, nullptr, nullptr, lnf_s, lnf_b);
}

// round 8
// speedup vs baseline: 4.6938x; 1.2596x over previous
#include <cuda_runtime.h>
#include <cuda_fp16.h>
#include <math.h>
#include <stdint.h>

// Problem constants
#define B_   4
#define S_   1024
#define D_   1024
#define F_   4096
#define H_   8
#define DH_  128
#define L_   4
#define NTOK (B_ * S_)          // 4096
#define WIN_ 100
#define LFW_ 20

typedef __half  hf;
typedef __half2 hf2;

// -------------------- scratch --------------------
__device__ float g_h [NTOK * D_];
__device__ float g_q [NTOK * D_];
__device__ float g_k [NTOK * D_];
__device__ float g_v [NTOK * D_];
__device__ float g_vmean[B_ * H_ * DH_];
__device__ float g_rcos[S_ * 64];
__device__ float g_rsin[S_ * 64];

// fp16 hi/lo activation buffers
__device__ hf g_xhi[NTOK * 2048], g_xlo[NTOK * 2048];
__device__ hf g_yhi[NTOK * D_],   g_ylo[NTOK * D_];
__device__ hf g_chi[NTOK * D_],   g_clo[NTOK * D_];
__device__ hf g_fhi[NTOK * F_];

// converted weights (single fp16), offsets in elements
#define WP_OFF   0u
#define QKV_OFF  2097152u
#define WO_OFF   (QKV_OFF + 4u * 3145728u)
#define W1_OFF   (WO_OFF + 4u * 1048576u)
#define W2_OFF   (W1_OFF + 4u * 4194304u)
#define WTOT     (W2_OFF + 4u * 4194304u)
__device__ hf g_w[WTOT];

// ==================== helpers ====================
__device__ __forceinline__ uint32_t smem_u32(const void* p) {
    uint32_t a;
    asm("{ .reg .u64 t; cvta.to.shared.u64 t, %1; cvt.u32.u64 %0, t; }" : "=r"(a) : "l"(p));
    return a;
}
__device__ __forceinline__ void cp16(uint32_t saddr, const void* gaddr) {
    asm volatile("cp.async.cg.shared.global [%0], [%1], 16;" :: "r"(saddr), "l"(gaddr));
}
__device__ __forceinline__ void cp_commit() {
    asm volatile("cp.async.commit_group;" ::: "memory");
}
__device__ __forceinline__ void ldsm4(uint32_t& r0, uint32_t& r1, uint32_t& r2, uint32_t& r3,
                                      uint32_t addr) {
    asm volatile("ldmatrix.sync.aligned.m8n8.x4.shared.b16 {%0,%1,%2,%3}, [%4];"
                 : "=r"(r0), "=r"(r1), "=r"(r2), "=r"(r3) : "r"(addr));
}
__device__ __forceinline__ void ldsm4t(uint32_t& r0, uint32_t& r1, uint32_t& r2, uint32_t& r3,
                                       uint32_t addr) {
    asm volatile("ldmatrix.sync.aligned.m8n8.x4.trans.shared.b16 {%0,%1,%2,%3}, [%4];"
                 : "=r"(r0), "=r"(r1), "=r"(r2), "=r"(r3) : "r"(addr));
}
__device__ __forceinline__ void mma16816(float* d, const uint32_t* a, const uint32_t* b) {
    asm volatile(
        "mma.sync.aligned.m16n8k16.row.col.f32.f16.f16.f32 "
        "{%0,%1,%2,%3}, {%4,%5,%6,%7}, {%8,%9}, {%0,%1,%2,%3};"
        : "+f"(d[0]), "+f"(d[1]), "+f"(d[2]), "+f"(d[3])
        : "r"(a[0]), "r"(a[1]), "r"(a[2]), "r"(a[3]), "r"(b[0]), "r"(b[1]));
}
__device__ __forceinline__ void split2h(float x, float y, hf2& h, hf2& l) {
    h = __floats2half2_rn(x, y);
    float2 hfv = __half22float2(h);
    l = __floats2half2_rn(x - hfv.x, y - hfv.y);
}

// ==================== converters ====================
__global__ void __launch_bounds__(256)
conv_split(const float* __restrict__ in, hf* __restrict__ hi, hf* __restrict__ lo, int n4)
{
    int i = blockIdx.x * blockDim.x + threadIdx.x;
    if (i >= n4) return;
    float4 v = ((const float4*)in)[i];
    hf2 h0, l0, h1, l1;
    split2h(v.x, v.y, h0, l0);
    split2h(v.z, v.w, h1, l1);
    ((hf2*)hi)[2 * i] = h0; ((hf2*)hi)[2 * i + 1] = h1;
    ((hf2*)lo)[2 * i] = l0; ((hf2*)lo)[2 * i + 1] = l1;
}
__global__ void __launch_bounds__(256)
conv_w(const float* __restrict__ in, hf* __restrict__ w, int n4)
{
    int i = blockIdx.x * blockDim.x + threadIdx.x;
    if (i >= n4) return;
    float4 v = ((const float4*)in)[i];
    ((hf2*)w)[2 * i]     = __floats2half2_rn(v.x, v.y);
    ((hf2*)w)[2 * i + 1] = __floats2half2_rn(v.z, v.w);
}
__global__ void __launch_bounds__(256)
conv_w_qkv(const float* __restrict__ in, hf* __restrict__ w, int coff)
{
    int i = blockIdx.x * blockDim.x + threadIdx.x;
    int row = i >> 8, c4 = i & 255;
    float4 v = ((const float4*)in)[i];
    size_t o2 = ((size_t)row * 3072 + coff + c4 * 4) >> 1;
    ((hf2*)w)[o2]     = __floats2half2_rn(v.x, v.y);
    ((hf2*)w)[o2 + 1] = __floats2half2_rn(v.z, v.w);
}

// ==================== pipelined fp16(-split) GEMM ====================
#define EP_PROJ  1
#define EP_QKV   2
#define EP_RESID 3
#define EP_SILU  4

#define A_PITCH 144
#define B_PITCH 272
#define OFF_AH 0
#define OFF_AL 18432
#define OFF_B  36864
#define STAGE_B 54272
#define GEMM_SMEM (2 * STAGE_B)   // 108544

template <int NT>
__device__ __forceinline__ void stage_load(
    uint32_t stb, const hf* Ah, const hf* Al, const hf* Bw,
    int k0, int bm, int bn, int K, int NN, int tid)
{
#pragma unroll
    for (int t = 0; t < 4; t++) {
        const int idx = t * 256 + tid;
        const int row = idx >> 3, seg = idx & 7;
        const size_t go = (size_t)(bm + row) * K + k0 + seg * 8;
        const uint32_t so = stb + (uint32_t)row * A_PITCH + seg * 16;
        cp16(so + OFF_AH, Ah + go);
        if (NT == 2) cp16(so + OFF_AL, Al + go);
    }
#pragma unroll
    for (int t = 0; t < 4; t++) {
        const int idx = t * 256 + tid;
        const int row = idx >> 4, seg = idx & 15;
        const size_t go = (size_t)(k0 + row) * NN + bn + seg * 8;
        const uint32_t so = stb + (uint32_t)row * B_PITCH + seg * 16;
        cp16(so + OFF_B, Bw + go);
    }
}

template <int MODE, int NT>
__global__ void __launch_bounds__(256, 2)
mma_gemm(int K, int NN,
         const hf* __restrict__ Ah, const hf* __restrict__ Al,
         const hf* __restrict__ Bw,
         const float* __restrict__ bias, const float* __restrict__ bias2,
         const float* __restrict__ bias3,
         float* __restrict__ out, hf* __restrict__ outHi, hf* __restrict__ outLo,
         const int* __restrict__ x_lengths)
{
    extern __shared__ char sm[];
    const uint32_t sb = smem_u32(sm);
    const int tid  = threadIdx.x;
    const int wid  = tid >> 5;
    const int lane = tid & 31;
    const int bn = blockIdx.x * 128;
    const int bm = blockIdx.y * 128;
    const int wm = wid & 1;
    const int wn = wid >> 1;

    float acc[4][4][4];
#pragma unroll
    for (int i = 0; i < 4; i++)
#pragma unroll
        for (int j = 0; j < 4; j++)
#pragma unroll
            for (int r = 0; r < 4; r++) acc[i][j][r] = 0.f;

    const int quad = lane >> 3;
    const int qr   = lane & 7;
    const uint32_t aOffH = OFF_AH + (uint32_t)(wm * 64 + (quad & 1) * 8 + qr) * A_PITCH + (quad >> 1) * 16;
    const uint32_t bOff  = OFF_B + (uint32_t)((quad & 1) * 8 + qr) * B_PITCH
                         + (uint32_t)(wn * 32 + (quad >> 1) * 8) * 2;

    const int nch = K >> 6;

    stage_load<NT>(sb, Ah, Al, Bw, 0, bm, bn, K, NN, tid);
    cp_commit();
    if (nch > 1) {
        stage_load<NT>(sb + STAGE_B, Ah, Al, Bw, 64, bm, bn, K, NN, tid);
        cp_commit();
    }

    for (int c = 0; c < nch; c++) {
        if (c < nch - 1) asm volatile("cp.async.wait_group 1;" ::: "memory");
        else             asm volatile("cp.async.wait_group 0;" ::: "memory");
        __syncthreads();

        const uint32_t stb = sb + (uint32_t)(c & 1) * STAGE_B;

#pragma unroll
        for (int ks = 0; ks < 4; ks++) {
            uint32_t aH[4][4], aL[4][4], bF[4][2];
#pragma unroll
            for (int mi = 0; mi < 4; mi++) {
                const uint32_t ad = stb + aOffH + (uint32_t)mi * (16 * A_PITCH) + ks * 32;
                ldsm4(aH[mi][0], aH[mi][1], aH[mi][2], aH[mi][3], ad);
                if (NT == 2)
                    ldsm4(aL[mi][0], aL[mi][1], aL[mi][2], aL[mi][3], ad + (OFF_AL - OFF_AH));
            }
#pragma unroll
            for (int bp = 0; bp < 2; bp++) {
                const uint32_t ad = stb + bOff + (uint32_t)ks * (16 * B_PITCH) + bp * 32;
                uint32_t r0, r1, r2, r3;
                ldsm4t(r0, r1, r2, r3, ad);
                bF[2 * bp][0] = r0; bF[2 * bp][1] = r1;
                bF[2 * bp + 1][0] = r2; bF[2 * bp + 1][1] = r3;
            }
#pragma unroll
            for (int mi = 0; mi < 4; mi++)
#pragma unroll
                for (int ni = 0; ni < 4; ni++) {
                    mma16816(acc[mi][ni], aH[mi], bF[ni]);
                    if (NT == 2) mma16816(acc[mi][ni], aL[mi], bF[ni]);
                }
        }
        __syncthreads();

        if (c + 2 < nch) {
            stage_load<NT>(stb, Ah, Al, Bw, (c + 2) << 6, bm, bn, K, NN, tid);
            cp_commit();
        }
    }

    // ---- epilogue ----
    const int grp = lane >> 2;
    const int qc  = (lane & 3) * 2;
#pragma unroll
    for (int mi = 0; mi < 4; mi++) {
        const int m0 = bm + wm * 64 + mi * 16 + grp;
#pragma unroll
        for (int ni = 0; ni < 4; ni++) {
            const int n = bn + wn * 32 + ni * 8 + qc;
            float2 bsv;
            if (MODE == EP_QKV) {
                const int sel = n >> 10;
                const float* bp = (sel == 0) ? bias : (sel == 1) ? bias2 : bias3;
                bsv = *(const float2*)(bp + (n & 1023));
            } else {
                bsv = *(const float2*)(bias + n);
            }
            float2 v01, v23;
            v01.x = acc[mi][ni][0] + bsv.x;
            v01.y = acc[mi][ni][1] + bsv.y;
            v23.x = acc[mi][ni][2] + bsv.x;
            v23.y = acc[mi][ni][3] + bsv.y;
#pragma unroll
            for (int half = 0; half < 2; half++) {
                const int m = m0 + half * 8;
                float2 v = half ? v23 : v01;
                if (MODE == EP_PROJ) {
                    const int b = m >> 10, s = m & 1023;
                    const int len = x_lengths[b] >> 2;
                    if (s >= len) { v.x = 0.f; v.y = 0.f; }
                    *(float2*)(out + (size_t)m * NN + n) = v;
                } else if (MODE == EP_QKV) {
                    const int sel = n >> 10;
                    const int nl = n & 1023;
                    const int b = m >> 10, s = m & 1023;
                    const int hh = nl >> 7, dh = nl & 127;
                    float* dst = (sel == 0) ? out : (sel == 1) ? (float*)outHi : (float*)outLo;
                    *(float2*)(dst + ((size_t)((b << 3) | hh) * 1024 + s) * 128 + dh) = v;
                } else if (MODE == EP_RESID) {
                    float2 o = *(float2*)(out + (size_t)m * NN + n);
                    o.x += v.x; o.y += v.y;
                    *(float2*)(out + (size_t)m * NN + n) = o;
                } else { // EP_SILU -> single fp16
                    v.x = v.x / (1.f + __expf(-v.x));
                    v.y = v.y / (1.f + __expf(-v.y));
                    const size_t o2 = ((size_t)m * NN + n) >> 1;
                    ((hf2*)outHi)[o2] = __floats2half2_rn(v.x, v.y);
                }
            }
        }
    }
}

// -------------------- LayerNorm --------------------
template <bool HFOUT>
__global__ void __launch_bounds__(256)
layernorm_kernel(const float* __restrict__ in, float* __restrict__ out,
                 hf* __restrict__ outHi, hf* __restrict__ outLo,
                 const float* __restrict__ scale, const float* __restrict__ bias)
{
    __shared__ float sh1[8];
    __shared__ float sh2[8];
    const int row = blockIdx.x;
    const int t = threadIdx.x;
    const int lane = t & 31, w = t >> 5;
    const float* xr = in + (size_t)row * 1024;

    float vals[4];
    float s = 0.f;
#pragma unroll
    for (int r = 0; r < 4; r++) { vals[r] = xr[t + 256 * r]; s += vals[r]; }
#pragma unroll
    for (int o = 16; o; o >>= 1) s += __shfl_xor_sync(0xffffffffu, s, o);
    if (lane == 0) sh1[w] = s;
    __syncthreads();
    float tot = (t < 8) ? sh1[t] : 0.f;
    if (w == 0) {
#pragma unroll
        for (int o = 16; o; o >>= 1) tot += __shfl_xor_sync(0xffffffffu, tot, o);
        if (lane == 0) sh1[0] = tot;
    }
    __syncthreads();
    const float mean = sh1[0] * (1.f / 1024.f);

    float vs = 0.f;
#pragma unroll
    for (int r = 0; r < 4; r++) { float d = vals[r] - mean; vs += d * d; }
#pragma unroll
    for (int o = 16; o; o >>= 1) vs += __shfl_xor_sync(0xffffffffu, vs, o);
    if (lane == 0) sh2[w] = vs;
    __syncthreads();
    float vtot = (t < 8) ? sh2[t] : 0.f;
    if (w == 0) {
#pragma unroll
        for (int o = 16; o; o >>= 1) vtot += __shfl_xor_sync(0xffffffffu, vtot, o);
        if (lane == 0) sh2[0] = vtot;
    }
    __syncthreads();
    const float var = sh2[0] * (1.f / 1024.f);
    const float inv = rsqrtf(var + 1e-5f);

#pragma unroll
    for (int r = 0; r < 4; r++) {
        int d = t + 256 * r;
        float v = (vals[r] - mean) * inv * scale[d] + bias[d];
        if (HFOUT) {
            hf h = __float2half_rn(v);
            outHi[(size_t)row * 1024 + d] = h;
            outLo[(size_t)row * 1024 + d] = __float2half_rn(v - __half2float(h));
        } else {
            out[(size_t)row * 1024 + d] = v;
        }
    }
}

// -------------------- RoPE table + apply --------------------
__global__ void __launch_bounds__(256)
rope_table_kernel(float* __restrict__ rc, float* __restrict__ rs)
{
    int idx = blockIdx.x * blockDim.x + threadIdx.x;
    int p = idx & 63;
    int s = idx >> 6;
    float inv_freq = expf(-(float)p * (9.210340371976184f / 64.f));
    float ang = (float)s * inv_freq;
    float sn, cs;
    sincosf(ang, &sn, &cs);
    rc[idx] = cs;
    rs[idx] = sn;
}

__global__ void __launch_bounds__(256)
rope_kernel(float* __restrict__ q, float* __restrict__ k,
            const float* __restrict__ rc, const float* __restrict__ rs)
{
    const int total = B_ * H_ * S_ * 64;
    int idx = blockIdx.x * blockDim.x + threadIdx.x;
    if (idx >= 2 * total) return;
    float* ptr = (idx < total) ? q : k;
    int id = (idx < total) ? idx : idx - total;
    int p  = id & 63;
    int s  = (id >> 6) & 1023;
    int bh = id >> 16;
    int tix = (s << 6) | p;
    float cs = rc[tix], sn = rs[tix];
    int base = (bh * 1024 + s) * 128 + p;
    float x1 = ptr[base];
    float x2 = ptr[base + 64];
    ptr[base]      = x1 * cs - x2 * sn;
    ptr[base + 64] = x1 * sn + x2 * cs;
}

// -------------------- V mean --------------------
__global__ void __launch_bounds__(1024)
vmean_kernel(const float* __restrict__ v, float* __restrict__ vmean)
{
    __shared__ float partial[8][128];
    const int bh = blockIdx.x;
    const int d  = threadIdx.x & 127;
    const int sl = threadIdx.x >> 7;
    const float* base = v + (size_t)bh * S_ * DH_ + (size_t)sl * 128 * DH_ + d;
    float s = 0.f;
#pragma unroll 4
    for (int j = 0; j < 128; j++) s += base[j * DH_];
    partial[sl][d] = s;
    __syncthreads();
    if (sl == 0) {
        float t = 0.f;
#pragma unroll
        for (int r = 0; r < 8; r++) t += partial[r][d];
        vmean[bh * DH_ + d] = t * (1.f / (float)S_);
    }
}

// -------------------- windowed attention --------------------
__global__ void __launch_bounds__(128)
attn_kernel(const float* __restrict__ q, const float* __restrict__ k,
            const float* __restrict__ v, const float* __restrict__ vmean,
            hf* __restrict__ ctxHi, hf* __restrict__ ctxLo,
            const int* __restrict__ x_lengths)
{
    const int wid  = blockIdx.x * 4 + (threadIdx.x >> 5);
    const int lane = threadIdx.x & 31;
    const int i  = wid & 1023;
    const int hh = (wid >> 10) & 7;
    const int b  = wid >> 13;

    const int len = x_lengths[b] >> 2;
    int jlo = i - (WIN_ - 1); if (jlo < 0) jlo = 0;
    int jhi = i + LFW_;       if (jhi > S_ - 1) jhi = S_ - 1;
    int jh  = (len - 1 < jhi) ? (len - 1) : jhi;

    const size_t obase = ((size_t)(b * 1024 + i)) * 1024 + hh * 128 + lane * 4;

    if (jh < jlo) {
        const float4 vm = *(const float4*)(vmean + (b * 8 + hh) * 128 + lane * 4);
        hf2 h0, l0, h1, l1;
        split2h(vm.x, vm.y, h0, l0);
        split2h(vm.z, vm.w, h1, l1);
        *(hf2*)(ctxHi + obase)     = h0; *(hf2*)(ctxHi + obase + 2) = h1;
        *(hf2*)(ctxLo + obase)     = l0; *(hf2*)(ctxLo + obase + 2) = l1;
        return;
    }

    const size_t head = ((size_t)(b * 8 + hh)) * 1024;
    const float4 qv = *(const float4*)(q + (head + i) * 128 + lane * 4);
    const float scale = 0.08838834764831845f;

    float sc[4] = {-1e30f, -1e30f, -1e30f, -1e30f};
#pragma unroll
    for (int slot = 0; slot < 4; slot++) {
        const int jbase = jlo + slot * 32;
        if (jbase > jh) break;
        for (int t = 0; t < 32; t++) {
            const int j = jbase + t;
            if (j > jh) break;
            float4 kv = *(const float4*)(k + (head + j) * 128 + lane * 4);
            float s = qv.x * kv.x + qv.y * kv.y + qv.z * kv.z + qv.w * kv.w;
#pragma unroll
            for (int o = 16; o; o >>= 1) s += __shfl_xor_sync(0xffffffffu, s, o);
            if (t == lane) sc[slot] = s * scale;
        }
    }

    float m = fmaxf(fmaxf(sc[0], sc[1]), fmaxf(sc[2], sc[3]));
#pragma unroll
    for (int o = 16; o; o >>= 1) m = fmaxf(m, __shfl_xor_sync(0xffffffffu, m, o));

    float p0 = __expf(sc[0] - m);
    float p1 = __expf(sc[1] - m);
    float p2 = __expf(sc[2] - m);
    float p3 = __expf(sc[3] - m);
    float l = p0 + p1 + p2 + p3;
#pragma unroll
    for (int o = 16; o; o >>= 1) l += __shfl_xor_sync(0xffffffffu, l, o);

    float4 acc = {0.f, 0.f, 0.f, 0.f};
#pragma unroll
    for (int slot = 0; slot < 4; slot++) {
        const int jbase = jlo + slot * 32;
        if (jbase > jh) break;
        const float ps = (slot == 0) ? p0 : (slot == 1) ? p1 : (slot == 2) ? p2 : p3;
        for (int t = 0; t < 32; t++) {
            const int j = jbase + t;
            if (j > jh) break;
            const float pj = __shfl_sync(0xffffffffu, ps, t);
            float4 vv = *(const float4*)(v + (head + j) * 128 + lane * 4);
            acc.x += pj * vv.x;
            acc.y += pj * vv.y;
            acc.z += pj * vv.z;
            acc.w += pj * vv.w;
        }
    }

    const float invl = 1.f / l;
    hf2 h0, l0h, h1, l1h;
    split2h(acc.x * invl, acc.y * invl, h0, l0h);
    split2h(acc.z * invl, acc.w * invl, h1, l1h);
    *(hf2*)(ctxHi + obase)     = h0; *(hf2*)(ctxHi + obase + 2) = h1;
    *(hf2*)(ctxLo + obase)     = l0h; *(hf2*)(ctxLo + obase + 2) = l1h;
}

// -------------------- launch --------------------
extern "C" void kernel_launch(void* const* d_in, const int* in_sizes, int n_in,
                              void* d_out, int out_size)
{
    const float* x     = (const float*)d_in[0];
    const int*   xlen  = (const int*)  d_in[1];
    const float* Wp    = (const float*)d_in[2];
    const float* bp    = (const float*)d_in[3];
    const float* ln1_s = (const float*)d_in[4];
    const float* ln1_b = (const float*)d_in[5];
    const float* Wq    = (const float*)d_in[6];
    const float* bq    = (const float*)d_in[7];
    const float* Wk    = (const float*)d_in[8];
    const float* bk    = (const float*)d_in[9];
    const float* Wv    = (const float*)d_in[10];
    const float* bv    = (const float*)d_in[11];
    const float* Wo    = (const float*)d_in[12];
    const float* bo    = (const float*)d_in[13];
    const float* ln2_s = (const float*)d_in[14];
    const float* ln2_b = (const float*)d_in[15];
    const float* W1    = (const float*)d_in[16];
    const float* b1    = (const float*)d_in[17];
    const float* W2    = (const float*)d_in[18];
    const float* b2    = (const float*)d_in[19];
    const float* lnf_s = (const float*)d_in[20];
    const float* lnf_b = (const float*)d_in[21];
    float* out = (float*)d_out;

    float *h, *q, *k, *v, *vmean, *rc, *rs;
    hf *xhi, *xlo, *yhi, *ylo, *chi, *clo, *fhi, *w;
    cudaGetSymbolAddress((void**)&h,    g_h);
    cudaGetSymbolAddress((void**)&q,    g_q);
    cudaGetSymbolAddress((void**)&k,    g_k);
    cudaGetSymbolAddress((void**)&v,    g_v);
    cudaGetSymbolAddress((void**)&vmean,g_vmean);
    cudaGetSymbolAddress((void**)&rc,   g_rcos);
    cudaGetSymbolAddress((void**)&rs,   g_rsin);
    cudaGetSymbolAddress((void**)&xhi,  g_xhi);
    cudaGetSymbolAddress((void**)&xlo,  g_xlo);
    cudaGetSymbolAddress((void**)&yhi,  g_yhi);
    cudaGetSymbolAddress((void**)&ylo,  g_ylo);
    cudaGetSymbolAddress((void**)&chi,  g_chi);
    cudaGetSymbolAddress((void**)&clo,  g_clo);
    cudaGetSymbolAddress((void**)&fhi,  g_fhi);
    cudaGetSymbolAddress((void**)&w,    g_w);

    cudaFuncSetAttribute((const void*)mma_gemm<EP_PROJ, 2>,  cudaFuncAttributeMaxDynamicSharedMemorySize, GEMM_SMEM);
    cudaFuncSetAttribute((const void*)mma_gemm<EP_QKV, 2>,   cudaFuncAttributeMaxDynamicSharedMemorySize, GEMM_SMEM);
    cudaFuncSetAttribute((const void*)mma_gemm<EP_RESID, 2>, cudaFuncAttributeMaxDynamicSharedMemorySize, GEMM_SMEM);
    cudaFuncSetAttribute((const void*)mma_gemm<EP_SILU, 1>,  cudaFuncAttributeMaxDynamicSharedMemorySize, GEMM_SMEM);
    cudaFuncSetAttribute((const void*)mma_gemm<EP_RESID, 1>, cudaFuncAttributeMaxDynamicSharedMemorySize, GEMM_SMEM);

    const dim3 blk(256);

    rope_table_kernel<<<256, blk>>>(rc, rs);
    conv_split<<<(NTOK * 2048 / 4 + 255) / 256, blk>>>(x, xhi, xlo, NTOK * 2048 / 4);
    conv_w<<<(2048 * 1024 / 4 + 255) / 256, blk>>>(Wp, w + WP_OFF, 2048 * 1024 / 4);
    conv_w_qkv<<<4096, blk>>>(Wq, w + QKV_OFF, 0);
    conv_w_qkv<<<4096, blk>>>(Wk, w + QKV_OFF, 1024);
    conv_w_qkv<<<4096, blk>>>(Wv, w + QKV_OFF, 2048);
    conv_w<<<(4 * 1048576 / 4 + 255) / 256, blk>>>(Wo, w + WO_OFF, 4 * 1048576 / 4);
    conv_w<<<(4 * 4194304 / 4 + 255) / 256, blk>>>(W1, w + W1_OFF, 4 * 4194304 / 4);
    conv_w<<<(4 * 4194304 / 4 + 255) / 256, blk>>>(W2, w + W2_OFF, 4 * 4194304 / 4);

    // projector (2-term)
    mma_gemm<EP_PROJ, 2><<<dim3(8, 32), blk, GEMM_SMEM>>>(
        2048, 1024, xhi, xlo, w + WP_OFF,
        bp, nullptr, nullptr, h, nullptr, nullptr, xlen);

    for (int l = 0; l < L_; l++) {
        const size_t oD  = (size_t)l * D_;
        const size_t oF  = (size_t)l * F_;
        const uint32_t oQKV = QKV_OFF + (uint32_t)l * 3145728u;
        const uint32_t oWO  = WO_OFF  + (uint32_t)l * 1048576u;
        const uint32_t oW1  = W1_OFF  + (uint32_t)l * 4194304u;
        const uint32_t oW2  = W2_OFF  + (uint32_t)l * 4194304u;

        layernorm_kernel<true><<<NTOK, blk>>>(h, nullptr, yhi, ylo, ln1_s + oD, ln1_b + oD);

        mma_gemm<EP_QKV, 2><<<dim3(24, 32), blk, GEMM_SMEM>>>(
            1024, 3072, yhi, ylo, w + oQKV,
            bq + oD, bk + oD, bv + oD, q, (hf*)k, (hf*)v, nullptr);

        rope_kernel<<<(2 * B_ * H_ * S_ * 64) / 256, blk>>>(q, k, rc, rs);
        vmean_kernel<<<B_ * H_, 1024>>>(v, vmean);
        attn_kernel<<<(B_ * H_ * S_) / 4, 128>>>(q, k, v, vmean, chi, clo, xlen);

        mma_gemm<EP_RESID, 2><<<dim3(8, 32), blk, GEMM_SMEM>>>(
            1024, 1024, chi, clo, w + oWO,
            bo + oD, nullptr, nullptr, h, nullptr, nullptr, nullptr);

        layernorm_kernel<true><<<NTOK, blk>>>(h, nullptr, yhi, ylo, ln2_s + oD, ln2_b + oD);

        // FFN up: single-term (y_hi only) + SiLU -> fhi
        mma_gemm<EP_SILU, 1><<<dim3(32, 32), blk, GEMM_SMEM>>>(
            1024, 4096, yhi, nullptr, w + oW1,
            b1 + oF, nullptr, nullptr, nullptr, fhi, nullptr, nullptr);

        // FFN down: single-term (f_hi only)
        mma_gemm<EP_RESID, 1><<<dim3(8, 32), blk, GEMM_SMEM>>>(
            4096, 1024, fhi, nullptr, w + oW2,
            b2 + oD, nullptr, nullptr, h, nullptr, nullptr, nullptr);
    }

    layernorm_kernel<false><<<NTOK, blk>>>(h, out, nullptr, nullptr, lnf_s, lnf_b);
}

// round 9
// speedup vs baseline: 5.1680x; 1.1010x over previous
#include <cuda_runtime.h>
#include <cuda_fp16.h>
#include <math.h>
#include <stdint.h>

// Problem constants
#define B_   4
#define S_   1024
#define D_   1024
#define F_   4096
#define H_   8
#define DH_  128
#define L_   4
#define NTOK (B_ * S_)          // 4096
#define WIN_ 100
#define LFW_ 20

typedef __half  hf;
typedef __half2 hf2;

// -------------------- scratch --------------------
__device__ float g_h [NTOK * D_];
__device__ float g_q [NTOK * D_];
__device__ float g_k [NTOK * D_];
__device__ float g_v [NTOK * D_];
__device__ float g_vmean[B_ * H_ * DH_];
__device__ float g_rcos[S_ * 64];
__device__ float g_rsin[S_ * 64];

// fp16 hi/lo activation buffers
__device__ hf g_xhi[NTOK * 2048], g_xlo[NTOK * 2048];
__device__ hf g_yhi[NTOK * D_];
__device__ hf g_chi[NTOK * D_],   g_clo[NTOK * D_];
__device__ hf g_fhi[NTOK * F_];

// converted weights (single fp16), offsets in elements
#define WP_OFF   0u
#define QKV_OFF  2097152u
#define WO_OFF   (QKV_OFF + 4u * 3145728u)
#define W1_OFF   (WO_OFF + 4u * 1048576u)
#define W2_OFF   (W1_OFF + 4u * 4194304u)
#define WTOT     (W2_OFF + 4u * 4194304u)
__device__ hf g_w[WTOT];

// ==================== helpers ====================
__device__ __forceinline__ uint32_t smem_u32(const void* p) {
    uint32_t a;
    asm("{ .reg .u64 t; cvta.to.shared.u64 t, %1; cvt.u32.u64 %0, t; }" : "=r"(a) : "l"(p));
    return a;
}
__device__ __forceinline__ void cp16(uint32_t saddr, const void* gaddr) {
    asm volatile("cp.async.cg.shared.global [%0], [%1], 16;" :: "r"(saddr), "l"(gaddr));
}
__device__ __forceinline__ void cp_commit() {
    asm volatile("cp.async.commit_group;" ::: "memory");
}
__device__ __forceinline__ void ldsm4(uint32_t& r0, uint32_t& r1, uint32_t& r2, uint32_t& r3,
                                      uint32_t addr) {
    asm volatile("ldmatrix.sync.aligned.m8n8.x4.shared.b16 {%0,%1,%2,%3}, [%4];"
                 : "=r"(r0), "=r"(r1), "=r"(r2), "=r"(r3) : "r"(addr));
}
__device__ __forceinline__ void ldsm4t(uint32_t& r0, uint32_t& r1, uint32_t& r2, uint32_t& r3,
                                       uint32_t addr) {
    asm volatile("ldmatrix.sync.aligned.m8n8.x4.trans.shared.b16 {%0,%1,%2,%3}, [%4];"
                 : "=r"(r0), "=r"(r1), "=r"(r2), "=r"(r3) : "r"(addr));
}
__device__ __forceinline__ void mma16816(float* d, const uint32_t* a, const uint32_t* b) {
    asm volatile(
        "mma.sync.aligned.m16n8k16.row.col.f32.f16.f16.f32 "
        "{%0,%1,%2,%3}, {%4,%5,%6,%7}, {%8,%9}, {%0,%1,%2,%3};"
        : "+f"(d[0]), "+f"(d[1]), "+f"(d[2]), "+f"(d[3])
        : "r"(a[0]), "r"(a[1]), "r"(a[2]), "r"(a[3]), "r"(b[0]), "r"(b[1]));
}
__device__ __forceinline__ void split2h(float x, float y, hf2& h, hf2& l) {
    h = __floats2half2_rn(x, y);
    float2 hfv = __half22float2(h);
    l = __floats2half2_rn(x - hfv.x, y - hfv.y);
}

// ==================== converters ====================
__global__ void __launch_bounds__(256)
conv_split(const float* __restrict__ in, hf* __restrict__ hi, hf* __restrict__ lo, int n4)
{
    int i = blockIdx.x * blockDim.x + threadIdx.x;
    if (i >= n4) return;
    float4 v = ((const float4*)in)[i];
    hf2 h0, l0, h1, l1;
    split2h(v.x, v.y, h0, l0);
    split2h(v.z, v.w, h1, l1);
    ((hf2*)hi)[2 * i] = h0; ((hf2*)hi)[2 * i + 1] = h1;
    ((hf2*)lo)[2 * i] = l0; ((hf2*)lo)[2 * i + 1] = l1;
}
__global__ void __launch_bounds__(256)
conv_w(const float* __restrict__ in, hf* __restrict__ w, int n4)
{
    int i = blockIdx.x * blockDim.x + threadIdx.x;
    if (i >= n4) return;
    float4 v = ((const float4*)in)[i];
    ((hf2*)w)[2 * i]     = __floats2half2_rn(v.x, v.y);
    ((hf2*)w)[2 * i + 1] = __floats2half2_rn(v.z, v.w);
}
__global__ void __launch_bounds__(256)
conv_w_qkv(const float* __restrict__ in, hf* __restrict__ w, int coff)
{
    int i = blockIdx.x * blockDim.x + threadIdx.x;
    int row = i >> 8, c4 = i & 255;
    float4 v = ((const float4*)in)[i];
    size_t o2 = ((size_t)row * 3072 + coff + c4 * 4) >> 1;
    ((hf2*)w)[o2]     = __floats2half2_rn(v.x, v.y);
    ((hf2*)w)[o2 + 1] = __floats2half2_rn(v.z, v.w);
}

// ==================== pipelined fp16(-split) GEMM ====================
#define EP_PROJ  1
#define EP_QKV   2
#define EP_RESID 3
#define EP_SILU  4

#define A_PITCH 144
#define B_PITCH 272
#define OFF_AH 0
#define OFF_AL 18432
#define OFF_B  36864
#define STAGE_B 54272
#define GEMM_SMEM (2 * STAGE_B)   // 108544

template <int NT>
__device__ __forceinline__ void stage_load(
    uint32_t stb, const hf* Ah, const hf* Al, const hf* Bw,
    int k0, int bm, int bn, int K, int NN, int tid)
{
#pragma unroll
    for (int t = 0; t < 4; t++) {
        const int idx = t * 256 + tid;
        const int row = idx >> 3, seg = idx & 7;
        const size_t go = (size_t)(bm + row) * K + k0 + seg * 8;
        const uint32_t so = stb + (uint32_t)row * A_PITCH + seg * 16;
        cp16(so + OFF_AH, Ah + go);
        if (NT == 2) cp16(so + OFF_AL, Al + go);
    }
#pragma unroll
    for (int t = 0; t < 4; t++) {
        const int idx = t * 256 + tid;
        const int row = idx >> 4, seg = idx & 15;
        const size_t go = (size_t)(k0 + row) * NN + bn + seg * 8;
        const uint32_t so = stb + (uint32_t)row * B_PITCH + seg * 16;
        cp16(so + OFF_B, Bw + go);
    }
}

template <int MODE, int NT>
__global__ void __launch_bounds__(256, 2)
mma_gemm(int K, int NN,
         const hf* __restrict__ Ah, const hf* __restrict__ Al,
         const hf* __restrict__ Bw,
         const float* __restrict__ bias, const float* __restrict__ bias2,
         const float* __restrict__ bias3,
         float* __restrict__ out, hf* __restrict__ outHi, hf* __restrict__ outLo,
         const int* __restrict__ x_lengths)
{
    extern __shared__ char sm[];
    const uint32_t sb = smem_u32(sm);
    const int tid  = threadIdx.x;
    const int wid  = tid >> 5;
    const int lane = tid & 31;
    const int bn = blockIdx.x * 128;
    const int bm = blockIdx.y * 128;
    const int wm = wid & 1;
    const int wn = wid >> 1;

    float acc[4][4][4];
#pragma unroll
    for (int i = 0; i < 4; i++)
#pragma unroll
        for (int j = 0; j < 4; j++)
#pragma unroll
            for (int r = 0; r < 4; r++) acc[i][j][r] = 0.f;

    const int quad = lane >> 3;
    const int qr   = lane & 7;
    const uint32_t aOffH = OFF_AH + (uint32_t)(wm * 64 + (quad & 1) * 8 + qr) * A_PITCH + (quad >> 1) * 16;
    const uint32_t bOff  = OFF_B + (uint32_t)((quad & 1) * 8 + qr) * B_PITCH
                         + (uint32_t)(wn * 32 + (quad >> 1) * 8) * 2;

    const int nch = K >> 6;

    stage_load<NT>(sb, Ah, Al, Bw, 0, bm, bn, K, NN, tid);
    cp_commit();
    if (nch > 1) {
        stage_load<NT>(sb + STAGE_B, Ah, Al, Bw, 64, bm, bn, K, NN, tid);
        cp_commit();
    }

    for (int c = 0; c < nch; c++) {
        if (c < nch - 1) asm volatile("cp.async.wait_group 1;" ::: "memory");
        else             asm volatile("cp.async.wait_group 0;" ::: "memory");
        __syncthreads();

        const uint32_t stb = sb + (uint32_t)(c & 1) * STAGE_B;

#pragma unroll
        for (int ks = 0; ks < 4; ks++) {
            uint32_t aH[4][4], aL[4][4], bF[4][2];
#pragma unroll
            for (int mi = 0; mi < 4; mi++) {
                const uint32_t ad = stb + aOffH + (uint32_t)mi * (16 * A_PITCH) + ks * 32;
                ldsm4(aH[mi][0], aH[mi][1], aH[mi][2], aH[mi][3], ad);
                if (NT == 2)
                    ldsm4(aL[mi][0], aL[mi][1], aL[mi][2], aL[mi][3], ad + (OFF_AL - OFF_AH));
            }
#pragma unroll
            for (int bp = 0; bp < 2; bp++) {
                const uint32_t ad = stb + bOff + (uint32_t)ks * (16 * B_PITCH) + bp * 32;
                uint32_t r0, r1, r2, r3;
                ldsm4t(r0, r1, r2, r3, ad);
                bF[2 * bp][0] = r0; bF[2 * bp][1] = r1;
                bF[2 * bp + 1][0] = r2; bF[2 * bp + 1][1] = r3;
            }
#pragma unroll
            for (int mi = 0; mi < 4; mi++)
#pragma unroll
                for (int ni = 0; ni < 4; ni++) {
                    mma16816(acc[mi][ni], aH[mi], bF[ni]);
                    if (NT == 2) mma16816(acc[mi][ni], aL[mi], bF[ni]);
                }
        }
        __syncthreads();

        if (c + 2 < nch) {
            stage_load<NT>(stb, Ah, Al, Bw, (c + 2) << 6, bm, bn, K, NN, tid);
            cp_commit();
        }
    }

    // ---- epilogue ----
    const int grp = lane >> 2;
    const int qc  = (lane & 3) * 2;
#pragma unroll
    for (int mi = 0; mi < 4; mi++) {
        const int m0 = bm + wm * 64 + mi * 16 + grp;
#pragma unroll
        for (int ni = 0; ni < 4; ni++) {
            const int n = bn + wn * 32 + ni * 8 + qc;
            float2 bsv;
            if (MODE == EP_QKV) {
                const int sel = n >> 10;
                const float* bp = (sel == 0) ? bias : (sel == 1) ? bias2 : bias3;
                bsv = *(const float2*)(bp + (n & 1023));
            } else {
                bsv = *(const float2*)(bias + n);
            }
            float2 v01, v23;
            v01.x = acc[mi][ni][0] + bsv.x;
            v01.y = acc[mi][ni][1] + bsv.y;
            v23.x = acc[mi][ni][2] + bsv.x;
            v23.y = acc[mi][ni][3] + bsv.y;
#pragma unroll
            for (int half = 0; half < 2; half++) {
                const int m = m0 + half * 8;
                float2 v = half ? v23 : v01;
                if (MODE == EP_PROJ) {
                    const int b = m >> 10, s = m & 1023;
                    const int len = x_lengths[b] >> 2;
                    if (s >= len) { v.x = 0.f; v.y = 0.f; }
                    *(float2*)(out + (size_t)m * NN + n) = v;
                } else if (MODE == EP_QKV) {
                    const int sel = n >> 10;
                    const int nl = n & 1023;
                    const int b = m >> 10, s = m & 1023;
                    const int hh = nl >> 7, dh = nl & 127;
                    float* dst = (sel == 0) ? out : (sel == 1) ? (float*)outHi : (float*)outLo;
                    *(float2*)(dst + ((size_t)((b << 3) | hh) * 1024 + s) * 128 + dh) = v;
                } else if (MODE == EP_RESID) {
                    float2 o = *(float2*)(out + (size_t)m * NN + n);
                    o.x += v.x; o.y += v.y;
                    *(float2*)(out + (size_t)m * NN + n) = o;
                } else { // EP_SILU -> single fp16
                    v.x = v.x / (1.f + __expf(-v.x));
                    v.y = v.y / (1.f + __expf(-v.y));
                    const size_t o2 = ((size_t)m * NN + n) >> 1;
                    ((hf2*)outHi)[o2] = __floats2half2_rn(v.x, v.y);
                }
            }
        }
    }
}

// -------------------- LayerNorm --------------------
template <bool HFOUT>
__global__ void __launch_bounds__(256)
layernorm_kernel(const float* __restrict__ in, float* __restrict__ out,
                 hf* __restrict__ outHi,
                 const float* __restrict__ scale, const float* __restrict__ bias)
{
    __shared__ float sh1[8];
    __shared__ float sh2[8];
    const int row = blockIdx.x;
    const int t = threadIdx.x;
    const int lane = t & 31, w = t >> 5;
    const float* xr = in + (size_t)row * 1024;

    float vals[4];
    float s = 0.f;
#pragma unroll
    for (int r = 0; r < 4; r++) { vals[r] = xr[t + 256 * r]; s += vals[r]; }
#pragma unroll
    for (int o = 16; o; o >>= 1) s += __shfl_xor_sync(0xffffffffu, s, o);
    if (lane == 0) sh1[w] = s;
    __syncthreads();
    float tot = (t < 8) ? sh1[t] : 0.f;
    if (w == 0) {
#pragma unroll
        for (int o = 16; o; o >>= 1) tot += __shfl_xor_sync(0xffffffffu, tot, o);
        if (lane == 0) sh1[0] = tot;
    }
    __syncthreads();
    const float mean = sh1[0] * (1.f / 1024.f);

    float vs = 0.f;
#pragma unroll
    for (int r = 0; r < 4; r++) { float d = vals[r] - mean; vs += d * d; }
#pragma unroll
    for (int o = 16; o; o >>= 1) vs += __shfl_xor_sync(0xffffffffu, vs, o);
    if (lane == 0) sh2[w] = vs;
    __syncthreads();
    float vtot = (t < 8) ? sh2[t] : 0.f;
    if (w == 0) {
#pragma unroll
        for (int o = 16; o; o >>= 1) vtot += __shfl_xor_sync(0xffffffffu, vtot, o);
        if (lane == 0) sh2[0] = vtot;
    }
    __syncthreads();
    const float var = sh2[0] * (1.f / 1024.f);
    const float inv = rsqrtf(var + 1e-5f);

#pragma unroll
    for (int r = 0; r < 4; r++) {
        int d = t + 256 * r;
        float v = (vals[r] - mean) * inv * scale[d] + bias[d];
        if (HFOUT) {
            outHi[(size_t)row * 1024 + d] = __float2half_rn(v);
        } else {
            out[(size_t)row * 1024 + d] = v;
        }
    }
}

// -------------------- RoPE table + apply --------------------
__global__ void __launch_bounds__(256)
rope_table_kernel(float* __restrict__ rc, float* __restrict__ rs)
{
    int idx = blockIdx.x * blockDim.x + threadIdx.x;
    int p = idx & 63;
    int s = idx >> 6;
    float inv_freq = expf(-(float)p * (9.210340371976184f / 64.f));
    float ang = (float)s * inv_freq;
    float sn, cs;
    sincosf(ang, &sn, &cs);
    rc[idx] = cs;
    rs[idx] = sn;
}

__global__ void __launch_bounds__(256)
rope_kernel(float* __restrict__ q, float* __restrict__ k,
            const float* __restrict__ rc, const float* __restrict__ rs)
{
    const int total = B_ * H_ * S_ * 64;
    int idx = blockIdx.x * blockDim.x + threadIdx.x;
    if (idx >= 2 * total) return;
    float* ptr = (idx < total) ? q : k;
    int id = (idx < total) ? idx : idx - total;
    int p  = id & 63;
    int s  = (id >> 6) & 1023;
    int bh = id >> 16;
    int tix = (s << 6) | p;
    float cs = rc[tix], sn = rs[tix];
    int base = (bh * 1024 + s) * 128 + p;
    float x1 = ptr[base];
    float x2 = ptr[base + 64];
    ptr[base]      = x1 * cs - x2 * sn;
    ptr[base + 64] = x1 * sn + x2 * cs;
}

// -------------------- V mean --------------------
__global__ void __launch_bounds__(1024)
vmean_kernel(const float* __restrict__ v, float* __restrict__ vmean)
{
    __shared__ float partial[8][128];
    const int bh = blockIdx.x;
    const int d  = threadIdx.x & 127;
    const int sl = threadIdx.x >> 7;
    const float* base = v + (size_t)bh * S_ * DH_ + (size_t)sl * 128 * DH_ + d;
    float s = 0.f;
#pragma unroll 4
    for (int j = 0; j < 128; j++) s += base[j * DH_];
    partial[sl][d] = s;
    __syncthreads();
    if (sl == 0) {
        float t = 0.f;
#pragma unroll
        for (int r = 0; r < 8; r++) t += partial[r][d];
        vmean[bh * DH_ + d] = t * (1.f / (float)S_);
    }
}

// -------------------- windowed attention (16 queries per CTA) ---------------
__global__ void __launch_bounds__(512)
attn_kernel(const float* __restrict__ q, const float* __restrict__ k,
            const float* __restrict__ v, const float* __restrict__ vmean,
            hf* __restrict__ ctxHi, hf* __restrict__ ctxLo,
            const int* __restrict__ x_lengths)
{
    const int wid  = blockIdx.x * 16 + (threadIdx.x >> 5);
    const int lane = threadIdx.x & 31;
    const int i  = wid & 1023;
    const int hh = (wid >> 10) & 7;
    const int b  = wid >> 13;

    const int len = x_lengths[b] >> 2;
    int jlo = i - (WIN_ - 1); if (jlo < 0) jlo = 0;
    int jhi = i + LFW_;       if (jhi > S_ - 1) jhi = S_ - 1;
    int jh  = (len - 1 < jhi) ? (len - 1) : jhi;

    const size_t obase = ((size_t)(b * 1024 + i)) * 1024 + hh * 128 + lane * 4;

    if (jh < jlo) {
        const float4 vm = *(const float4*)(vmean + (b * 8 + hh) * 128 + lane * 4);
        hf2 h0, l0, h1, l1;
        split2h(vm.x, vm.y, h0, l0);
        split2h(vm.z, vm.w, h1, l1);
        *(hf2*)(ctxHi + obase)     = h0; *(hf2*)(ctxHi + obase + 2) = h1;
        *(hf2*)(ctxLo + obase)     = l0; *(hf2*)(ctxLo + obase + 2) = l1;
        return;
    }

    const size_t head = ((size_t)(b * 8 + hh)) * 1024;
    const float4 qv = *(const float4*)(q + (head + i) * 128 + lane * 4);
    const float scale = 0.08838834764831845f;

    float sc[4] = {-1e30f, -1e30f, -1e30f, -1e30f};
#pragma unroll
    for (int slot = 0; slot < 4; slot++) {
        const int jbase = jlo + slot * 32;
        if (jbase > jh) break;
        for (int t = 0; t < 32; t++) {
            const int j = jbase + t;
            if (j > jh) break;
            float4 kv = *(const float4*)(k + (head + j) * 128 + lane * 4);
            float s = qv.x * kv.x + qv.y * kv.y + qv.z * kv.z + qv.w * kv.w;
#pragma unroll
            for (int o = 16; o; o >>= 1) s += __shfl_xor_sync(0xffffffffu, s, o);
            if (t == lane) sc[slot] = s * scale;
        }
    }

    float m = fmaxf(fmaxf(sc[0], sc[1]), fmaxf(sc[2], sc[3]));
#pragma unroll
    for (int o = 16; o; o >>= 1) m = fmaxf(m, __shfl_xor_sync(0xffffffffu, m, o));

    float p0 = __expf(sc[0] - m);
    float p1 = __expf(sc[1] - m);
    float p2 = __expf(sc[2] - m);
    float p3 = __expf(sc[3] - m);
    float l = p0 + p1 + p2 + p3;
#pragma unroll
    for (int o = 16; o; o >>= 1) l += __shfl_xor_sync(0xffffffffu, l, o);

    float4 acc = {0.f, 0.f, 0.f, 0.f};
#pragma unroll
    for (int slot = 0; slot < 4; slot++) {
        const int jbase = jlo + slot * 32;
        if (jbase > jh) break;
        const float ps = (slot == 0) ? p0 : (slot == 1) ? p1 : (slot == 2) ? p2 : p3;
        for (int t = 0; t < 32; t++) {
            const int j = jbase + t;
            if (j > jh) break;
            const float pj = __shfl_sync(0xffffffffu, ps, t);
            float4 vv = *(const float4*)(v + (head + j) * 128 + lane * 4);
            acc.x += pj * vv.x;
            acc.y += pj * vv.y;
            acc.z += pj * vv.z;
            acc.w += pj * vv.w;
        }
    }

    const float invl = 1.f / l;
    hf2 h0, l0h, h1, l1h;
    split2h(acc.x * invl, acc.y * invl, h0, l0h);
    split2h(acc.z * invl, acc.w * invl, h1, l1h);
    *(hf2*)(ctxHi + obase)     = h0; *(hf2*)(ctxHi + obase + 2) = h1;
    *(hf2*)(ctxLo + obase)     = l0h; *(hf2*)(ctxLo + obase + 2) = l1h;
}

// -------------------- launch --------------------
extern "C" void kernel_launch(void* const* d_in, const int* in_sizes, int n_in,
                              void* d_out, int out_size)
{
    const float* x     = (const float*)d_in[0];
    const int*   xlen  = (const int*)  d_in[1];
    const float* Wp    = (const float*)d_in[2];
    const float* bp    = (const float*)d_in[3];
    const float* ln1_s = (const float*)d_in[4];
    const float* ln1_b = (const float*)d_in[5];
    const float* Wq    = (const float*)d_in[6];
    const float* bq    = (const float*)d_in[7];
    const float* Wk    = (const float*)d_in[8];
    const float* bk    = (const float*)d_in[9];
    const float* Wv    = (const float*)d_in[10];
    const float* bv    = (const float*)d_in[11];
    const float* Wo    = (const float*)d_in[12];
    const float* bo    = (const float*)d_in[13];
    const float* ln2_s = (const float*)d_in[14];
    const float* ln2_b = (const float*)d_in[15];
    const float* W1    = (const float*)d_in[16];
    const float* b1    = (const float*)d_in[17];
    const float* W2    = (const float*)d_in[18];
    const float* b2    = (const float*)d_in[19];
    const float* lnf_s = (const float*)d_in[20];
    const float* lnf_b = (const float*)d_in[21];
    float* out = (float*)d_out;

    float *h, *q, *k, *v, *vmean, *rc, *rs;
    hf *xhi, *xlo, *yhi, *chi, *clo, *fhi, *w;
    cudaGetSymbolAddress((void**)&h,    g_h);
    cudaGetSymbolAddress((void**)&q,    g_q);
    cudaGetSymbolAddress((void**)&k,    g_k);
    cudaGetSymbolAddress((void**)&v,    g_v);
    cudaGetSymbolAddress((void**)&vmean,g_vmean);
    cudaGetSymbolAddress((void**)&rc,   g_rcos);
    cudaGetSymbolAddress((void**)&rs,   g_rsin);
    cudaGetSymbolAddress((void**)&xhi,  g_xhi);
    cudaGetSymbolAddress((void**)&xlo,  g_xlo);
    cudaGetSymbolAddress((void**)&yhi,  g_yhi);
    cudaGetSymbolAddress((void**)&chi,  g_chi);
    cudaGetSymbolAddress((void**)&clo,  g_clo);
    cudaGetSymbolAddress((void**)&fhi,  g_fhi);
    cudaGetSymbolAddress((void**)&w,    g_w);

    cudaFuncSetAttribute((const void*)mma_gemm<EP_PROJ, 2>,  cudaFuncAttributeMaxDynamicSharedMemorySize, GEMM_SMEM);
    cudaFuncSetAttribute((const void*)mma_gemm<EP_QKV, 1>,   cudaFuncAttributeMaxDynamicSharedMemorySize, GEMM_SMEM);
    cudaFuncSetAttribute((const void*)mma_gemm<EP_RESID, 2>, cudaFuncAttributeMaxDynamicSharedMemorySize, GEMM_SMEM);
    cudaFuncSetAttribute((const void*)mma_gemm<EP_SILU, 1>,  cudaFuncAttributeMaxDynamicSharedMemorySize, GEMM_SMEM);
    cudaFuncSetAttribute((const void*)mma_gemm<EP_RESID, 1>, cudaFuncAttributeMaxDynamicSharedMemorySize, GEMM_SMEM);

    const dim3 blk(256);

    rope_table_kernel<<<256, blk>>>(rc, rs);
    conv_split<<<(NTOK * 2048 / 4 + 255) / 256, blk>>>(x, xhi, xlo, NTOK * 2048 / 4);
    conv_w<<<(2048 * 1024 / 4 + 255) / 256, blk>>>(Wp, w + WP_OFF, 2048 * 1024 / 4);
    conv_w_qkv<<<4096, blk>>>(Wq, w + QKV_OFF, 0);
    conv_w_qkv<<<4096, blk>>>(Wk, w + QKV_OFF, 1024);
    conv_w_qkv<<<4096, blk>>>(Wv, w + QKV_OFF, 2048);
    conv_w<<<(4 * 1048576 / 4 + 255) / 256, blk>>>(Wo, w + WO_OFF, 4 * 1048576 / 4);
    conv_w<<<(4 * 4194304 / 4 + 255) / 256, blk>>>(W1, w + W1_OFF, 4 * 4194304 / 4);
    conv_w<<<(4 * 4194304 / 4 + 255) / 256, blk>>>(W2, w + W2_OFF, 4 * 4194304 / 4);

    // projector (2-term)
    mma_gemm<EP_PROJ, 2><<<dim3(8, 32), blk, GEMM_SMEM>>>(
        2048, 1024, xhi, xlo, w + WP_OFF,
        bp, nullptr, nullptr, h, nullptr, nullptr, xlen);

    for (int l = 0; l < L_; l++) {
        const size_t oD  = (size_t)l * D_;
        const size_t oF  = (size_t)l * F_;
        const uint32_t oQKV = QKV_OFF + (uint32_t)l * 3145728u;
        const uint32_t oWO  = WO_OFF  + (uint32_t)l * 1048576u;
        const uint32_t oW1  = W1_OFF  + (uint32_t)l * 4194304u;
        const uint32_t oW2  = W2_OFF  + (uint32_t)l * 4194304u;

        layernorm_kernel<true><<<NTOK, blk>>>(h, nullptr, yhi, ln1_s + oD, ln1_b + oD);

        // fused QKV GEMM, single-term activations
        mma_gemm<EP_QKV, 1><<<dim3(24, 32), blk, GEMM_SMEM>>>(
            1024, 3072, yhi, nullptr, w + oQKV,
            bq + oD, bk + oD, bv + oD, q, (hf*)k, (hf*)v, nullptr);

        rope_kernel<<<(2 * B_ * H_ * S_ * 64) / 256, blk>>>(q, k, rc, rs);
        vmean_kernel<<<B_ * H_, 1024>>>(v, vmean);
        attn_kernel<<<(B_ * H_ * S_) / 16, 512>>>(q, k, v, vmean, chi, clo, xlen);

        // WO: 2-term (ctx hi+lo)
        mma_gemm<EP_RESID, 2><<<dim3(8, 32), blk, GEMM_SMEM>>>(
            1024, 1024, chi, clo, w + oWO,
            bo + oD, nullptr, nullptr, h, nullptr, nullptr, nullptr);

        layernorm_kernel<true><<<NTOK, blk>>>(h, nullptr, yhi, ln2_s + oD, ln2_b + oD);

        mma_gemm<EP_SILU, 1><<<dim3(32, 32), blk, GEMM_SMEM>>>(
            1024, 4096, yhi, nullptr, w + oW1,
            b1 + oF, nullptr, nullptr, nullptr, fhi, nullptr, nullptr);

        mma_gemm<EP_RESID, 1><<<dim3(8, 32), blk, GEMM_SMEM>>>(
            4096, 1024, fhi, nullptr, w + oW2,
            b2 + oD, nullptr, nullptr, h, nullptr, nullptr, nullptr);
    }

    layernorm_kernel<false><<<NTOK, blk>>>(h, out, nullptr, lnf_s, lnf_b);
}

// round 10
// speedup vs baseline: 5.1939x; 1.0050x over previous
#include <cuda_runtime.h>
#include <cuda_fp16.h>
#include <math.h>
#include <stdint.h>

// Problem constants
#define B_   4
#define S_   1024
#define D_   1024
#define F_   4096
#define H_   8
#define DH_  128
#define L_   4
#define NTOK (B_ * S_)          // 4096
#define WIN_ 100
#define LFW_ 20

typedef __half  hf;
typedef __half2 hf2;

// -------------------- scratch --------------------
__device__ float g_h [NTOK * D_];
__device__ float g_q [NTOK * D_];
__device__ float g_k [NTOK * D_];
__device__ float g_v [NTOK * D_];
__device__ float g_vmean[B_ * H_ * DH_];
__device__ float g_rcos[S_ * 64];
__device__ float g_rsin[S_ * 64];

// fp16 activation buffers
__device__ hf g_xhi[NTOK * 2048], g_xlo[NTOK * 2048];
__device__ hf g_yhi[NTOK * D_];
__device__ hf g_chi[NTOK * D_];
__device__ hf g_fhi[NTOK * F_];

// converted weights (single fp16), offsets in elements
#define WP_OFF   0u
#define QKV_OFF  2097152u
#define WO_OFF   (QKV_OFF + 4u * 3145728u)
#define W1_OFF   (WO_OFF + 4u * 1048576u)
#define W2_OFF   (W1_OFF + 4u * 4194304u)
#define WTOT     (W2_OFF + 4u * 4194304u)
__device__ hf g_w[WTOT];

// ==================== helpers ====================
__device__ __forceinline__ uint32_t smem_u32(const void* p) {
    uint32_t a;
    asm("{ .reg .u64 t; cvta.to.shared.u64 t, %1; cvt.u32.u64 %0, t; }" : "=r"(a) : "l"(p));
    return a;
}
__device__ __forceinline__ void cp16(uint32_t saddr, const void* gaddr) {
    asm volatile("cp.async.cg.shared.global [%0], [%1], 16;" :: "r"(saddr), "l"(gaddr));
}
__device__ __forceinline__ void cp_commit() {
    asm volatile("cp.async.commit_group;" ::: "memory");
}
__device__ __forceinline__ void ldsm4(uint32_t& r0, uint32_t& r1, uint32_t& r2, uint32_t& r3,
                                      uint32_t addr) {
    asm volatile("ldmatrix.sync.aligned.m8n8.x4.shared.b16 {%0,%1,%2,%3}, [%4];"
                 : "=r"(r0), "=r"(r1), "=r"(r2), "=r"(r3) : "r"(addr));
}
__device__ __forceinline__ void ldsm4t(uint32_t& r0, uint32_t& r1, uint32_t& r2, uint32_t& r3,
                                       uint32_t addr) {
    asm volatile("ldmatrix.sync.aligned.m8n8.x4.trans.shared.b16 {%0,%1,%2,%3}, [%4];"
                 : "=r"(r0), "=r"(r1), "=r"(r2), "=r"(r3) : "r"(addr));
}
__device__ __forceinline__ void mma16816(float* d, const uint32_t* a, const uint32_t* b) {
    asm volatile(
        "mma.sync.aligned.m16n8k16.row.col.f32.f16.f16.f32 "
        "{%0,%1,%2,%3}, {%4,%5,%6,%7}, {%8,%9}, {%0,%1,%2,%3};"
        : "+f"(d[0]), "+f"(d[1]), "+f"(d[2]), "+f"(d[3])
        : "r"(a[0]), "r"(a[1]), "r"(a[2]), "r"(a[3]), "r"(b[0]), "r"(b[1]));
}
__device__ __forceinline__ void split2h(float x, float y, hf2& h, hf2& l) {
    h = __floats2half2_rn(x, y);
    float2 hfv = __half22float2(h);
    l = __floats2half2_rn(x - hfv.x, y - hfv.y);
}

// ==================== converters (4 float4 per thread) ====================
__global__ void __launch_bounds__(256)
conv_split(const float* __restrict__ in, hf* __restrict__ hi, hf* __restrict__ lo)
{
#pragma unroll
    for (int r = 0; r < 4; r++) {
        int i = blockIdx.x * 1024 + r * 256 + threadIdx.x;
        float4 v = ((const float4*)in)[i];
        hf2 h0, l0, h1, l1;
        split2h(v.x, v.y, h0, l0);
        split2h(v.z, v.w, h1, l1);
        ((hf2*)hi)[2 * i] = h0; ((hf2*)hi)[2 * i + 1] = h1;
        ((hf2*)lo)[2 * i] = l0; ((hf2*)lo)[2 * i + 1] = l1;
    }
}
__global__ void __launch_bounds__(256)
conv_w(const float* __restrict__ in, hf* __restrict__ w)
{
#pragma unroll
    for (int r = 0; r < 4; r++) {
        int i = blockIdx.x * 1024 + r * 256 + threadIdx.x;
        float4 v = ((const float4*)in)[i];
        ((hf2*)w)[2 * i]     = __floats2half2_rn(v.x, v.y);
        ((hf2*)w)[2 * i + 1] = __floats2half2_rn(v.z, v.w);
    }
}
__global__ void __launch_bounds__(256)
conv_w_qkv(const float* __restrict__ in, hf* __restrict__ w, int coff)
{
#pragma unroll
    for (int r = 0; r < 4; r++) {
        int i = blockIdx.x * 1024 + r * 256 + threadIdx.x;   // f4 index
        int row = i >> 8, c4 = i & 255;
        float4 v = ((const float4*)in)[i];
        size_t o2 = ((size_t)row * 3072 + coff + c4 * 4) >> 1;
        ((hf2*)w)[o2]     = __floats2half2_rn(v.x, v.y);
        ((hf2*)w)[o2 + 1] = __floats2half2_rn(v.z, v.w);
    }
}

// ==================== pipelined fp16(-split) GEMM ====================
#define EP_PROJ  1
#define EP_QKV   2
#define EP_RESID 3
#define EP_SILU  4

#define A_PITCH 144
#define B_PITCH 272
#define OFF_AH 0
#define OFF_AL 18432
#define OFF_B  36864
#define STAGE_B 54272
#define GEMM_SMEM (2 * STAGE_B)   // 108544

template <int NT>
__device__ __forceinline__ void stage_load(
    uint32_t stb, const hf* Ah, const hf* Al, const hf* Bw,
    int k0, int bm, int bn, int K, int NN, int tid)
{
#pragma unroll
    for (int t = 0; t < 4; t++) {
        const int idx = t * 256 + tid;
        const int row = idx >> 3, seg = idx & 7;
        const size_t go = (size_t)(bm + row) * K + k0 + seg * 8;
        const uint32_t so = stb + (uint32_t)row * A_PITCH + seg * 16;
        cp16(so + OFF_AH, Ah + go);
        if (NT == 2) cp16(so + OFF_AL, Al + go);
    }
#pragma unroll
    for (int t = 0; t < 4; t++) {
        const int idx = t * 256 + tid;
        const int row = idx >> 4, seg = idx & 15;
        const size_t go = (size_t)(k0 + row) * NN + bn + seg * 8;
        const uint32_t so = stb + (uint32_t)row * B_PITCH + seg * 16;
        cp16(so + OFF_B, Bw + go);
    }
}

template <int MODE, int NT>
__global__ void __launch_bounds__(256, 2)
mma_gemm(int K, int NN,
         const hf* __restrict__ Ah, const hf* __restrict__ Al,
         const hf* __restrict__ Bw,
         const float* __restrict__ bias, const float* __restrict__ bias2,
         const float* __restrict__ bias3,
         float* __restrict__ out, hf* __restrict__ outHi, hf* __restrict__ outLo,
         const int* __restrict__ x_lengths)
{
    extern __shared__ char sm[];
    const uint32_t sb = smem_u32(sm);
    const int tid  = threadIdx.x;
    const int wid  = tid >> 5;
    const int lane = tid & 31;
    const int bn = blockIdx.x * 128;
    const int bm = blockIdx.y * 128;
    const int wm = wid & 1;
    const int wn = wid >> 1;

    float acc[4][4][4];
#pragma unroll
    for (int i = 0; i < 4; i++)
#pragma unroll
        for (int j = 0; j < 4; j++)
#pragma unroll
            for (int r = 0; r < 4; r++) acc[i][j][r] = 0.f;

    const int quad = lane >> 3;
    const int qr   = lane & 7;
    const uint32_t aOffH = OFF_AH + (uint32_t)(wm * 64 + (quad & 1) * 8 + qr) * A_PITCH + (quad >> 1) * 16;
    const uint32_t bOff  = OFF_B + (uint32_t)((quad & 1) * 8 + qr) * B_PITCH
                         + (uint32_t)(wn * 32 + (quad >> 1) * 8) * 2;

    const int nch = K >> 6;

    stage_load<NT>(sb, Ah, Al, Bw, 0, bm, bn, K, NN, tid);
    cp_commit();
    if (nch > 1) {
        stage_load<NT>(sb + STAGE_B, Ah, Al, Bw, 64, bm, bn, K, NN, tid);
        cp_commit();
    }

    for (int c = 0; c < nch; c++) {
        if (c < nch - 1) asm volatile("cp.async.wait_group 1;" ::: "memory");
        else             asm volatile("cp.async.wait_group 0;" ::: "memory");
        __syncthreads();

        const uint32_t stb = sb + (uint32_t)(c & 1) * STAGE_B;

#pragma unroll
        for (int ks = 0; ks < 4; ks++) {
            uint32_t aH[4][4], aL[4][4], bF[4][2];
#pragma unroll
            for (int mi = 0; mi < 4; mi++) {
                const uint32_t ad = stb + aOffH + (uint32_t)mi * (16 * A_PITCH) + ks * 32;
                ldsm4(aH[mi][0], aH[mi][1], aH[mi][2], aH[mi][3], ad);
                if (NT == 2)
                    ldsm4(aL[mi][0], aL[mi][1], aL[mi][2], aL[mi][3], ad + (OFF_AL - OFF_AH));
            }
#pragma unroll
            for (int bp = 0; bp < 2; bp++) {
                const uint32_t ad = stb + bOff + (uint32_t)ks * (16 * B_PITCH) + bp * 32;
                uint32_t r0, r1, r2, r3;
                ldsm4t(r0, r1, r2, r3, ad);
                bF[2 * bp][0] = r0; bF[2 * bp][1] = r1;
                bF[2 * bp + 1][0] = r2; bF[2 * bp + 1][1] = r3;
            }
#pragma unroll
            for (int mi = 0; mi < 4; mi++)
#pragma unroll
                for (int ni = 0; ni < 4; ni++) {
                    mma16816(acc[mi][ni], aH[mi], bF[ni]);
                    if (NT == 2) mma16816(acc[mi][ni], aL[mi], bF[ni]);
                }
        }
        __syncthreads();

        if (c + 2 < nch) {
            stage_load<NT>(stb, Ah, Al, Bw, (c + 2) << 6, bm, bn, K, NN, tid);
            cp_commit();
        }
    }

    // ---- epilogue ----
    const int grp = lane >> 2;
    const int qc  = (lane & 3) * 2;
#pragma unroll
    for (int mi = 0; mi < 4; mi++) {
        const int m0 = bm + wm * 64 + mi * 16 + grp;
#pragma unroll
        for (int ni = 0; ni < 4; ni++) {
            const int n = bn + wn * 32 + ni * 8 + qc;
            float2 bsv;
            if (MODE == EP_QKV) {
                const int sel = n >> 10;
                const float* bp = (sel == 0) ? bias : (sel == 1) ? bias2 : bias3;
                bsv = *(const float2*)(bp + (n & 1023));
            } else {
                bsv = *(const float2*)(bias + n);
            }
            float2 v01, v23;
            v01.x = acc[mi][ni][0] + bsv.x;
            v01.y = acc[mi][ni][1] + bsv.y;
            v23.x = acc[mi][ni][2] + bsv.x;
            v23.y = acc[mi][ni][3] + bsv.y;
#pragma unroll
            for (int half = 0; half < 2; half++) {
                const int m = m0 + half * 8;
                float2 v = half ? v23 : v01;
                if (MODE == EP_PROJ) {
                    const int b = m >> 10, s = m & 1023;
                    const int len = x_lengths[b] >> 2;
                    if (s >= len) { v.x = 0.f; v.y = 0.f; }
                    *(float2*)(out + (size_t)m * NN + n) = v;
                } else if (MODE == EP_QKV) {
                    const int sel = n >> 10;
                    const int nl = n & 1023;
                    const int b = m >> 10, s = m & 1023;
                    const int hh = nl >> 7, dh = nl & 127;
                    float* dst = (sel == 0) ? out : (sel == 1) ? (float*)outHi : (float*)outLo;
                    *(float2*)(dst + ((size_t)((b << 3) | hh) * 1024 + s) * 128 + dh) = v;
                } else if (MODE == EP_RESID) {
                    float2 o = *(float2*)(out + (size_t)m * NN + n);
                    o.x += v.x; o.y += v.y;
                    *(float2*)(out + (size_t)m * NN + n) = o;
                } else { // EP_SILU -> single fp16
                    v.x = v.x / (1.f + __expf(-v.x));
                    v.y = v.y / (1.f + __expf(-v.y));
                    const size_t o2 = ((size_t)m * NN + n) >> 1;
                    ((hf2*)outHi)[o2] = __floats2half2_rn(v.x, v.y);
                }
            }
        }
    }
}

// -------------------- LayerNorm (float4 loads) --------------------
template <bool HFOUT>
__global__ void __launch_bounds__(256)
layernorm_kernel(const float* __restrict__ in, float* __restrict__ out,
                 hf* __restrict__ outHi,
                 const float* __restrict__ scale, const float* __restrict__ bias)
{
    __shared__ float sh1[8];
    __shared__ float sh2[8];
    const int row = blockIdx.x;
    const int t = threadIdx.x;
    const int lane = t & 31, w = t >> 5;
    const float* xr = in + (size_t)row * 1024;

    float4 vals = *(const float4*)(xr + 4 * t);
    float s = vals.x + vals.y + vals.z + vals.w;
#pragma unroll
    for (int o = 16; o; o >>= 1) s += __shfl_xor_sync(0xffffffffu, s, o);
    if (lane == 0) sh1[w] = s;
    __syncthreads();
    float tot = (t < 8) ? sh1[t] : 0.f;
    if (w == 0) {
#pragma unroll
        for (int o = 16; o; o >>= 1) tot += __shfl_xor_sync(0xffffffffu, tot, o);
        if (lane == 0) sh1[0] = tot;
    }
    __syncthreads();
    const float mean = sh1[0] * (1.f / 1024.f);

    float dx = vals.x - mean, dy = vals.y - mean, dz = vals.z - mean, dw = vals.w - mean;
    float vs = dx * dx + dy * dy + dz * dz + dw * dw;
#pragma unroll
    for (int o = 16; o; o >>= 1) vs += __shfl_xor_sync(0xffffffffu, vs, o);
    if (lane == 0) sh2[w] = vs;
    __syncthreads();
    float vtot = (t < 8) ? sh2[t] : 0.f;
    if (w == 0) {
#pragma unroll
        for (int o = 16; o; o >>= 1) vtot += __shfl_xor_sync(0xffffffffu, vtot, o);
        if (lane == 0) sh2[0] = vtot;
    }
    __syncthreads();
    const float var = sh2[0] * (1.f / 1024.f);
    const float inv = rsqrtf(var + 1e-5f);

    float4 sc = *(const float4*)(scale + 4 * t);
    float4 bi = *(const float4*)(bias + 4 * t);
    float r0 = dx * inv * sc.x + bi.x;
    float r1 = dy * inv * sc.y + bi.y;
    float r2 = dz * inv * sc.z + bi.z;
    float r3 = dw * inv * sc.w + bi.w;
    if (HFOUT) {
        hf2* dst = (hf2*)(outHi + (size_t)row * 1024 + 4 * t);
        dst[0] = __floats2half2_rn(r0, r1);
        dst[1] = __floats2half2_rn(r2, r3);
    } else {
        float4 o = {r0, r1, r2, r3};
        *(float4*)(out + (size_t)row * 1024 + 4 * t) = o;
    }
}

// -------------------- RoPE table + vectorized apply --------------------
__global__ void __launch_bounds__(256)
rope_table_kernel(float* __restrict__ rc, float* __restrict__ rs)
{
    int idx = blockIdx.x * blockDim.x + threadIdx.x;
    int p = idx & 63;
    int s = idx >> 6;
    float inv_freq = expf(-(float)p * (9.210340371976184f / 64.f));
    float ang = (float)s * inv_freq;
    float sn, cs;
    sincosf(ang, &sn, &cs);
    rc[idx] = cs;
    rs[idx] = sn;
}

// one thread = 4 consecutive rope pairs (float4 granularity)
__global__ void __launch_bounds__(256)
rope_kernel(float* __restrict__ q, float* __restrict__ k,
            const float* __restrict__ rc, const float* __restrict__ rs)
{
    const int total = B_ * H_ * S_ * 16;    // pair-quads per tensor (64/4=16 per row)
    int gid = blockIdx.x * blockDim.x + threadIdx.x;
    float* ptr = (gid < total) ? q : k;
    int id = (gid < total) ? gid : gid - total;
    int p4 = id & 15;
    int s  = (id >> 4) & 1023;
    int bh = id >> 14;
    int tix = (s << 6) | (p4 << 2);
    float4 cs = *(const float4*)(rc + tix);
    float4 sn = *(const float4*)(rs + tix);
    int base = (bh * 1024 + s) * 128 + p4 * 4;
    float4 x1 = *(const float4*)(ptr + base);
    float4 x2 = *(const float4*)(ptr + base + 64);
    float4 o1, o2;
    o1.x = x1.x * cs.x - x2.x * sn.x;  o2.x = x1.x * sn.x + x2.x * cs.x;
    o1.y = x1.y * cs.y - x2.y * sn.y;  o2.y = x1.y * sn.y + x2.y * cs.y;
    o1.z = x1.z * cs.z - x2.z * sn.z;  o2.z = x1.z * sn.z + x2.z * cs.z;
    o1.w = x1.w * cs.w - x2.w * sn.w;  o2.w = x1.w * sn.w + x2.w * cs.w;
    *(float4*)(ptr + base)      = o1;
    *(float4*)(ptr + base + 64) = o2;
}

// -------------------- V mean --------------------
__global__ void __launch_bounds__(1024)
vmean_kernel(const float* __restrict__ v, float* __restrict__ vmean)
{
    __shared__ float partial[8][128];
    const int bh = blockIdx.x;
    const int d  = threadIdx.x & 127;
    const int sl = threadIdx.x >> 7;
    const float* base = v + (size_t)bh * S_ * DH_ + (size_t)sl * 128 * DH_ + d;
    float s = 0.f;
#pragma unroll 4
    for (int j = 0; j < 128; j++) s += base[j * DH_];
    partial[sl][d] = s;
    __syncthreads();
    if (sl == 0) {
        float t = 0.f;
#pragma unroll
        for (int r = 0; r < 8; r++) t += partial[r][d];
        vmean[bh * DH_ + d] = t * (1.f / (float)S_);
    }
}

// -------------------- windowed attention (fp16-hi ctx out only) -------------
__global__ void __launch_bounds__(512)
attn_kernel(const float* __restrict__ q, const float* __restrict__ k,
            const float* __restrict__ v, const float* __restrict__ vmean,
            hf* __restrict__ ctxHi, const int* __restrict__ x_lengths)
{
    const int wid  = blockIdx.x * 16 + (threadIdx.x >> 5);
    const int lane = threadIdx.x & 31;
    const int i  = wid & 1023;
    const int hh = (wid >> 10) & 7;
    const int b  = wid >> 13;

    const int len = x_lengths[b] >> 2;
    int jlo = i - (WIN_ - 1); if (jlo < 0) jlo = 0;
    int jhi = i + LFW_;       if (jhi > S_ - 1) jhi = S_ - 1;
    int jh  = (len - 1 < jhi) ? (len - 1) : jhi;

    const size_t obase = ((size_t)(b * 1024 + i)) * 1024 + hh * 128 + lane * 4;

    if (jh < jlo) {
        const float4 vm = *(const float4*)(vmean + (b * 8 + hh) * 128 + lane * 4);
        *(hf2*)(ctxHi + obase)     = __floats2half2_rn(vm.x, vm.y);
        *(hf2*)(ctxHi + obase + 2) = __floats2half2_rn(vm.z, vm.w);
        return;
    }

    const size_t head = ((size_t)(b * 8 + hh)) * 1024;
    const float4 qv = *(const float4*)(q + (head + i) * 128 + lane * 4);
    const float scale = 0.08838834764831845f;

    float sc[4] = {-1e30f, -1e30f, -1e30f, -1e30f};
#pragma unroll
    for (int slot = 0; slot < 4; slot++) {
        const int jbase = jlo + slot * 32;
        if (jbase > jh) break;
        for (int t = 0; t < 32; t++) {
            const int j = jbase + t;
            if (j > jh) break;
            float4 kv = *(const float4*)(k + (head + j) * 128 + lane * 4);
            float s = qv.x * kv.x + qv.y * kv.y + qv.z * kv.z + qv.w * kv.w;
#pragma unroll
            for (int o = 16; o; o >>= 1) s += __shfl_xor_sync(0xffffffffu, s, o);
            if (t == lane) sc[slot] = s * scale;
        }
    }

    float m = fmaxf(fmaxf(sc[0], sc[1]), fmaxf(sc[2], sc[3]));
#pragma unroll
    for (int o = 16; o; o >>= 1) m = fmaxf(m, __shfl_xor_sync(0xffffffffu, m, o));

    float p0 = __expf(sc[0] - m);
    float p1 = __expf(sc[1] - m);
    float p2 = __expf(sc[2] - m);
    float p3 = __expf(sc[3] - m);
    float l = p0 + p1 + p2 + p3;
#pragma unroll
    for (int o = 16; o; o >>= 1) l += __shfl_xor_sync(0xffffffffu, l, o);

    float4 acc = {0.f, 0.f, 0.f, 0.f};
#pragma unroll
    for (int slot = 0; slot < 4; slot++) {
        const int jbase = jlo + slot * 32;
        if (jbase > jh) break;
        const float ps = (slot == 0) ? p0 : (slot == 1) ? p1 : (slot == 2) ? p2 : p3;
        for (int t = 0; t < 32; t++) {
            const int j = jbase + t;
            if (j > jh) break;
            const float pj = __shfl_sync(0xffffffffu, ps, t);
            float4 vv = *(const float4*)(v + (head + j) * 128 + lane * 4);
            acc.x += pj * vv.x;
            acc.y += pj * vv.y;
            acc.z += pj * vv.z;
            acc.w += pj * vv.w;
        }
    }

    const float invl = 1.f / l;
    *(hf2*)(ctxHi + obase)     = __floats2half2_rn(acc.x * invl, acc.y * invl);
    *(hf2*)(ctxHi + obase + 2) = __floats2half2_rn(acc.z * invl, acc.w * invl);
}

// -------------------- launch --------------------
extern "C" void kernel_launch(void* const* d_in, const int* in_sizes, int n_in,
                              void* d_out, int out_size)
{
    const float* x     = (const float*)d_in[0];
    const int*   xlen  = (const int*)  d_in[1];
    const float* Wp    = (const float*)d_in[2];
    const float* bp    = (const float*)d_in[3];
    const float* ln1_s = (const float*)d_in[4];
    const float* ln1_b = (const float*)d_in[5];
    const float* Wq    = (const float*)d_in[6];
    const float* bq    = (const float*)d_in[7];
    const float* Wk    = (const float*)d_in[8];
    const float* bk    = (const float*)d_in[9];
    const float* Wv    = (const float*)d_in[10];
    const float* bv    = (const float*)d_in[11];
    const float* Wo    = (const float*)d_in[12];
    const float* bo    = (const float*)d_in[13];
    const float* ln2_s = (const float*)d_in[14];
    const float* ln2_b = (const float*)d_in[15];
    const float* W1    = (const float*)d_in[16];
    const float* b1    = (const float*)d_in[17];
    const float* W2    = (const float*)d_in[18];
    const float* b2    = (const float*)d_in[19];
    const float* lnf_s = (const float*)d_in[20];
    const float* lnf_b = (const float*)d_in[21];
    float* out = (float*)d_out;

    float *h, *q, *k, *v, *vmean, *rc, *rs;
    hf *xhi, *xlo, *yhi, *chi, *fhi, *w;
    cudaGetSymbolAddress((void**)&h,    g_h);
    cudaGetSymbolAddress((void**)&q,    g_q);
    cudaGetSymbolAddress((void**)&k,    g_k);
    cudaGetSymbolAddress((void**)&v,    g_v);
    cudaGetSymbolAddress((void**)&vmean,g_vmean);
    cudaGetSymbolAddress((void**)&rc,   g_rcos);
    cudaGetSymbolAddress((void**)&rs,   g_rsin);
    cudaGetSymbolAddress((void**)&xhi,  g_xhi);
    cudaGetSymbolAddress((void**)&xlo,  g_xlo);
    cudaGetSymbolAddress((void**)&yhi,  g_yhi);
    cudaGetSymbolAddress((void**)&chi,  g_chi);
    cudaGetSymbolAddress((void**)&fhi,  g_fhi);
    cudaGetSymbolAddress((void**)&w,    g_w);

    cudaFuncSetAttribute((const void*)mma_gemm<EP_PROJ, 2>,  cudaFuncAttributeMaxDynamicSharedMemorySize, GEMM_SMEM);
    cudaFuncSetAttribute((const void*)mma_gemm<EP_QKV, 1>,   cudaFuncAttributeMaxDynamicSharedMemorySize, GEMM_SMEM);
    cudaFuncSetAttribute((const void*)mma_gemm<EP_SILU, 1>,  cudaFuncAttributeMaxDynamicSharedMemorySize, GEMM_SMEM);
    cudaFuncSetAttribute((const void*)mma_gemm<EP_RESID, 1>, cudaFuncAttributeMaxDynamicSharedMemorySize, GEMM_SMEM);

    const dim3 blk(256);

    rope_table_kernel<<<256, blk>>>(rc, rs);
    conv_split<<<2048, blk>>>(x, xhi, xlo);                         // 2,097,152 f4
    conv_w<<<512, blk>>>(Wp, w + WP_OFF);                           // 524,288 f4
    conv_w_qkv<<<1024, blk>>>(Wq, w + QKV_OFF, 0);                  // 1,048,576 f4
    conv_w_qkv<<<1024, blk>>>(Wk, w + QKV_OFF, 1024);
    conv_w_qkv<<<1024, blk>>>(Wv, w + QKV_OFF, 2048);
    conv_w<<<1024, blk>>>(Wo, w + WO_OFF);                          // 1,048,576 f4
    conv_w<<<4096, blk>>>(W1, w + W1_OFF);                          // 4,194,304 f4
    conv_w<<<4096, blk>>>(W2, w + W2_OFF);

    // projector (2-term)
    mma_gemm<EP_PROJ, 2><<<dim3(8, 32), blk, GEMM_SMEM>>>(
        2048, 1024, xhi, xlo, w + WP_OFF,
        bp, nullptr, nullptr, h, nullptr, nullptr, xlen);

    for (int l = 0; l < L_; l++) {
        const size_t oD  = (size_t)l * D_;
        const size_t oF  = (size_t)l * F_;
        const uint32_t oQKV = QKV_OFF + (uint32_t)l * 3145728u;
        const uint32_t oWO  = WO_OFF  + (uint32_t)l * 1048576u;
        const uint32_t oW1  = W1_OFF  + (uint32_t)l * 4194304u;
        const uint32_t oW2  = W2_OFF  + (uint32_t)l * 4194304u;

        layernorm_kernel<true><<<NTOK, blk>>>(h, nullptr, yhi, ln1_s + oD, ln1_b + oD);

        mma_gemm<EP_QKV, 1><<<dim3(24, 32), blk, GEMM_SMEM>>>(
            1024, 3072, yhi, nullptr, w + oQKV,
            bq + oD, bk + oD, bv + oD, q, (hf*)k, (hf*)v, nullptr);

        rope_kernel<<<4096, blk>>>(q, k, rc, rs);   // 2 * 524288 pair-quads
        vmean_kernel<<<B_ * H_, 1024>>>(v, vmean);
        attn_kernel<<<(B_ * H_ * S_) / 16, 512>>>(q, k, v, vmean, chi, xlen);

        // WO: single-term ctx
        mma_gemm<EP_RESID, 1><<<dim3(8, 32), blk, GEMM_SMEM>>>(
            1024, 1024, chi, nullptr, w + oWO,
            bo + oD, nullptr, nullptr, h, nullptr, nullptr, nullptr);

        layernorm_kernel<true><<<NTOK, blk>>>(h, nullptr, yhi, ln2_s + oD, ln2_b + oD);

        mma_gemm<EP_SILU, 1><<<dim3(32, 32), blk, GEMM_SMEM>>>(
            1024, 4096, yhi, nullptr, w + oW1,
            b1 + oF, nullptr, nullptr, nullptr, fhi, nullptr, nullptr);

        mma_gemm<EP_RESID, 1><<<dim3(8, 32), blk, GEMM_SMEM>>>(
            4096, 1024, fhi, nullptr, w + oW2,
            b2 + oD, nullptr, nullptr, h, nullptr, nullptr, nullptr);
    }

    layernorm_kernel<false><<<NTOK, blk>>>(h, out, nullptr, lnf_s, lnf_b);
}

// round 11
// speedup vs baseline: 5.4616x; 1.0515x over previous
#include <cuda_runtime.h>
#include <cuda_fp16.h>
#include <math.h>
#include <stdint.h>

// Problem constants
#define B_   4
#define S_   1024
#define D_   1024
#define F_   4096
#define H_   8
#define DH_  128
#define L_   4
#define NTOK (B_ * S_)          // 4096
#define WIN_ 100
#define LFW_ 20

typedef __half  hf;
typedef __half2 hf2;

// -------------------- scratch --------------------
__device__ float g_h [NTOK * D_];
__device__ float g_q [NTOK * D_];
__device__ float g_k [NTOK * D_];
__device__ float g_v [NTOK * D_];
__device__ float g_vmean[B_ * H_ * DH_];
__device__ float g_rcos[S_ * 64];
__device__ float g_rsin[S_ * 64];

// fp16 activation buffers
__device__ hf g_xhi[NTOK * 2048], g_xlo[NTOK * 2048];
__device__ hf g_yhi[NTOK * D_];
__device__ hf g_chi[NTOK * D_];
__device__ hf g_fhi[NTOK * F_];

// converted weights (single fp16), offsets in elements
#define WP_OFF   0u
#define QKV_OFF  2097152u
#define WO_OFF   (QKV_OFF + 4u * 3145728u)
#define W1_OFF   (WO_OFF + 4u * 1048576u)
#define W2_OFF   (W1_OFF + 4u * 4194304u)
#define WTOT     (W2_OFF + 4u * 4194304u)
__device__ hf g_w[WTOT];

// ==================== helpers ====================
__device__ __forceinline__ uint32_t smem_u32(const void* p) {
    uint32_t a;
    asm("{ .reg .u64 t; cvta.to.shared.u64 t, %1; cvt.u32.u64 %0, t; }" : "=r"(a) : "l"(p));
    return a;
}
__device__ __forceinline__ void cp16(uint32_t saddr, const void* gaddr) {
    asm volatile("cp.async.cg.shared.global [%0], [%1], 16;" :: "r"(saddr), "l"(gaddr));
}
__device__ __forceinline__ void cp_commit() {
    asm volatile("cp.async.commit_group;" ::: "memory");
}
__device__ __forceinline__ void ldsm4(uint32_t& r0, uint32_t& r1, uint32_t& r2, uint32_t& r3,
                                      uint32_t addr) {
    asm volatile("ldmatrix.sync.aligned.m8n8.x4.shared.b16 {%0,%1,%2,%3}, [%4];"
                 : "=r"(r0), "=r"(r1), "=r"(r2), "=r"(r3) : "r"(addr));
}
__device__ __forceinline__ void ldsm4t(uint32_t& r0, uint32_t& r1, uint32_t& r2, uint32_t& r3,
                                       uint32_t addr) {
    asm volatile("ldmatrix.sync.aligned.m8n8.x4.trans.shared.b16 {%0,%1,%2,%3}, [%4];"
                 : "=r"(r0), "=r"(r1), "=r"(r2), "=r"(r3) : "r"(addr));
}
__device__ __forceinline__ void mma16816(float* d, const uint32_t* a, const uint32_t* b) {
    asm volatile(
        "mma.sync.aligned.m16n8k16.row.col.f32.f16.f16.f32 "
        "{%0,%1,%2,%3}, {%4,%5,%6,%7}, {%8,%9}, {%0,%1,%2,%3};"
        : "+f"(d[0]), "+f"(d[1]), "+f"(d[2]), "+f"(d[3])
        : "r"(a[0]), "r"(a[1]), "r"(a[2]), "r"(a[3]), "r"(b[0]), "r"(b[1]));
}
__device__ __forceinline__ void split2h(float x, float y, hf2& h, hf2& l) {
    h = __floats2half2_rn(x, y);
    float2 hfv = __half22float2(h);
    l = __floats2half2_rn(x - hfv.x, y - hfv.y);
}

// ==================== converters ====================
__global__ void __launch_bounds__(256)
conv_split(const float* __restrict__ in, hf* __restrict__ hi, hf* __restrict__ lo)
{
#pragma unroll
    for (int r = 0; r < 4; r++) {
        int i = blockIdx.x * 1024 + r * 256 + threadIdx.x;
        float4 v = ((const float4*)in)[i];
        hf2 h0, l0, h1, l1;
        split2h(v.x, v.y, h0, l0);
        split2h(v.z, v.w, h1, l1);
        ((hf2*)hi)[2 * i] = h0; ((hf2*)hi)[2 * i + 1] = h1;
        ((hf2*)lo)[2 * i] = l0; ((hf2*)lo)[2 * i + 1] = l1;
    }
}
__device__ __forceinline__ void conv_plain_range(const float* in, hf* w, int blk0, int blk)
{
#pragma unroll
    for (int r = 0; r < 4; r++) {
        int i = (blk - blk0) * 1024 + r * 256 + threadIdx.x;
        float4 v = ((const float4*)in)[i];
        ((hf2*)w)[2 * i]     = __floats2half2_rn(v.x, v.y);
        ((hf2*)w)[2 * i + 1] = __floats2half2_rn(v.z, v.w);
    }
}
__global__ void __launch_bounds__(256)
conv_w(const float* __restrict__ in, hf* __restrict__ w)
{
    conv_plain_range(in, w, 0, blockIdx.x);
}
// merged Wo + W1 + W2 conversion: grid 1024 + 4096 + 4096 = 9216
__global__ void __launch_bounds__(256)
conv_w3(const float* __restrict__ Wo, const float* __restrict__ W1,
        const float* __restrict__ W2, hf* __restrict__ w)
{
    int blk = blockIdx.x;
    if (blk < 1024)       conv_plain_range(Wo, w + WO_OFF, 0,    blk);
    else if (blk < 5120)  conv_plain_range(W1, w + W1_OFF, 1024, blk);
    else                  conv_plain_range(W2, w + W2_OFF, 5120, blk);
}
// merged QKV interleave: grid 3072
__global__ void __launch_bounds__(256)
conv_w_qkv(const float* __restrict__ Wq, const float* __restrict__ Wk,
           const float* __restrict__ Wv, hf* __restrict__ w)
{
    int blk = blockIdx.x;
    const float* in = (blk < 1024) ? Wq : (blk < 2048) ? Wk : Wv;
    int coff = (blk < 1024) ? 0 : (blk < 2048) ? 1024 : 2048;
    int blk0 = (blk < 1024) ? 0 : (blk < 2048) ? 1024 : 2048;
#pragma unroll
    for (int r = 0; r < 4; r++) {
        int i = (blk - blk0) * 1024 + r * 256 + threadIdx.x;
        int row = i >> 8, c4 = i & 255;
        float4 v = ((const float4*)in)[i];
        size_t o2 = ((size_t)row * 3072 + coff + c4 * 4) >> 1;
        ((hf2*)(w + QKV_OFF))[o2]     = __floats2half2_rn(v.x, v.y);
        ((hf2*)(w + QKV_OFF))[o2 + 1] = __floats2half2_rn(v.z, v.w);
    }
}

// ==================== pipelined fp16(-split) GEMM ====================
#define EP_PROJ  1
#define EP_QKV   2
#define EP_RESID 3
#define EP_SILU  4

#define A_PITCH 144
#define B_PITCH 272
#define OFF_AH 0
#define OFF_AL 18432
#define OFF_B  36864
#define STAGE_B 54272
#define GEMM_SMEM (2 * STAGE_B)   // 108544

template <int NT>
__device__ __forceinline__ void stage_load(
    uint32_t stb, const hf* Ah, const hf* Al, const hf* Bw,
    int k0, int bm, int bn, int K, int NN, int tid)
{
#pragma unroll
    for (int t = 0; t < 4; t++) {
        const int idx = t * 256 + tid;
        const int row = idx >> 3, seg = idx & 7;
        const size_t go = (size_t)(bm + row) * K + k0 + seg * 8;
        const uint32_t so = stb + (uint32_t)row * A_PITCH + seg * 16;
        cp16(so + OFF_AH, Ah + go);
        if (NT == 2) cp16(so + OFF_AL, Al + go);
    }
#pragma unroll
    for (int t = 0; t < 4; t++) {
        const int idx = t * 256 + tid;
        const int row = idx >> 4, seg = idx & 15;
        const size_t go = (size_t)(k0 + row) * NN + bn + seg * 8;
        const uint32_t so = stb + (uint32_t)row * B_PITCH + seg * 16;
        cp16(so + OFF_B, Bw + go);
    }
}

template <int MODE, int NT>
__global__ void __launch_bounds__(256, 2)
mma_gemm(int K, int NN,
         const hf* __restrict__ Ah, const hf* __restrict__ Al,
         const hf* __restrict__ Bw,
         const float* __restrict__ bias, const float* __restrict__ bias2,
         const float* __restrict__ bias3,
         float* __restrict__ out, hf* __restrict__ outHi, hf* __restrict__ outLo,
         const int* __restrict__ x_lengths)
{
    extern __shared__ char sm[];
    const uint32_t sb = smem_u32(sm);
    const int tid  = threadIdx.x;
    const int wid  = tid >> 5;
    const int lane = tid & 31;
    const int bn = blockIdx.x * 128;
    const int bm = blockIdx.y * 128;
    const int wm = wid & 1;
    const int wn = wid >> 1;

    float acc[4][4][4];
#pragma unroll
    for (int i = 0; i < 4; i++)
#pragma unroll
        for (int j = 0; j < 4; j++)
#pragma unroll
            for (int r = 0; r < 4; r++) acc[i][j][r] = 0.f;

    const int quad = lane >> 3;
    const int qr   = lane & 7;
    const uint32_t aOffH = OFF_AH + (uint32_t)(wm * 64 + (quad & 1) * 8 + qr) * A_PITCH + (quad >> 1) * 16;
    const uint32_t bOff  = OFF_B + (uint32_t)((quad & 1) * 8 + qr) * B_PITCH
                         + (uint32_t)(wn * 32 + (quad >> 1) * 8) * 2;

    const int nch = K >> 6;

    stage_load<NT>(sb, Ah, Al, Bw, 0, bm, bn, K, NN, tid);
    cp_commit();
    if (nch > 1) {
        stage_load<NT>(sb + STAGE_B, Ah, Al, Bw, 64, bm, bn, K, NN, tid);
        cp_commit();
    }

    for (int c = 0; c < nch; c++) {
        if (c < nch - 1) asm volatile("cp.async.wait_group 1;" ::: "memory");
        else             asm volatile("cp.async.wait_group 0;" ::: "memory");
        __syncthreads();

        const uint32_t stb = sb + (uint32_t)(c & 1) * STAGE_B;

#pragma unroll
        for (int ks = 0; ks < 4; ks++) {
            uint32_t aH[4][4], aL[4][4], bF[4][2];
#pragma unroll
            for (int mi = 0; mi < 4; mi++) {
                const uint32_t ad = stb + aOffH + (uint32_t)mi * (16 * A_PITCH) + ks * 32;
                ldsm4(aH[mi][0], aH[mi][1], aH[mi][2], aH[mi][3], ad);
                if (NT == 2)
                    ldsm4(aL[mi][0], aL[mi][1], aL[mi][2], aL[mi][3], ad + (OFF_AL - OFF_AH));
            }
#pragma unroll
            for (int bp = 0; bp < 2; bp++) {
                const uint32_t ad = stb + bOff + (uint32_t)ks * (16 * B_PITCH) + bp * 32;
                uint32_t r0, r1, r2, r3;
                ldsm4t(r0, r1, r2, r3, ad);
                bF[2 * bp][0] = r0; bF[2 * bp][1] = r1;
                bF[2 * bp + 1][0] = r2; bF[2 * bp + 1][1] = r3;
            }
#pragma unroll
            for (int mi = 0; mi < 4; mi++)
#pragma unroll
                for (int ni = 0; ni < 4; ni++) {
                    mma16816(acc[mi][ni], aH[mi], bF[ni]);
                    if (NT == 2) mma16816(acc[mi][ni], aL[mi], bF[ni]);
                }
        }
        __syncthreads();

        if (c + 2 < nch) {
            stage_load<NT>(stb, Ah, Al, Bw, (c + 2) << 6, bm, bn, K, NN, tid);
            cp_commit();
        }
    }

    // ---- epilogue ----
    const int grp = lane >> 2;
    const int qc  = (lane & 3) * 2;
#pragma unroll
    for (int mi = 0; mi < 4; mi++) {
        const int m0 = bm + wm * 64 + mi * 16 + grp;
#pragma unroll
        for (int ni = 0; ni < 4; ni++) {
            const int n = bn + wn * 32 + ni * 8 + qc;
            float2 bsv;
            if (MODE == EP_QKV) {
                const int sel = n >> 10;
                const float* bp = (sel == 0) ? bias : (sel == 1) ? bias2 : bias3;
                bsv = *(const float2*)(bp + (n & 1023));
            } else {
                bsv = *(const float2*)(bias + n);
            }
            float2 v01, v23;
            v01.x = acc[mi][ni][0] + bsv.x;
            v01.y = acc[mi][ni][1] + bsv.y;
            v23.x = acc[mi][ni][2] + bsv.x;
            v23.y = acc[mi][ni][3] + bsv.y;
#pragma unroll
            for (int half = 0; half < 2; half++) {
                const int m = m0 + half * 8;
                float2 v = half ? v23 : v01;
                if (MODE == EP_PROJ) {
                    const int b = m >> 10, s = m & 1023;
                    const int len = x_lengths[b] >> 2;
                    if (s >= len) { v.x = 0.f; v.y = 0.f; }
                    *(float2*)(out + (size_t)m * NN + n) = v;
                } else if (MODE == EP_QKV) {
                    const int sel = n >> 10;
                    const int nl = n & 1023;
                    const int b = m >> 10, s = m & 1023;
                    const int hh = nl >> 7, dh = nl & 127;
                    float* dst = (sel == 0) ? out : (sel == 1) ? (float*)outHi : (float*)outLo;
                    *(float2*)(dst + ((size_t)((b << 3) | hh) * 1024 + s) * 128 + dh) = v;
                } else if (MODE == EP_RESID) {
                    float2 o = *(float2*)(out + (size_t)m * NN + n);
                    o.x += v.x; o.y += v.y;
                    *(float2*)(out + (size_t)m * NN + n) = o;
                } else { // EP_SILU -> single fp16
                    v.x = v.x / (1.f + __expf(-v.x));
                    v.y = v.y / (1.f + __expf(-v.y));
                    const size_t o2 = ((size_t)m * NN + n) >> 1;
                    ((hf2*)outHi)[o2] = __floats2half2_rn(v.x, v.y);
                }
            }
        }
    }
}

// -------------------- LayerNorm (float4 loads) --------------------
template <bool HFOUT>
__global__ void __launch_bounds__(256)
layernorm_kernel(const float* __restrict__ in, float* __restrict__ out,
                 hf* __restrict__ outHi,
                 const float* __restrict__ scale, const float* __restrict__ bias)
{
    __shared__ float sh1[8];
    __shared__ float sh2[8];
    const int row = blockIdx.x;
    const int t = threadIdx.x;
    const int lane = t & 31, w = t >> 5;
    const float* xr = in + (size_t)row * 1024;

    float4 vals = *(const float4*)(xr + 4 * t);
    float s = vals.x + vals.y + vals.z + vals.w;
#pragma unroll
    for (int o = 16; o; o >>= 1) s += __shfl_xor_sync(0xffffffffu, s, o);
    if (lane == 0) sh1[w] = s;
    __syncthreads();
    float tot = (t < 8) ? sh1[t] : 0.f;
    if (w == 0) {
#pragma unroll
        for (int o = 16; o; o >>= 1) tot += __shfl_xor_sync(0xffffffffu, tot, o);
        if (lane == 0) sh1[0] = tot;
    }
    __syncthreads();
    const float mean = sh1[0] * (1.f / 1024.f);

    float dx = vals.x - mean, dy = vals.y - mean, dz = vals.z - mean, dw = vals.w - mean;
    float vs = dx * dx + dy * dy + dz * dz + dw * dw;
#pragma unroll
    for (int o = 16; o; o >>= 1) vs += __shfl_xor_sync(0xffffffffu, vs, o);
    if (lane == 0) sh2[w] = vs;
    __syncthreads();
    float vtot = (t < 8) ? sh2[t] : 0.f;
    if (w == 0) {
#pragma unroll
        for (int o = 16; o; o >>= 1) vtot += __shfl_xor_sync(0xffffffffu, vtot, o);
        if (lane == 0) sh2[0] = vtot;
    }
    __syncthreads();
    const float var = sh2[0] * (1.f / 1024.f);
    const float inv = rsqrtf(var + 1e-5f);

    float4 sc = *(const float4*)(scale + 4 * t);
    float4 bi = *(const float4*)(bias + 4 * t);
    float r0 = dx * inv * sc.x + bi.x;
    float r1 = dy * inv * sc.y + bi.y;
    float r2 = dz * inv * sc.z + bi.z;
    float r3 = dw * inv * sc.w + bi.w;
    if (HFOUT) {
        hf2* dst = (hf2*)(outHi + (size_t)row * 1024 + 4 * t);
        dst[0] = __floats2half2_rn(r0, r1);
        dst[1] = __floats2half2_rn(r2, r3);
    } else {
        float4 o = {r0, r1, r2, r3};
        *(float4*)(out + (size_t)row * 1024 + 4 * t) = o;
    }
}

// -------------------- RoPE table + vectorized apply --------------------
__global__ void __launch_bounds__(256)
rope_table_kernel(float* __restrict__ rc, float* __restrict__ rs)
{
    int idx = blockIdx.x * blockDim.x + threadIdx.x;
    int p = idx & 63;
    int s = idx >> 6;
    float inv_freq = expf(-(float)p * (9.210340371976184f / 64.f));
    float ang = (float)s * inv_freq;
    float sn, cs;
    sincosf(ang, &sn, &cs);
    rc[idx] = cs;
    rs[idx] = sn;
}

__global__ void __launch_bounds__(256)
rope_kernel(float* __restrict__ q, float* __restrict__ k,
            const float* __restrict__ rc, const float* __restrict__ rs)
{
    const int total = B_ * H_ * S_ * 16;
    int gid = blockIdx.x * blockDim.x + threadIdx.x;
    float* ptr = (gid < total) ? q : k;
    int id = (gid < total) ? gid : gid - total;
    int p4 = id & 15;
    int s  = (id >> 4) & 1023;
    int bh = id >> 14;
    int tix = (s << 6) | (p4 << 2);
    float4 cs = *(const float4*)(rc + tix);
    float4 sn = *(const float4*)(rs + tix);
    int base = (bh * 1024 + s) * 128 + p4 * 4;
    float4 x1 = *(const float4*)(ptr + base);
    float4 x2 = *(const float4*)(ptr + base + 64);
    float4 o1, o2;
    o1.x = x1.x * cs.x - x2.x * sn.x;  o2.x = x1.x * sn.x + x2.x * cs.x;
    o1.y = x1.y * cs.y - x2.y * sn.y;  o2.y = x1.y * sn.y + x2.y * cs.y;
    o1.z = x1.z * cs.z - x2.z * sn.z;  o2.z = x1.z * sn.z + x2.z * cs.z;
    o1.w = x1.w * cs.w - x2.w * sn.w;  o2.w = x1.w * sn.w + x2.w * cs.w;
    *(float4*)(ptr + base)      = o1;
    *(float4*)(ptr + base + 64) = o2;
}

// -------------------- V mean --------------------
__global__ void __launch_bounds__(1024)
vmean_kernel(const float* __restrict__ v, float* __restrict__ vmean)
{
    __shared__ float partial[8][128];
    const int bh = blockIdx.x;
    const int d  = threadIdx.x & 127;
    const int sl = threadIdx.x >> 7;
    const float* base = v + (size_t)bh * S_ * DH_ + (size_t)sl * 128 * DH_ + d;
    float s = 0.f;
#pragma unroll 4
    for (int j = 0; j < 128; j++) s += base[j * DH_];
    partial[sl][d] = s;
    __syncthreads();
    if (sl == 0) {
        float t = 0.f;
#pragma unroll
        for (int r = 0; r < 8; r++) t += partial[r][d];
        vmean[bh * DH_ + d] = t * (1.f / (float)S_);
    }
}

// -------------------- windowed attention: 4 queries per warp ----------------
__global__ void __launch_bounds__(256)
attn_kernel(const float* __restrict__ q, const float* __restrict__ k,
            const float* __restrict__ v, const float* __restrict__ vmean,
            hf* __restrict__ ctxHi, const int* __restrict__ x_lengths)
{
    const int g    = blockIdx.x * 8 + (threadIdx.x >> 5);   // 0..8191
    const int lane = threadIdx.x & 31;
    const int i0 = (g & 255) * 4;
    const int hh = (g >> 8) & 7;
    const int b  = g >> 11;

    const int len = x_lengths[b] >> 2;
    const size_t head = ((size_t)(b * 8 + hh)) * 1024;
    const float scale = 0.08838834764831845f;

    int jloq[4], jhq[4];
    bool msk[4];
    int lo = 0x7fffffff, hi = -1;
    bool anyLive = false, anyMasked = false;
#pragma unroll
    for (int qq = 0; qq < 4; qq++) {
        const int i = i0 + qq;
        int jl = i - (WIN_ - 1); if (jl < 0) jl = 0;
        int jh_ = i + LFW_;      if (jh_ > S_ - 1) jh_ = S_ - 1;
        if (len - 1 < jh_) jh_ = len - 1;
        jloq[qq] = jl; jhq[qq] = jh_;
        msk[qq] = (jh_ < jl);
        if (msk[qq]) anyMasked = true;
        else { anyLive = true; if (jl < lo) lo = jl; if (jh_ > hi) hi = jh_; }
    }

    float4 vmv = {0.f, 0.f, 0.f, 0.f};
    if (anyMasked)
        vmv = *(const float4*)(vmean + (b * 8 + hh) * 128 + lane * 4);

    if (!anyLive) {
#pragma unroll
        for (int qq = 0; qq < 4; qq++) {
            const size_t ob = ((size_t)(b * 1024 + i0 + qq)) * 1024 + hh * 128 + lane * 4;
            *(hf2*)(ctxHi + ob)     = __floats2half2_rn(vmv.x, vmv.y);
            *(hf2*)(ctxHi + ob + 2) = __floats2half2_rn(vmv.z, vmv.w);
        }
        return;
    }

    float4 qv[4];
#pragma unroll
    for (int qq = 0; qq < 4; qq++)
        qv[qq] = *(const float4*)(q + (head + i0 + qq) * 128 + lane * 4);

    // ---- phase 1: scores for union window, 4 queries at once ----
    float sc[4][4];
#pragma unroll
    for (int qq = 0; qq < 4; qq++)
#pragma unroll
        for (int s = 0; s < 4; s++) sc[qq][s] = -1e30f;

#pragma unroll
    for (int jb = 0; jb < 4; jb++) {
        const int jbase = lo + jb * 32;
        if (jbase > hi) break;
        for (int t = 0; t < 32; t++) {
            const int j = jbase + t;
            if (j > hi) break;
            float4 kv = *(const float4*)(k + (head + j) * 128 + lane * 4);
            float s0 = qv[0].x * kv.x + qv[0].y * kv.y + qv[0].z * kv.z + qv[0].w * kv.w;
            float s1 = qv[1].x * kv.x + qv[1].y * kv.y + qv[1].z * kv.z + qv[1].w * kv.w;
            float s2 = qv[2].x * kv.x + qv[2].y * kv.y + qv[2].z * kv.z + qv[2].w * kv.w;
            float s3 = qv[3].x * kv.x + qv[3].y * kv.y + qv[3].z * kv.z + qv[3].w * kv.w;
#pragma unroll
            for (int o = 16; o; o >>= 1) {
                s0 += __shfl_xor_sync(0xffffffffu, s0, o);
                s1 += __shfl_xor_sync(0xffffffffu, s1, o);
                s2 += __shfl_xor_sync(0xffffffffu, s2, o);
                s3 += __shfl_xor_sync(0xffffffffu, s3, o);
            }
            if (t == lane) {
                sc[0][jb] = s0 * scale;
                sc[1][jb] = s1 * scale;
                sc[2][jb] = s2 * scale;
                sc[3][jb] = s3 * scale;
            }
        }
    }

    // ---- per-query softmax weights ----
    float p[4][4], invl[4];
#pragma unroll
    for (int qq = 0; qq < 4; qq++) {
        if (msk[qq]) { invl[qq] = 0.f; continue; }
        float m = -1e30f;
#pragma unroll
        for (int s = 0; s < 4; s++) {
            const int j = lo + s * 32 + lane;
            const bool ok = (j >= jloq[qq]) && (j <= jhq[qq]);
            const float val = ok ? sc[qq][s] : -1e30f;
            sc[qq][s] = val;
            m = fmaxf(m, val);
        }
#pragma unroll
        for (int o = 16; o; o >>= 1) m = fmaxf(m, __shfl_xor_sync(0xffffffffu, m, o));
        float l = 0.f;
#pragma unroll
        for (int s = 0; s < 4; s++) {
            const float pe = (sc[qq][s] > -1e29f) ? __expf(sc[qq][s] - m) : 0.f;
            p[qq][s] = pe;
            l += pe;
        }
#pragma unroll
        for (int o = 16; o; o >>= 1) l += __shfl_xor_sync(0xffffffffu, l, o);
        invl[qq] = 1.f / l;
    }

    // ---- phase 2: P @ V ----
    float4 acc[4];
#pragma unroll
    for (int qq = 0; qq < 4; qq++) acc[qq] = make_float4(0.f, 0.f, 0.f, 0.f);

#pragma unroll
    for (int jb = 0; jb < 4; jb++) {
        const int jbase = lo + jb * 32;
        if (jbase > hi) break;
        for (int t = 0; t < 32; t++) {
            const int j = jbase + t;
            if (j > hi) break;
            float4 vv = *(const float4*)(v + (head + j) * 128 + lane * 4);
            const float p0 = __shfl_sync(0xffffffffu, p[0][jb], t);
            const float p1 = __shfl_sync(0xffffffffu, p[1][jb], t);
            const float p2 = __shfl_sync(0xffffffffu, p[2][jb], t);
            const float p3 = __shfl_sync(0xffffffffu, p[3][jb], t);
            acc[0].x += p0 * vv.x; acc[0].y += p0 * vv.y; acc[0].z += p0 * vv.z; acc[0].w += p0 * vv.w;
            acc[1].x += p1 * vv.x; acc[1].y += p1 * vv.y; acc[1].z += p1 * vv.z; acc[1].w += p1 * vv.w;
            acc[2].x += p2 * vv.x; acc[2].y += p2 * vv.y; acc[2].z += p2 * vv.z; acc[2].w += p2 * vv.w;
            acc[3].x += p3 * vv.x; acc[3].y += p3 * vv.y; acc[3].z += p3 * vv.z; acc[3].w += p3 * vv.w;
        }
    }

    // ---- store ----
#pragma unroll
    for (int qq = 0; qq < 4; qq++) {
        const size_t ob = ((size_t)(b * 1024 + i0 + qq)) * 1024 + hh * 128 + lane * 4;
        float4 r;
        if (msk[qq]) r = vmv;
        else {
            const float il = invl[qq];
            r.x = acc[qq].x * il; r.y = acc[qq].y * il;
            r.z = acc[qq].z * il; r.w = acc[qq].w * il;
        }
        *(hf2*)(ctxHi + ob)     = __floats2half2_rn(r.x, r.y);
        *(hf2*)(ctxHi + ob + 2) = __floats2half2_rn(r.z, r.w);
    }
}

// -------------------- launch --------------------
extern "C" void kernel_launch(void* const* d_in, const int* in_sizes, int n_in,
                              void* d_out, int out_size)
{
    const float* x     = (const float*)d_in[0];
    const int*   xlen  = (const int*)  d_in[1];
    const float* Wp    = (const float*)d_in[2];
    const float* bp    = (const float*)d_in[3];
    const float* ln1_s = (const float*)d_in[4];
    const float* ln1_b = (const float*)d_in[5];
    const float* Wq    = (const float*)d_in[6];
    const float* bq    = (const float*)d_in[7];
    const float* Wk    = (const float*)d_in[8];
    const float* bk    = (const float*)d_in[9];
    const float* Wv    = (const float*)d_in[10];
    const float* bv    = (const float*)d_in[11];
    const float* Wo    = (const float*)d_in[12];
    const float* bo    = (const float*)d_in[13];
    const float* ln2_s = (const float*)d_in[14];
    const float* ln2_b = (const float*)d_in[15];
    const float* W1    = (const float*)d_in[16];
    const float* b1    = (const float*)d_in[17];
    const float* W2    = (const float*)d_in[18];
    const float* b2    = (const float*)d_in[19];
    const float* lnf_s = (const float*)d_in[20];
    const float* lnf_b = (const float*)d_in[21];
    float* out = (float*)d_out;

    float *h, *q, *k, *v, *vmean, *rc, *rs;
    hf *xhi, *xlo, *yhi, *chi, *fhi, *w;
    cudaGetSymbolAddress((void**)&h,    g_h);
    cudaGetSymbolAddress((void**)&q,    g_q);
    cudaGetSymbolAddress((void**)&k,    g_k);
    cudaGetSymbolAddress((void**)&v,    g_v);
    cudaGetSymbolAddress((void**)&vmean,g_vmean);
    cudaGetSymbolAddress((void**)&rc,   g_rcos);
    cudaGetSymbolAddress((void**)&rs,   g_rsin);
    cudaGetSymbolAddress((void**)&xhi,  g_xhi);
    cudaGetSymbolAddress((void**)&xlo,  g_xlo);
    cudaGetSymbolAddress((void**)&yhi,  g_yhi);
    cudaGetSymbolAddress((void**)&chi,  g_chi);
    cudaGetSymbolAddress((void**)&fhi,  g_fhi);
    cudaGetSymbolAddress((void**)&w,    g_w);

    cudaFuncSetAttribute((const void*)mma_gemm<EP_PROJ, 2>,  cudaFuncAttributeMaxDynamicSharedMemorySize, GEMM_SMEM);
    cudaFuncSetAttribute((const void*)mma_gemm<EP_QKV, 1>,   cudaFuncAttributeMaxDynamicSharedMemorySize, GEMM_SMEM);
    cudaFuncSetAttribute((const void*)mma_gemm<EP_SILU, 1>,  cudaFuncAttributeMaxDynamicSharedMemorySize, GEMM_SMEM);
    cudaFuncSetAttribute((const void*)mma_gemm<EP_RESID, 1>, cudaFuncAttributeMaxDynamicSharedMemorySize, GEMM_SMEM);

    const dim3 blk(256);

    // launch order chosen so the projector GEMM is the 6th launch (ncu -s 5 -c 1)
    conv_split<<<2048, blk>>>(x, xhi, xlo);              // 1
    conv_w<<<512, blk>>>(Wp, w + WP_OFF);                // 2
    rope_table_kernel<<<256, blk>>>(rc, rs);             // 3
    conv_w_qkv<<<3072, blk>>>(Wq, Wk, Wv, w);            // 4
    conv_w3<<<9216, blk>>>(Wo, W1, W2, w);               // 5

    // 6: projector (2-term)
    mma_gemm<EP_PROJ, 2><<<dim3(8, 32), blk, GEMM_SMEM>>>(
        2048, 1024, xhi, xlo, w + WP_OFF,
        bp, nullptr, nullptr, h, nullptr, nullptr, xlen);

    for (int l = 0; l < L_; l++) {
        const size_t oD  = (size_t)l * D_;
        const size_t oF  = (size_t)l * F_;
        const uint32_t oQKV = QKV_OFF + (uint32_t)l * 3145728u;
        const uint32_t oWO  = WO_OFF  + (uint32_t)l * 1048576u;
        const uint32_t oW1  = W1_OFF  + (uint32_t)l * 4194304u;
        const uint32_t oW2  = W2_OFF  + (uint32_t)l * 4194304u;

        layernorm_kernel<true><<<NTOK, blk>>>(h, nullptr, yhi, ln1_s + oD, ln1_b + oD);

        mma_gemm<EP_QKV, 1><<<dim3(24, 32), blk, GEMM_SMEM>>>(
            1024, 3072, yhi, nullptr, w + oQKV,
            bq + oD, bk + oD, bv + oD, q, (hf*)k, (hf*)v, nullptr);

        rope_kernel<<<4096, blk>>>(q, k, rc, rs);
        vmean_kernel<<<B_ * H_, 1024>>>(v, vmean);
        attn_kernel<<<(B_ * H_ * S_) / 32, 256>>>(q, k, v, vmean, chi, xlen);

        mma_gemm<EP_RESID, 1><<<dim3(8, 32), blk, GEMM_SMEM>>>(
            1024, 1024, chi, nullptr, w + oWO,
            bo + oD, nullptr, nullptr, h, nullptr, nullptr, nullptr);

        layernorm_kernel<true><<<NTOK, blk>>>(h, nullptr, yhi, ln2_s + oD, ln2_b + oD);

        mma_gemm<EP_SILU, 1><<<dim3(32, 32), blk, GEMM_SMEM>>>(
            1024, 4096, yhi, nullptr, w + oW1,
            b1 + oF, nullptr, nullptr, nullptr, fhi, nullptr, nullptr);

        mma_gemm<EP_RESID, 1><<<dim3(8, 32), blk, GEMM_SMEM>>>(
            4096, 1024, fhi, nullptr, w + oW2,
            b2 + oD, nullptr, nullptr, h, nullptr, nullptr, nullptr);
    }

    layernorm_kernel<false><<<NTOK, blk>>>(h, out, nullptr, lnf_s, lnf_b);
}

// round 12
// speedup vs baseline: 5.8246x; 1.0665x over previous
#include <cuda_runtime.h>
#include <cuda_fp16.h>
#include <math.h>
#include <stdint.h>

// Problem constants
#define B_   4
#define S_   1024
#define D_   1024
#define F_   4096
#define H_   8
#define DH_  128
#define L_   4
#define NTOK (B_ * S_)          // 4096
#define WIN_ 100
#define LFW_ 20

typedef __half  hf;
typedef __half2 hf2;

// -------------------- scratch --------------------
__device__ float g_h [NTOK * D_];
__device__ float g_q [NTOK * D_];
__device__ float g_k [NTOK * D_];
__device__ float g_v [NTOK * D_];
__device__ float g_vmean[B_ * H_ * DH_];
__device__ float g_rcos[S_ * 64];
__device__ float g_rsin[S_ * 64];

// fp16 activation buffers
__device__ hf g_xhi[NTOK * 2048];
__device__ hf g_yhi[NTOK * D_];
__device__ hf g_chi[NTOK * D_];
__device__ hf g_fhi[NTOK * F_];

// converted weights (single fp16), offsets in elements
#define WP_OFF   0u
#define QKV_OFF  2097152u
#define WO_OFF   (QKV_OFF + 4u * 3145728u)
#define W1_OFF   (WO_OFF + 4u * 1048576u)
#define W2_OFF   (W1_OFF + 4u * 4194304u)
#define WTOT     (W2_OFF + 4u * 4194304u)
__device__ hf g_w[WTOT];

// ==================== helpers ====================
__device__ __forceinline__ uint32_t smem_u32(const void* p) {
    uint32_t a;
    asm("{ .reg .u64 t; cvta.to.shared.u64 t, %1; cvt.u32.u64 %0, t; }" : "=r"(a) : "l"(p));
    return a;
}
__device__ __forceinline__ void cp16(uint32_t saddr, const void* gaddr) {
    asm volatile("cp.async.cg.shared.global [%0], [%1], 16;" :: "r"(saddr), "l"(gaddr));
}
__device__ __forceinline__ void cp_commit() {
    asm volatile("cp.async.commit_group;" ::: "memory");
}
__device__ __forceinline__ void ldsm4(uint32_t& r0, uint32_t& r1, uint32_t& r2, uint32_t& r3,
                                      uint32_t addr) {
    asm volatile("ldmatrix.sync.aligned.m8n8.x4.shared.b16 {%0,%1,%2,%3}, [%4];"
                 : "=r"(r0), "=r"(r1), "=r"(r2), "=r"(r3) : "r"(addr));
}
__device__ __forceinline__ void ldsm4t(uint32_t& r0, uint32_t& r1, uint32_t& r2, uint32_t& r3,
                                       uint32_t addr) {
    asm volatile("ldmatrix.sync.aligned.m8n8.x4.trans.shared.b16 {%0,%1,%2,%3}, [%4];"
                 : "=r"(r0), "=r"(r1), "=r"(r2), "=r"(r3) : "r"(addr));
}
__device__ __forceinline__ void mma16816(float* d, const uint32_t* a, const uint32_t* b) {
    asm volatile(
        "mma.sync.aligned.m16n8k16.row.col.f32.f16.f16.f32 "
        "{%0,%1,%2,%3}, {%4,%5,%6,%7}, {%8,%9}, {%0,%1,%2,%3};"
        : "+f"(d[0]), "+f"(d[1]), "+f"(d[2]), "+f"(d[3])
        : "r"(a[0]), "r"(a[1]), "r"(a[2]), "r"(a[3]), "r"(b[0]), "r"(b[1]));
}

// ==================== converters ====================
__device__ __forceinline__ void conv_plain_range(const float* in, hf* w, int blk0, int blk)
{
#pragma unroll
    for (int r = 0; r < 4; r++) {
        int i = (blk - blk0) * 1024 + r * 256 + threadIdx.x;
        float4 v = ((const float4*)in)[i];
        ((hf2*)w)[2 * i]     = __floats2half2_rn(v.x, v.y);
        ((hf2*)w)[2 * i + 1] = __floats2half2_rn(v.z, v.w);
    }
}
__global__ void __launch_bounds__(256)
conv_w(const float* __restrict__ in, hf* __restrict__ w)
{
    conv_plain_range(in, w, 0, blockIdx.x);
}
// merged Wo + W1 + W2 conversion: grid 1024 + 4096 + 4096 = 9216
__global__ void __launch_bounds__(256)
conv_w3(const float* __restrict__ Wo, const float* __restrict__ W1,
        const float* __restrict__ W2, hf* __restrict__ w)
{
    int blk = blockIdx.x;
    if (blk < 1024)       conv_plain_range(Wo, w + WO_OFF, 0,    blk);
    else if (blk < 5120)  conv_plain_range(W1, w + W1_OFF, 1024, blk);
    else                  conv_plain_range(W2, w + W2_OFF, 5120, blk);
}
// merged QKV interleave: grid 3072
__global__ void __launch_bounds__(256)
conv_w_qkv(const float* __restrict__ Wq, const float* __restrict__ Wk,
           const float* __restrict__ Wv, hf* __restrict__ w)
{
    int blk = blockIdx.x;
    const float* in = (blk < 1024) ? Wq : (blk < 2048) ? Wk : Wv;
    int coff = (blk < 1024) ? 0 : (blk < 2048) ? 1024 : 2048;
    int blk0 = (blk < 1024) ? 0 : (blk < 2048) ? 1024 : 2048;
#pragma unroll
    for (int r = 0; r < 4; r++) {
        int i = (blk - blk0) * 1024 + r * 256 + threadIdx.x;
        int row = i >> 8, c4 = i & 255;
        float4 v = ((const float4*)in)[i];
        size_t o2 = ((size_t)row * 3072 + coff + c4 * 4) >> 1;
        ((hf2*)(w + QKV_OFF))[o2]     = __floats2half2_rn(v.x, v.y);
        ((hf2*)(w + QKV_OFF))[o2 + 1] = __floats2half2_rn(v.z, v.w);
    }
}

// ==================== pipelined fp16 GEMM ====================
#define EP_PROJ  1
#define EP_QKV   2
#define EP_RESID 3
#define EP_SILU  4

#define A_PITCH 144
#define B_PITCH 272
#define OFF_AH 0
#define OFF_AL 18432
#define OFF_B  36864
#define STAGE_B 54272
#define GEMM_SMEM (2 * STAGE_B)   // 108544

template <int NT>
__device__ __forceinline__ void stage_load(
    uint32_t stb, const hf* Ah, const hf* Al, const hf* Bw,
    int k0, int bm, int bn, int K, int NN, int tid)
{
#pragma unroll
    for (int t = 0; t < 4; t++) {
        const int idx = t * 256 + tid;
        const int row = idx >> 3, seg = idx & 7;
        const size_t go = (size_t)(bm + row) * K + k0 + seg * 8;
        const uint32_t so = stb + (uint32_t)row * A_PITCH + seg * 16;
        cp16(so + OFF_AH, Ah + go);
        if (NT == 2) cp16(so + OFF_AL, Al + go);
    }
#pragma unroll
    for (int t = 0; t < 4; t++) {
        const int idx = t * 256 + tid;
        const int row = idx >> 4, seg = idx & 15;
        const size_t go = (size_t)(k0 + row) * NN + bn + seg * 8;
        const uint32_t so = stb + (uint32_t)row * B_PITCH + seg * 16;
        cp16(so + OFF_B, Bw + go);
    }
}

template <int MODE, int NT>
__global__ void __launch_bounds__(256, 2)
mma_gemm(int K, int NN,
         const hf* __restrict__ Ah, const hf* __restrict__ Al,
         const hf* __restrict__ Bw,
         const float* __restrict__ bias, const float* __restrict__ bias2,
         const float* __restrict__ bias3,
         float* __restrict__ out, hf* __restrict__ outHi, hf* __restrict__ outLo,
         const int* __restrict__ x_lengths,
         const float* __restrict__ rc, const float* __restrict__ rs)
{
    extern __shared__ char sm[];
    const uint32_t sb = smem_u32(sm);
    const int tid  = threadIdx.x;
    const int wid  = tid >> 5;
    const int lane = tid & 31;
    const int bn = blockIdx.x * 128;
    const int bm = blockIdx.y * 128;
    const int wm = wid & 1;
    const int wn = wid >> 1;

    float acc[4][4][4];
#pragma unroll
    for (int i = 0; i < 4; i++)
#pragma unroll
        for (int j = 0; j < 4; j++)
#pragma unroll
            for (int r = 0; r < 4; r++) acc[i][j][r] = 0.f;

    const int quad = lane >> 3;
    const int qr   = lane & 7;
    const uint32_t aOffH = OFF_AH + (uint32_t)(wm * 64 + (quad & 1) * 8 + qr) * A_PITCH + (quad >> 1) * 16;
    const uint32_t bOff  = OFF_B + (uint32_t)((quad & 1) * 8 + qr) * B_PITCH
                         + (uint32_t)(wn * 32 + (quad >> 1) * 8) * 2;

    const int nch = K >> 6;

    stage_load<NT>(sb, Ah, Al, Bw, 0, bm, bn, K, NN, tid);
    cp_commit();
    if (nch > 1) {
        stage_load<NT>(sb + STAGE_B, Ah, Al, Bw, 64, bm, bn, K, NN, tid);
        cp_commit();
    }

    for (int c = 0; c < nch; c++) {
        if (c < nch - 1) asm volatile("cp.async.wait_group 1;" ::: "memory");
        else             asm volatile("cp.async.wait_group 0;" ::: "memory");
        __syncthreads();

        const uint32_t stb = sb + (uint32_t)(c & 1) * STAGE_B;

#pragma unroll
        for (int ks = 0; ks < 4; ks++) {
            uint32_t aH[4][4], aL[4][4], bF[4][2];
#pragma unroll
            for (int mi = 0; mi < 4; mi++) {
                const uint32_t ad = stb + aOffH + (uint32_t)mi * (16 * A_PITCH) + ks * 32;
                ldsm4(aH[mi][0], aH[mi][1], aH[mi][2], aH[mi][3], ad);
                if (NT == 2)
                    ldsm4(aL[mi][0], aL[mi][1], aL[mi][2], aL[mi][3], ad + (OFF_AL - OFF_AH));
            }
#pragma unroll
            for (int bp = 0; bp < 2; bp++) {
                const uint32_t ad = stb + bOff + (uint32_t)ks * (16 * B_PITCH) + bp * 32;
                uint32_t r0, r1, r2, r3;
                ldsm4t(r0, r1, r2, r3, ad);
                bF[2 * bp][0] = r0; bF[2 * bp][1] = r1;
                bF[2 * bp + 1][0] = r2; bF[2 * bp + 1][1] = r3;
            }
#pragma unroll
            for (int mi = 0; mi < 4; mi++)
#pragma unroll
                for (int ni = 0; ni < 4; ni++) {
                    mma16816(acc[mi][ni], aH[mi], bF[ni]);
                    if (NT == 2) mma16816(acc[mi][ni], aL[mi], bF[ni]);
                }
        }
        __syncthreads();

        if (c + 2 < nch) {
            stage_load<NT>(stb, Ah, Al, Bw, (c + 2) << 6, bm, bn, K, NN, tid);
            cp_commit();
        }
    }

    // ---- epilogue ----
    const int grp = lane >> 2;
    const int qc  = (lane & 3) * 2;

    if (MODE == EP_QKV) {
        // stage biased tile in smem, then fused RoPE (q,k) / copy (v) to [B,H,S,Dh]
        float* sf = (float*)sm;   // 128 x 132 floats
#pragma unroll
        for (int mi = 0; mi < 4; mi++) {
#pragma unroll
            for (int ni = 0; ni < 4; ni++) {
                const int n = bn + wn * 32 + ni * 8 + qc;
                const int sel0 = n >> 10;
                const float* bp = (sel0 == 0) ? bias : (sel0 == 1) ? bias2 : bias3;
                float2 bsv = *(const float2*)(bp + (n & 1023));
                const int nl = wn * 32 + ni * 8 + qc;
#pragma unroll
                for (int half = 0; half < 2; half++) {
                    const int ml = wm * 64 + mi * 16 + grp + half * 8;
                    float2 v;
                    v.x = acc[mi][ni][2 * half + 0] + bsv.x;
                    v.y = acc[mi][ni][2 * half + 1] + bsv.y;
                    *(float2*)&sf[ml * 132 + nl] = v;
                }
            }
        }
        __syncthreads();

        const int sel = bn >> 10;
        const int hh  = (bn & 1023) >> 7;
        float* dst = (sel == 0) ? out : (sel == 1) ? (float*)outHi : (float*)outLo;
#pragma unroll
        for (int e = 0; e < 16; e++) {
            const int lin = e * 256 + tid;          // 4096 float4 slots
            const int row = lin >> 5;
            const int dh0 = (lin & 31) * 4;
            const int sg  = bm + row;
            const int b = sg >> 10, s = sg & 1023;
            float4 xv = *(float4*)&sf[row * 132 + dh0];
            float4 o;
            if (sel == 2) {
                o = xv;
            } else {
                const int p = dh0 & 63;
                float4 pr = *(float4*)&sf[row * 132 + (dh0 ^ 64)];
                float4 cs = *(const float4*)(rc + (s << 6) + p);
                float4 sn = *(const float4*)(rs + (s << 6) + p);
                if (dh0 < 64) {
                    o.x = xv.x * cs.x - pr.x * sn.x;
                    o.y = xv.y * cs.y - pr.y * sn.y;
                    o.z = xv.z * cs.z - pr.z * sn.z;
                    o.w = xv.w * cs.w - pr.w * sn.w;
                } else {
                    o.x = pr.x * sn.x + xv.x * cs.x;
                    o.y = pr.y * sn.y + xv.y * cs.y;
                    o.z = pr.z * sn.z + xv.z * cs.z;
                    o.w = pr.w * sn.w + xv.w * cs.w;
                }
            }
            *(float4*)(dst + ((size_t)((b << 3) | hh) * 1024 + s) * 128 + dh0) = o;
        }
        return;
    }

#pragma unroll
    for (int mi = 0; mi < 4; mi++) {
        const int m0 = bm + wm * 64 + mi * 16 + grp;
#pragma unroll
        for (int ni = 0; ni < 4; ni++) {
            const int n = bn + wn * 32 + ni * 8 + qc;
            float2 bsv = *(const float2*)(bias + n);
            float2 v01, v23;
            v01.x = acc[mi][ni][0] + bsv.x;
            v01.y = acc[mi][ni][1] + bsv.y;
            v23.x = acc[mi][ni][2] + bsv.x;
            v23.y = acc[mi][ni][3] + bsv.y;
#pragma unroll
            for (int half = 0; half < 2; half++) {
                const int m = m0 + half * 8;
                float2 v = half ? v23 : v01;
                if (MODE == EP_PROJ) {
                    const int b = m >> 10, s = m & 1023;
                    const int len = x_lengths[b] >> 2;
                    if (s >= len) { v.x = 0.f; v.y = 0.f; }
                    *(float2*)(out + (size_t)m * NN + n) = v;
                } else if (MODE == EP_RESID) {
                    float2 o = *(float2*)(out + (size_t)m * NN + n);
                    o.x += v.x; o.y += v.y;
                    *(float2*)(out + (size_t)m * NN + n) = o;
                } else { // EP_SILU -> single fp16
                    v.x = v.x / (1.f + __expf(-v.x));
                    v.y = v.y / (1.f + __expf(-v.y));
                    const size_t o2 = ((size_t)m * NN + n) >> 1;
                    ((hf2*)outHi)[o2] = __floats2half2_rn(v.x, v.y);
                }
            }
        }
    }
}

// -------------------- LayerNorm (float4 loads) --------------------
template <bool HFOUT>
__global__ void __launch_bounds__(256)
layernorm_kernel(const float* __restrict__ in, float* __restrict__ out,
                 hf* __restrict__ outHi,
                 const float* __restrict__ scale, const float* __restrict__ bias)
{
    __shared__ float sh1[8];
    __shared__ float sh2[8];
    const int row = blockIdx.x;
    const int t = threadIdx.x;
    const int lane = t & 31, w = t >> 5;
    const float* xr = in + (size_t)row * 1024;

    float4 vals = *(const float4*)(xr + 4 * t);
    float s = vals.x + vals.y + vals.z + vals.w;
#pragma unroll
    for (int o = 16; o; o >>= 1) s += __shfl_xor_sync(0xffffffffu, s, o);
    if (lane == 0) sh1[w] = s;
    __syncthreads();
    float tot = (t < 8) ? sh1[t] : 0.f;
    if (w == 0) {
#pragma unroll
        for (int o = 16; o; o >>= 1) tot += __shfl_xor_sync(0xffffffffu, tot, o);
        if (lane == 0) sh1[0] = tot;
    }
    __syncthreads();
    const float mean = sh1[0] * (1.f / 1024.f);

    float dx = vals.x - mean, dy = vals.y - mean, dz = vals.z - mean, dw = vals.w - mean;
    float vs = dx * dx + dy * dy + dz * dz + dw * dw;
#pragma unroll
    for (int o = 16; o; o >>= 1) vs += __shfl_xor_sync(0xffffffffu, vs, o);
    if (lane == 0) sh2[w] = vs;
    __syncthreads();
    float vtot = (t < 8) ? sh2[t] : 0.f;
    if (w == 0) {
#pragma unroll
        for (int o = 16; o; o >>= 1) vtot += __shfl_xor_sync(0xffffffffu, vtot, o);
        if (lane == 0) sh2[0] = vtot;
    }
    __syncthreads();
    const float var = sh2[0] * (1.f / 1024.f);
    const float inv = rsqrtf(var + 1e-5f);

    float4 sc = *(const float4*)(scale + 4 * t);
    float4 bi = *(const float4*)(bias + 4 * t);
    float r0 = dx * inv * sc.x + bi.x;
    float r1 = dy * inv * sc.y + bi.y;
    float r2 = dz * inv * sc.z + bi.z;
    float r3 = dw * inv * sc.w + bi.w;
    if (HFOUT) {
        hf2* dst = (hf2*)(outHi + (size_t)row * 1024 + 4 * t);
        dst[0] = __floats2half2_rn(r0, r1);
        dst[1] = __floats2half2_rn(r2, r3);
    } else {
        float4 o = {r0, r1, r2, r3};
        *(float4*)(out + (size_t)row * 1024 + 4 * t) = o;
    }
}

// -------------------- RoPE table --------------------
__global__ void __launch_bounds__(256)
rope_table_kernel(float* __restrict__ rc, float* __restrict__ rs)
{
    int idx = blockIdx.x * blockDim.x + threadIdx.x;
    int p = idx & 63;
    int s = idx >> 6;
    float inv_freq = expf(-(float)p * (9.210340371976184f / 64.f));
    float ang = (float)s * inv_freq;
    float sn, cs;
    sincosf(ang, &sn, &cs);
    rc[idx] = cs;
    rs[idx] = sn;
}

// -------------------- V mean --------------------
__global__ void __launch_bounds__(1024)
vmean_kernel(const float* __restrict__ v, float* __restrict__ vmean)
{
    __shared__ float partial[8][128];
    const int bh = blockIdx.x;
    const int d  = threadIdx.x & 127;
    const int sl = threadIdx.x >> 7;
    const float* base = v + (size_t)bh * S_ * DH_ + (size_t)sl * 128 * DH_ + d;
    float s = 0.f;
#pragma unroll 4
    for (int j = 0; j < 128; j++) s += base[j * DH_];
    partial[sl][d] = s;
    __syncthreads();
    if (sl == 0) {
        float t = 0.f;
#pragma unroll
        for (int r = 0; r < 8; r++) t += partial[r][d];
        vmean[bh * DH_ + d] = t * (1.f / (float)S_);
    }
}

// -------------------- windowed attention: 4 queries per warp ----------------
__global__ void __launch_bounds__(256)
attn_kernel(const float* __restrict__ q, const float* __restrict__ k,
            const float* __restrict__ v, const float* __restrict__ vmean,
            hf* __restrict__ ctxHi, const int* __restrict__ x_lengths)
{
    const int g    = blockIdx.x * 8 + (threadIdx.x >> 5);
    const int lane = threadIdx.x & 31;
    const int i0 = (g & 255) * 4;
    const int hh = (g >> 8) & 7;
    const int b  = g >> 11;

    const int len = x_lengths[b] >> 2;
    const size_t head = ((size_t)(b * 8 + hh)) * 1024;
    const float scale = 0.08838834764831845f;

    int jloq[4], jhq[4];
    bool msk[4];
    int lo = 0x7fffffff, hi = -1;
    bool anyLive = false, anyMasked = false;
#pragma unroll
    for (int qq = 0; qq < 4; qq++) {
        const int i = i0 + qq;
        int jl = i - (WIN_ - 1); if (jl < 0) jl = 0;
        int jh_ = i + LFW_;      if (jh_ > S_ - 1) jh_ = S_ - 1;
        if (len - 1 < jh_) jh_ = len - 1;
        jloq[qq] = jl; jhq[qq] = jh_;
        msk[qq] = (jh_ < jl);
        if (msk[qq]) anyMasked = true;
        else { anyLive = true; if (jl < lo) lo = jl; if (jh_ > hi) hi = jh_; }
    }

    float4 vmv = {0.f, 0.f, 0.f, 0.f};
    if (anyMasked)
        vmv = *(const float4*)(vmean + (b * 8 + hh) * 128 + lane * 4);

    if (!anyLive) {
#pragma unroll
        for (int qq = 0; qq < 4; qq++) {
            const size_t ob = ((size_t)(b * 1024 + i0 + qq)) * 1024 + hh * 128 + lane * 4;
            *(hf2*)(ctxHi + ob)     = __floats2half2_rn(vmv.x, vmv.y);
            *(hf2*)(ctxHi + ob + 2) = __floats2half2_rn(vmv.z, vmv.w);
        }
        return;
    }

    float4 qv[4];
#pragma unroll
    for (int qq = 0; qq < 4; qq++)
        qv[qq] = *(const float4*)(q + (head + i0 + qq) * 128 + lane * 4);

    float sc[4][4];
#pragma unroll
    for (int qq = 0; qq < 4; qq++)
#pragma unroll
        for (int s = 0; s < 4; s++) sc[qq][s] = -1e30f;

#pragma unroll
    for (int jb = 0; jb < 4; jb++) {
        const int jbase = lo + jb * 32;
        if (jbase > hi) break;
        for (int t = 0; t < 32; t++) {
            const int j = jbase + t;
            if (j > hi) break;
            float4 kv = *(const float4*)(k + (head + j) * 128 + lane * 4);
            float s0 = qv[0].x * kv.x + qv[0].y * kv.y + qv[0].z * kv.z + qv[0].w * kv.w;
            float s1 = qv[1].x * kv.x + qv[1].y * kv.y + qv[1].z * kv.z + qv[1].w * kv.w;
            float s2 = qv[2].x * kv.x + qv[2].y * kv.y + qv[2].z * kv.z + qv[2].w * kv.w;
            float s3 = qv[3].x * kv.x + qv[3].y * kv.y + qv[3].z * kv.z + qv[3].w * kv.w;
#pragma unroll
            for (int o = 16; o; o >>= 1) {
                s0 += __shfl_xor_sync(0xffffffffu, s0, o);
                s1 += __shfl_xor_sync(0xffffffffu, s1, o);
                s2 += __shfl_xor_sync(0xffffffffu, s2, o);
                s3 += __shfl_xor_sync(0xffffffffu, s3, o);
            }
            if (t == lane) {
                sc[0][jb] = s0 * scale;
                sc[1][jb] = s1 * scale;
                sc[2][jb] = s2 * scale;
                sc[3][jb] = s3 * scale;
            }
        }
    }

    float p[4][4], invl[4];
#pragma unroll
    for (int qq = 0; qq < 4; qq++) {
        if (msk[qq]) { invl[qq] = 0.f; continue; }
        float m = -1e30f;
#pragma unroll
        for (int s = 0; s < 4; s++) {
            const int j = lo + s * 32 + lane;
            const bool ok = (j >= jloq[qq]) && (j <= jhq[qq]);
            const float val = ok ? sc[qq][s] : -1e30f;
            sc[qq][s] = val;
            m = fmaxf(m, val);
        }
#pragma unroll
        for (int o = 16; o; o >>= 1) m = fmaxf(m, __shfl_xor_sync(0xffffffffu, m, o));
        float l = 0.f;
#pragma unroll
        for (int s = 0; s < 4; s++) {
            const float pe = (sc[qq][s] > -1e29f) ? __expf(sc[qq][s] - m) : 0.f;
            p[qq][s] = pe;
            l += pe;
        }
#pragma unroll
        for (int o = 16; o; o >>= 1) l += __shfl_xor_sync(0xffffffffu, l, o);
        invl[qq] = 1.f / l;
    }

    float4 acc[4];
#pragma unroll
    for (int qq = 0; qq < 4; qq++) acc[qq] = make_float4(0.f, 0.f, 0.f, 0.f);

#pragma unroll
    for (int jb = 0; jb < 4; jb++) {
        const int jbase = lo + jb * 32;
        if (jbase > hi) break;
        for (int t = 0; t < 32; t++) {
            const int j = jbase + t;
            if (j > hi) break;
            float4 vv = *(const float4*)(v + (head + j) * 128 + lane * 4);
            const float p0 = __shfl_sync(0xffffffffu, p[0][jb], t);
            const float p1 = __shfl_sync(0xffffffffu, p[1][jb], t);
            const float p2 = __shfl_sync(0xffffffffu, p[2][jb], t);
            const float p3 = __shfl_sync(0xffffffffu, p[3][jb], t);
            acc[0].x += p0 * vv.x; acc[0].y += p0 * vv.y; acc[0].z += p0 * vv.z; acc[0].w += p0 * vv.w;
            acc[1].x += p1 * vv.x; acc[1].y += p1 * vv.y; acc[1].z += p1 * vv.z; acc[1].w += p1 * vv.w;
            acc[2].x += p2 * vv.x; acc[2].y += p2 * vv.y; acc[2].z += p2 * vv.z; acc[2].w += p2 * vv.w;
            acc[3].x += p3 * vv.x; acc[3].y += p3 * vv.y; acc[3].z += p3 * vv.z; acc[3].w += p3 * vv.w;
        }
    }

#pragma unroll
    for (int qq = 0; qq < 4; qq++) {
        const size_t ob = ((size_t)(b * 1024 + i0 + qq)) * 1024 + hh * 128 + lane * 4;
        float4 r;
        if (msk[qq]) r = vmv;
        else {
            const float il = invl[qq];
            r.x = acc[qq].x * il; r.y = acc[qq].y * il;
            r.z = acc[qq].z * il; r.w = acc[qq].w * il;
        }
        *(hf2*)(ctxHi + ob)     = __floats2half2_rn(r.x, r.y);
        *(hf2*)(ctxHi + ob + 2) = __floats2half2_rn(r.z, r.w);
    }
}

// -------------------- launch --------------------
extern "C" void kernel_launch(void* const* d_in, const int* in_sizes, int n_in,
                              void* d_out, int out_size)
{
    const float* x     = (const float*)d_in[0];
    const int*   xlen  = (const int*)  d_in[1];
    const float* Wp    = (const float*)d_in[2];
    const float* bp    = (const float*)d_in[3];
    const float* ln1_s = (const float*)d_in[4];
    const float* ln1_b = (const float*)d_in[5];
    const float* Wq    = (const float*)d_in[6];
    const float* bq    = (const float*)d_in[7];
    const float* Wk    = (const float*)d_in[8];
    const float* bk    = (const float*)d_in[9];
    const float* Wv    = (const float*)d_in[10];
    const float* bv    = (const float*)d_in[11];
    const float* Wo    = (const float*)d_in[12];
    const float* bo    = (const float*)d_in[13];
    const float* ln2_s = (const float*)d_in[14];
    const float* ln2_b = (const float*)d_in[15];
    const float* W1    = (const float*)d_in[16];
    const float* b1    = (const float*)d_in[17];
    const float* W2    = (const float*)d_in[18];
    const float* b2    = (const float*)d_in[19];
    const float* lnf_s = (const float*)d_in[20];
    const float* lnf_b = (const float*)d_in[21];
    float* out = (float*)d_out;

    float *h, *q, *k, *v, *vmean, *rc, *rs;
    hf *xhi, *yhi, *chi, *fhi, *w;
    cudaGetSymbolAddress((void**)&h,    g_h);
    cudaGetSymbolAddress((void**)&q,    g_q);
    cudaGetSymbolAddress((void**)&k,    g_k);
    cudaGetSymbolAddress((void**)&v,    g_v);
    cudaGetSymbolAddress((void**)&vmean,g_vmean);
    cudaGetSymbolAddress((void**)&rc,   g_rcos);
    cudaGetSymbolAddress((void**)&rs,   g_rsin);
    cudaGetSymbolAddress((void**)&xhi,  g_xhi);
    cudaGetSymbolAddress((void**)&yhi,  g_yhi);
    cudaGetSymbolAddress((void**)&chi,  g_chi);
    cudaGetSymbolAddress((void**)&fhi,  g_fhi);
    cudaGetSymbolAddress((void**)&w,    g_w);

    cudaFuncSetAttribute((const void*)mma_gemm<EP_PROJ, 1>,  cudaFuncAttributeMaxDynamicSharedMemorySize, GEMM_SMEM);
    cudaFuncSetAttribute((const void*)mma_gemm<EP_QKV, 1>,   cudaFuncAttributeMaxDynamicSharedMemorySize, GEMM_SMEM);
    cudaFuncSetAttribute((const void*)mma_gemm<EP_SILU, 1>,  cudaFuncAttributeMaxDynamicSharedMemorySize, GEMM_SMEM);
    cudaFuncSetAttribute((const void*)mma_gemm<EP_RESID, 1>, cudaFuncAttributeMaxDynamicSharedMemorySize, GEMM_SMEM);

    const dim3 blk(256);

    conv_w<<<2048, blk>>>(x, xhi);                       // x -> fp16 (single-term)
    conv_w<<<512, blk>>>(Wp, w + WP_OFF);
    rope_table_kernel<<<256, blk>>>(rc, rs);
    conv_w_qkv<<<3072, blk>>>(Wq, Wk, Wv, w);
    conv_w3<<<9216, blk>>>(Wo, W1, W2, w);

    // projector (1-term)
    mma_gemm<EP_PROJ, 1><<<dim3(8, 32), blk, GEMM_SMEM>>>(
        2048, 1024, xhi, nullptr, w + WP_OFF,
        bp, nullptr, nullptr, h, nullptr, nullptr, xlen, nullptr, nullptr);

    for (int l = 0; l < L_; l++) {
        const size_t oD  = (size_t)l * D_;
        const size_t oF  = (size_t)l * F_;
        const uint32_t oQKV = QKV_OFF + (uint32_t)l * 3145728u;
        const uint32_t oWO  = WO_OFF  + (uint32_t)l * 1048576u;
        const uint32_t oW1  = W1_OFF  + (uint32_t)l * 4194304u;
        const uint32_t oW2  = W2_OFF  + (uint32_t)l * 4194304u;

        layernorm_kernel<true><<<NTOK, blk>>>(h, nullptr, yhi, ln1_s + oD, ln1_b + oD);

        // fused QKV GEMM + bias + RoPE (q,k) + relayout
        mma_gemm<EP_QKV, 1><<<dim3(24, 32), blk, GEMM_SMEM>>>(
            1024, 3072, yhi, nullptr, w + oQKV,
            bq + oD, bk + oD, bv + oD, q, (hf*)k, (hf*)v, nullptr, rc, rs);

        vmean_kernel<<<B_ * H_, 1024>>>(v, vmean);
        attn_kernel<<<(B_ * H_ * S_) / 32, 256>>>(q, k, v, vmean, chi, xlen);

        mma_gemm<EP_RESID, 1><<<dim3(8, 32), blk, GEMM_SMEM>>>(
            1024, 1024, chi, nullptr, w + oWO,
            bo + oD, nullptr, nullptr, h, nullptr, nullptr, nullptr, nullptr, nullptr);

        layernorm_kernel<true><<<NTOK, blk>>>(h, nullptr, yhi, ln2_s + oD, ln2_b + oD);

        mma_gemm<EP_SILU, 1><<<dim3(32, 32), blk, GEMM_SMEM>>>(
            1024, 4096, yhi, nullptr, w + oW1,
            b1 + oF, nullptr, nullptr, nullptr, fhi, nullptr, nullptr, nullptr, nullptr);

        mma_gemm<EP_RESID, 1><<<dim3(8, 32), blk, GEMM_SMEM>>>(
            4096, 1024, fhi, nullptr, w + oW2,
            b2 + oD, nullptr, nullptr, h, nullptr, nullptr, nullptr, nullptr, nullptr);
    }

    layernorm_kernel<false><<<NTOK, blk>>>(h, out, nullptr, lnf_s, lnf_b);
}

// round 13
// speedup vs baseline: 5.9390x; 1.0196x over previous
#include <cuda_runtime.h>
#include <cuda_fp16.h>
#include <math.h>
#include <stdint.h>

// Problem constants
#define B_   4
#define S_   1024
#define D_   1024
#define F_   4096
#define H_   8
#define DH_  128
#define L_   4
#define NTOK (B_ * S_)          // 4096
#define WIN_ 100
#define LFW_ 20

typedef __half  hf;
typedef __half2 hf2;

// -------------------- scratch --------------------
__device__ float g_h [NTOK * D_];
__device__ float g_q [NTOK * D_];
__device__ float g_k [NTOK * D_];
__device__ float g_v [NTOK * D_];
__device__ float g_vmean[B_ * H_ * DH_];
__device__ float g_rcos[S_ * 64];
__device__ float g_rsin[S_ * 64];

// fp16 activation buffers
__device__ hf g_xhi[NTOK * 2048];
__device__ hf g_yhi[NTOK * D_];
__device__ hf g_chi[NTOK * D_];
__device__ hf g_fhi[NTOK * F_];

// converted weights (single fp16), offsets in elements
#define WP_OFF   0u
#define QKV_OFF  2097152u
#define WO_OFF   (QKV_OFF + 4u * 3145728u)
#define W1_OFF   (WO_OFF + 4u * 1048576u)
#define W2_OFF   (W1_OFF + 4u * 4194304u)
#define WTOT     (W2_OFF + 4u * 4194304u)
__device__ hf g_w[WTOT];

// ==================== helpers ====================
__device__ __forceinline__ uint32_t smem_u32(const void* p) {
    uint32_t a;
    asm("{ .reg .u64 t; cvta.to.shared.u64 t, %1; cvt.u32.u64 %0, t; }" : "=r"(a) : "l"(p));
    return a;
}
__device__ __forceinline__ void cp16(uint32_t saddr, const void* gaddr) {
    asm volatile("cp.async.cg.shared.global [%0], [%1], 16;" :: "r"(saddr), "l"(gaddr));
}
__device__ __forceinline__ void cp_commit() {
    asm volatile("cp.async.commit_group;" ::: "memory");
}
__device__ __forceinline__ void ldsm4(uint32_t& r0, uint32_t& r1, uint32_t& r2, uint32_t& r3,
                                      uint32_t addr) {
    asm volatile("ldmatrix.sync.aligned.m8n8.x4.shared.b16 {%0,%1,%2,%3}, [%4];"
                 : "=r"(r0), "=r"(r1), "=r"(r2), "=r"(r3) : "r"(addr));
}
__device__ __forceinline__ void ldsm4t(uint32_t& r0, uint32_t& r1, uint32_t& r2, uint32_t& r3,
                                       uint32_t addr) {
    asm volatile("ldmatrix.sync.aligned.m8n8.x4.trans.shared.b16 {%0,%1,%2,%3}, [%4];"
                 : "=r"(r0), "=r"(r1), "=r"(r2), "=r"(r3) : "r"(addr));
}
__device__ __forceinline__ void mma16816(float* d, const uint32_t* a, const uint32_t* b) {
    asm volatile(
        "mma.sync.aligned.m16n8k16.row.col.f32.f16.f16.f32 "
        "{%0,%1,%2,%3}, {%4,%5,%6,%7}, {%8,%9}, {%0,%1,%2,%3};"
        : "+f"(d[0]), "+f"(d[1]), "+f"(d[2]), "+f"(d[3])
        : "r"(a[0]), "r"(a[1]), "r"(a[2]), "r"(a[3]), "r"(b[0]), "r"(b[1]));
}

// ==================== converters ====================
__device__ __forceinline__ void conv_plain_range(const float* in, hf* w, int blk0, int blk)
{
    float4 v[4];
    const int base = (blk - blk0) * 1024 + threadIdx.x;
#pragma unroll
    for (int r = 0; r < 4; r++) v[r] = ((const float4*)in)[base + r * 256];
#pragma unroll
    for (int r = 0; r < 4; r++) {
        int i = base + r * 256;
        ((hf2*)w)[2 * i]     = __floats2half2_rn(v[r].x, v[r].y);
        ((hf2*)w)[2 * i + 1] = __floats2half2_rn(v[r].z, v[r].w);
    }
}
__global__ void __launch_bounds__(256)
conv_w(const float* __restrict__ in, hf* __restrict__ w)
{
    conv_plain_range(in, w, 0, blockIdx.x);
}
__global__ void __launch_bounds__(256)
conv_w3(const float* __restrict__ Wo, const float* __restrict__ W1,
        const float* __restrict__ W2, hf* __restrict__ w)
{
    int blk = blockIdx.x;
    if (blk < 1024)       conv_plain_range(Wo, w + WO_OFF, 0,    blk);
    else if (blk < 5120)  conv_plain_range(W1, w + W1_OFF, 1024, blk);
    else                  conv_plain_range(W2, w + W2_OFF, 5120, blk);
}
__global__ void __launch_bounds__(256)
conv_w_qkv(const float* __restrict__ Wq, const float* __restrict__ Wk,
           const float* __restrict__ Wv, hf* __restrict__ w)
{
    int blk = blockIdx.x;
    const float* in = (blk < 1024) ? Wq : (blk < 2048) ? Wk : Wv;
    int coff = (blk < 1024) ? 0 : (blk < 2048) ? 1024 : 2048;
    int blk0 = (blk < 1024) ? 0 : (blk < 2048) ? 1024 : 2048;
    float4 v[4];
    const int base = (blk - blk0) * 1024 + threadIdx.x;
#pragma unroll
    for (int r = 0; r < 4; r++) v[r] = ((const float4*)in)[base + r * 256];
#pragma unroll
    for (int r = 0; r < 4; r++) {
        int i = base + r * 256;
        int row = i >> 8, c4 = i & 255;
        size_t o2 = ((size_t)row * 3072 + coff + c4 * 4) >> 1;
        ((hf2*)(w + QKV_OFF))[o2]     = __floats2half2_rn(v[r].x, v[r].y);
        ((hf2*)(w + QKV_OFF))[o2 + 1] = __floats2half2_rn(v[r].z, v[r].w);
    }
}

// ==================== pipelined fp16 GEMM ====================
#define EP_PROJ  1
#define EP_QKV   2
#define EP_RESID 3
#define EP_SILU  4

#define A_PITCH 144
#define B_PITCH 272
#define OFF_AH 0
#define OFF_AL 18432
#define OFF_B  36864
#define STAGE_B 54272
#define GEMM_SMEM (2 * STAGE_B)   // 108544

template <int NT>
__device__ __forceinline__ void stage_load(
    uint32_t stb, const hf* Ah, const hf* Al, const hf* Bw,
    int k0, int bm, int bn, int K, int NN, int tid)
{
#pragma unroll
    for (int t = 0; t < 4; t++) {
        const int idx = t * 256 + tid;
        const int row = idx >> 3, seg = idx & 7;
        const size_t go = (size_t)(bm + row) * K + k0 + seg * 8;
        const uint32_t so = stb + (uint32_t)row * A_PITCH + seg * 16;
        cp16(so + OFF_AH, Ah + go);
        if (NT == 2) cp16(so + OFF_AL, Al + go);
    }
#pragma unroll
    for (int t = 0; t < 4; t++) {
        const int idx = t * 256 + tid;
        const int row = idx >> 4, seg = idx & 15;
        const size_t go = (size_t)(k0 + row) * NN + bn + seg * 8;
        const uint32_t so = stb + (uint32_t)row * B_PITCH + seg * 16;
        cp16(so + OFF_B, Bw + go);
    }
}

template <int MODE, int NT>
__global__ void __launch_bounds__(256, 2)
mma_gemm(int K, int NN,
         const hf* __restrict__ Ah, const hf* __restrict__ Al,
         const hf* __restrict__ Bw,
         const float* __restrict__ bias, const float* __restrict__ bias2,
         const float* __restrict__ bias3,
         float* __restrict__ out, hf* __restrict__ outHi, hf* __restrict__ outLo,
         const int* __restrict__ x_lengths,
         const float* __restrict__ rc, const float* __restrict__ rs)
{
    extern __shared__ char sm[];
    const uint32_t sb = smem_u32(sm);
    const int tid  = threadIdx.x;
    const int wid  = tid >> 5;
    const int lane = tid & 31;
    const int bn = blockIdx.x * 128;
    const int bm = blockIdx.y * 128;
    const int wm = wid & 1;
    const int wn = wid >> 1;

    float acc[4][4][4];
#pragma unroll
    for (int i = 0; i < 4; i++)
#pragma unroll
        for (int j = 0; j < 4; j++)
#pragma unroll
            for (int r = 0; r < 4; r++) acc[i][j][r] = 0.f;

    const int quad = lane >> 3;
    const int qr   = lane & 7;
    const uint32_t aOffH = OFF_AH + (uint32_t)(wm * 64 + (quad & 1) * 8 + qr) * A_PITCH + (quad >> 1) * 16;
    const uint32_t bOff  = OFF_B + (uint32_t)((quad & 1) * 8 + qr) * B_PITCH
                         + (uint32_t)(wn * 32 + (quad >> 1) * 8) * 2;

    const int nch = K >> 6;

    stage_load<NT>(sb, Ah, Al, Bw, 0, bm, bn, K, NN, tid);
    cp_commit();
    if (nch > 1) {
        stage_load<NT>(sb + STAGE_B, Ah, Al, Bw, 64, bm, bn, K, NN, tid);
        cp_commit();
    }

    for (int c = 0; c < nch; c++) {
        if (c < nch - 1) asm volatile("cp.async.wait_group 1;" ::: "memory");
        else             asm volatile("cp.async.wait_group 0;" ::: "memory");
        __syncthreads();

        const uint32_t stb = sb + (uint32_t)(c & 1) * STAGE_B;

#pragma unroll
        for (int ks = 0; ks < 4; ks++) {
            uint32_t aH[4][4], aL[4][4], bF[4][2];
#pragma unroll
            for (int mi = 0; mi < 4; mi++) {
                const uint32_t ad = stb + aOffH + (uint32_t)mi * (16 * A_PITCH) + ks * 32;
                ldsm4(aH[mi][0], aH[mi][1], aH[mi][2], aH[mi][3], ad);
                if (NT == 2)
                    ldsm4(aL[mi][0], aL[mi][1], aL[mi][2], aL[mi][3], ad + (OFF_AL - OFF_AH));
            }
#pragma unroll
            for (int bp = 0; bp < 2; bp++) {
                const uint32_t ad = stb + bOff + (uint32_t)ks * (16 * B_PITCH) + bp * 32;
                uint32_t r0, r1, r2, r3;
                ldsm4t(r0, r1, r2, r3, ad);
                bF[2 * bp][0] = r0; bF[2 * bp][1] = r1;
                bF[2 * bp + 1][0] = r2; bF[2 * bp + 1][1] = r3;
            }
#pragma unroll
            for (int mi = 0; mi < 4; mi++)
#pragma unroll
                for (int ni = 0; ni < 4; ni++) {
                    mma16816(acc[mi][ni], aH[mi], bF[ni]);
                    if (NT == 2) mma16816(acc[mi][ni], aL[mi], bF[ni]);
                }
        }
        __syncthreads();

        if (c + 2 < nch) {
            stage_load<NT>(stb, Ah, Al, Bw, (c + 2) << 6, bm, bn, K, NN, tid);
            cp_commit();
        }
    }

    // ---- epilogue ----
    const int grp = lane >> 2;
    const int qc  = (lane & 3) * 2;

    if (MODE == EP_QKV) {
        float* sf = (float*)sm;   // 128 x 132 floats
#pragma unroll
        for (int mi = 0; mi < 4; mi++) {
#pragma unroll
            for (int ni = 0; ni < 4; ni++) {
                const int n = bn + wn * 32 + ni * 8 + qc;
                const int sel0 = n >> 10;
                const float* bp = (sel0 == 0) ? bias : (sel0 == 1) ? bias2 : bias3;
                float2 bsv = *(const float2*)(bp + (n & 1023));
                const int nl = wn * 32 + ni * 8 + qc;
#pragma unroll
                for (int half = 0; half < 2; half++) {
                    const int ml = wm * 64 + mi * 16 + grp + half * 8;
                    float2 v;
                    v.x = acc[mi][ni][2 * half + 0] + bsv.x;
                    v.y = acc[mi][ni][2 * half + 1] + bsv.y;
                    *(float2*)&sf[ml * 132 + nl] = v;
                }
            }
        }
        __syncthreads();

        const int sel = bn >> 10;
        const int hh  = (bn & 1023) >> 7;
        float* dst = (sel == 0) ? out : (sel == 1) ? (float*)outHi : (float*)outLo;
#pragma unroll
        for (int e = 0; e < 16; e++) {
            const int lin = e * 256 + tid;
            const int row = lin >> 5;
            const int dh0 = (lin & 31) * 4;
            const int sg  = bm + row;
            const int b = sg >> 10, s = sg & 1023;
            float4 xv = *(float4*)&sf[row * 132 + dh0];
            float4 o;
            if (sel == 2) {
                o = xv;
            } else {
                const int p = dh0 & 63;
                float4 pr = *(float4*)&sf[row * 132 + (dh0 ^ 64)];
                float4 cs = *(const float4*)(rc + (s << 6) + p);
                float4 sn = *(const float4*)(rs + (s << 6) + p);
                if (dh0 < 64) {
                    o.x = xv.x * cs.x - pr.x * sn.x;
                    o.y = xv.y * cs.y - pr.y * sn.y;
                    o.z = xv.z * cs.z - pr.z * sn.z;
                    o.w = xv.w * cs.w - pr.w * sn.w;
                } else {
                    o.x = pr.x * sn.x + xv.x * cs.x;
                    o.y = pr.y * sn.y + xv.y * cs.y;
                    o.z = pr.z * sn.z + xv.z * cs.z;
                    o.w = pr.w * sn.w + xv.w * cs.w;
                }
            }
            *(float4*)(dst + ((size_t)((b << 3) | hh) * 1024 + s) * 128 + dh0) = o;
        }
        return;
    }

#pragma unroll
    for (int mi = 0; mi < 4; mi++) {
        const int m0 = bm + wm * 64 + mi * 16 + grp;
#pragma unroll
        for (int ni = 0; ni < 4; ni++) {
            const int n = bn + wn * 32 + ni * 8 + qc;
            float2 bsv = *(const float2*)(bias + n);
            float2 v01, v23;
            v01.x = acc[mi][ni][0] + bsv.x;
            v01.y = acc[mi][ni][1] + bsv.y;
            v23.x = acc[mi][ni][2] + bsv.x;
            v23.y = acc[mi][ni][3] + bsv.y;
#pragma unroll
            for (int half = 0; half < 2; half++) {
                const int m = m0 + half * 8;
                float2 v = half ? v23 : v01;
                if (MODE == EP_PROJ) {
                    const int b = m >> 10, s = m & 1023;
                    const int len = x_lengths[b] >> 2;
                    if (s >= len) { v.x = 0.f; v.y = 0.f; }
                    *(float2*)(out + (size_t)m * NN + n) = v;
                } else if (MODE == EP_RESID) {
                    float2 o = *(float2*)(out + (size_t)m * NN + n);
                    o.x += v.x; o.y += v.y;
                    *(float2*)(out + (size_t)m * NN + n) = o;
                } else { // EP_SILU
                    v.x = v.x / (1.f + __expf(-v.x));
                    v.y = v.y / (1.f + __expf(-v.y));
                    const size_t o2 = ((size_t)m * NN + n) >> 1;
                    ((hf2*)outHi)[o2] = __floats2half2_rn(v.x, v.y);
                }
            }
        }
    }
}

// -------------------- LayerNorm --------------------
template <bool HFOUT>
__global__ void __launch_bounds__(256)
layernorm_kernel(const float* __restrict__ in, float* __restrict__ out,
                 hf* __restrict__ outHi,
                 const float* __restrict__ scale, const float* __restrict__ bias)
{
    __shared__ float sh1[8];
    __shared__ float sh2[8];
    const int row = blockIdx.x;
    const int t = threadIdx.x;
    const int lane = t & 31, w = t >> 5;
    const float* xr = in + (size_t)row * 1024;

    float4 vals = *(const float4*)(xr + 4 * t);
    float s = vals.x + vals.y + vals.z + vals.w;
#pragma unroll
    for (int o = 16; o; o >>= 1) s += __shfl_xor_sync(0xffffffffu, s, o);
    if (lane == 0) sh1[w] = s;
    __syncthreads();
    float tot = (t < 8) ? sh1[t] : 0.f;
    if (w == 0) {
#pragma unroll
        for (int o = 16; o; o >>= 1) tot += __shfl_xor_sync(0xffffffffu, tot, o);
        if (lane == 0) sh1[0] = tot;
    }
    __syncthreads();
    const float mean = sh1[0] * (1.f / 1024.f);

    float dx = vals.x - mean, dy = vals.y - mean, dz = vals.z - mean, dw = vals.w - mean;
    float vs = dx * dx + dy * dy + dz * dz + dw * dw;
#pragma unroll
    for (int o = 16; o; o >>= 1) vs += __shfl_xor_sync(0xffffffffu, vs, o);
    if (lane == 0) sh2[w] = vs;
    __syncthreads();
    float vtot = (t < 8) ? sh2[t] : 0.f;
    if (w == 0) {
#pragma unroll
        for (int o = 16; o; o >>= 1) vtot += __shfl_xor_sync(0xffffffffu, vtot, o);
        if (lane == 0) sh2[0] = vtot;
    }
    __syncthreads();
    const float var = sh2[0] * (1.f / 1024.f);
    const float inv = rsqrtf(var + 1e-5f);

    float4 sc = *(const float4*)(scale + 4 * t);
    float4 bi = *(const float4*)(bias + 4 * t);
    float r0 = dx * inv * sc.x + bi.x;
    float r1 = dy * inv * sc.y + bi.y;
    float r2 = dz * inv * sc.z + bi.z;
    float r3 = dw * inv * sc.w + bi.w;
    if (HFOUT) {
        hf2* dst = (hf2*)(outHi + (size_t)row * 1024 + 4 * t);
        dst[0] = __floats2half2_rn(r0, r1);
        dst[1] = __floats2half2_rn(r2, r3);
    } else {
        float4 o = {r0, r1, r2, r3};
        *(float4*)(out + (size_t)row * 1024 + 4 * t) = o;
    }
}

// -------------------- RoPE table --------------------
__global__ void __launch_bounds__(256)
rope_table_kernel(float* __restrict__ rc, float* __restrict__ rs)
{
    int idx = blockIdx.x * blockDim.x + threadIdx.x;
    int p = idx & 63;
    int s = idx >> 6;
    float inv_freq = expf(-(float)p * (9.210340371976184f / 64.f));
    float ang = (float)s * inv_freq;
    float sn, cs;
    sincosf(ang, &sn, &cs);
    rc[idx] = cs;
    rs[idx] = sn;
}

// -------------------- V mean --------------------
__global__ void __launch_bounds__(1024)
vmean_kernel(const float* __restrict__ v, float* __restrict__ vmean)
{
    __shared__ float partial[8][128];
    const int bh = blockIdx.x;
    const int d  = threadIdx.x & 127;
    const int sl = threadIdx.x >> 7;
    const float* base = v + (size_t)bh * S_ * DH_ + (size_t)sl * 128 * DH_ + d;
    float s = 0.f;
#pragma unroll 4
    for (int j = 0; j < 128; j++) s += base[j * DH_];
    partial[sl][d] = s;
    __syncthreads();
    if (sl == 0) {
        float t = 0.f;
#pragma unroll
        for (int r = 0; r < 8; r++) t += partial[r][d];
        vmean[bh * DH_ + d] = t * (1.f / (float)S_);
    }
}

// -------------------- windowed attention: 4 q/warp, folded reductions -------
__global__ void __launch_bounds__(256)
attn_kernel(const float* __restrict__ q, const float* __restrict__ k,
            const float* __restrict__ v, const float* __restrict__ vmean,
            hf* __restrict__ ctxHi, const int* __restrict__ x_lengths)
{
    const int g    = blockIdx.x * 8 + (threadIdx.x >> 5);
    const int lane = threadIdx.x & 31;
    const int i0 = (g & 255) * 4;
    const int hh = (g >> 8) & 7;
    const int b  = g >> 11;

    const int len = x_lengths[b] >> 2;
    const size_t head = ((size_t)(b * 8 + hh)) * 1024;
    const float scale = 0.08838834764831845f;

    int jloq[4], jhq[4];
    bool msk[4];
    int lo = 0x7fffffff, hi = -1;
    bool anyLive = false, anyMasked = false;
#pragma unroll
    for (int qq = 0; qq < 4; qq++) {
        const int i = i0 + qq;
        int jl = i - (WIN_ - 1); if (jl < 0) jl = 0;
        int jh_ = i + LFW_;      if (jh_ > S_ - 1) jh_ = S_ - 1;
        if (len - 1 < jh_) jh_ = len - 1;
        jloq[qq] = jl; jhq[qq] = jh_;
        msk[qq] = (jh_ < jl);
        if (msk[qq]) anyMasked = true;
        else { anyLive = true; if (jl < lo) lo = jl; if (jh_ > hi) hi = jh_; }
    }

    float4 vmv = {0.f, 0.f, 0.f, 0.f};
    if (anyMasked)
        vmv = *(const float4*)(vmean + (b * 8 + hh) * 128 + lane * 4);

    if (!anyLive) {
#pragma unroll
        for (int qq = 0; qq < 4; qq++) {
            const size_t ob = ((size_t)(b * 1024 + i0 + qq)) * 1024 + hh * 128 + lane * 4;
            *(hf2*)(ctxHi + ob)     = __floats2half2_rn(vmv.x, vmv.y);
            *(hf2*)(ctxHi + ob + 2) = __floats2half2_rn(vmv.z, vmv.w);
        }
        return;
    }

    float4 qv[4];
#pragma unroll
    for (int qq = 0; qq < 4; qq++)
        qv[qq] = *(const float4*)(q + (head + i0 + qq) * 128 + lane * 4);

    const int pp = lane & 7;
    // group g owns query: g0->q0, g1->q2, g2->q1, g3->q3
    const int b8  = lane & 8;
    const int b16 = lane & 16;
    const int jlo_own = b16 ? (b8 ? jhq[3] * 0 + jloq[3] : jloq[1])
                            : (b8 ? jloq[2] : jloq[0]);
    const int jhi_own = b16 ? (b8 ? jhq[3] : jhq[1])
                            : (b8 ? jhq[2] : jhq[0]);

    // sc[jb][r] = (group query) score/exp for key lo + jb*32 + 8r + (lane&7)
    float sc[4][4];
#pragma unroll
    for (int jb = 0; jb < 4; jb++)
#pragma unroll
        for (int r = 0; r < 4; r++) sc[jb][r] = -1e30f;

    // ---- phase 1: dots + folded 4-way reduction ----
#pragma unroll
    for (int jb = 0; jb < 4; jb++) {
        const int jbase = lo + jb * 32;
        if (jbase > hi) break;
#pragma unroll
        for (int r = 0; r < 4; r++) {
            const int rbase = jbase + 8 * r;
            if (rbase > hi) break;
            for (int p = 0; p < 8; p++) {
                const int j = rbase + p;
                if (j > hi) break;
                float4 kv = *(const float4*)(k + (head + j) * 128 + lane * 4);
                float s0 = qv[0].x * kv.x + qv[0].y * kv.y + qv[0].z * kv.z + qv[0].w * kv.w;
                float s1 = qv[1].x * kv.x + qv[1].y * kv.y + qv[1].z * kv.z + qv[1].w * kv.w;
                float s2 = qv[2].x * kv.x + qv[2].y * kv.y + qv[2].z * kv.z + qv[2].w * kv.w;
                float s3 = qv[3].x * kv.x + qv[3].y * kv.y + qv[3].z * kv.z + qv[3].w * kv.w;
                s0 += __shfl_xor_sync(0xffffffffu, s0, 16);
                s1 += __shfl_xor_sync(0xffffffffu, s1, 16);
                s2 += __shfl_xor_sync(0xffffffffu, s2, 16);
                s3 += __shfl_xor_sync(0xffffffffu, s3, 16);
                float cA = b16 ? s1 : s0;
                float cB = b16 ? s3 : s2;
                cA += __shfl_xor_sync(0xffffffffu, cA, 8);
                cB += __shfl_xor_sync(0xffffffffu, cB, 8);
                float d = b8 ? cB : cA;
                d += __shfl_xor_sync(0xffffffffu, d, 4);
                d += __shfl_xor_sync(0xffffffffu, d, 2);
                d += __shfl_xor_sync(0xffffffffu, d, 1);
                if (p == pp) sc[jb][r] = d * scale;
            }
        }
    }

    // ---- group-local softmax (per owned query) ----
    float m = -1e30f;
#pragma unroll
    for (int jb = 0; jb < 4; jb++)
#pragma unroll
        for (int r = 0; r < 4; r++) {
            const int j = lo + jb * 32 + 8 * r + pp;
            const bool ok = (j >= jlo_own) && (j <= jhi_own);
            const float val = ok ? sc[jb][r] : -1e30f;
            sc[jb][r] = val;
            m = fmaxf(m, val);
        }
    m = fmaxf(m, __shfl_xor_sync(0xffffffffu, m, 4));
    m = fmaxf(m, __shfl_xor_sync(0xffffffffu, m, 2));
    m = fmaxf(m, __shfl_xor_sync(0xffffffffu, m, 1));

    float l = 0.f;
#pragma unroll
    for (int jb = 0; jb < 4; jb++)
#pragma unroll
        for (int r = 0; r < 4; r++) {
            const float pe = (sc[jb][r] > -1e29f) ? __expf(sc[jb][r] - m) : 0.f;
            sc[jb][r] = pe;
            l += pe;
        }
    l += __shfl_xor_sync(0xffffffffu, l, 4);
    l += __shfl_xor_sync(0xffffffffu, l, 2);
    l += __shfl_xor_sync(0xffffffffu, l, 1);
    const float linv = 1.f / l;

    // broadcast per-query invl to all lanes (src = group base lane)
    float invl[4];
    invl[0] = __shfl_sync(0xffffffffu, linv, 0);
    invl[1] = __shfl_sync(0xffffffffu, linv, 16);
    invl[2] = __shfl_sync(0xffffffffu, linv, 8);
    invl[3] = __shfl_sync(0xffffffffu, linv, 24);

    // ---- phase 2: P @ V ----
    float4 acc[4];
#pragma unroll
    for (int qq = 0; qq < 4; qq++) acc[qq] = make_float4(0.f, 0.f, 0.f, 0.f);

#pragma unroll
    for (int jb = 0; jb < 4; jb++) {
        const int jbase = lo + jb * 32;
        if (jbase > hi) break;
#pragma unroll
        for (int r = 0; r < 4; r++) {
            const int rbase = jbase + 8 * r;
            if (rbase > hi) break;
            for (int p = 0; p < 8; p++) {
                const int j = rbase + p;
                if (j > hi) break;
                float4 vv = *(const float4*)(v + (head + j) * 128 + lane * 4);
                const float w0 = __shfl_sync(0xffffffffu, sc[jb][r], p);
                const float w1 = __shfl_sync(0xffffffffu, sc[jb][r], 16 + p);
                const float w2 = __shfl_sync(0xffffffffu, sc[jb][r], 8 + p);
                const float w3 = __shfl_sync(0xffffffffu, sc[jb][r], 24 + p);
                acc[0].x += w0 * vv.x; acc[0].y += w0 * vv.y; acc[0].z += w0 * vv.z; acc[0].w += w0 * vv.w;
                acc[1].x += w1 * vv.x; acc[1].y += w1 * vv.y; acc[1].z += w1 * vv.z; acc[1].w += w1 * vv.w;
                acc[2].x += w2 * vv.x; acc[2].y += w2 * vv.y; acc[2].z += w2 * vv.z; acc[2].w += w2 * vv.w;
                acc[3].x += w3 * vv.x; acc[3].y += w3 * vv.y; acc[3].z += w3 * vv.z; acc[3].w += w3 * vv.w;
            }
        }
    }

#pragma unroll
    for (int qq = 0; qq < 4; qq++) {
        const size_t ob = ((size_t)(b * 1024 + i0 + qq)) * 1024 + hh * 128 + lane * 4;
        float4 r;
        if (msk[qq]) r = vmv;
        else {
            const float il = invl[qq];
            r.x = acc[qq].x * il; r.y = acc[qq].y * il;
            r.z = acc[qq].z * il; r.w = acc[qq].w * il;
        }
        *(hf2*)(ctxHi + ob)     = __floats2half2_rn(r.x, r.y);
        *(hf2*)(ctxHi + ob + 2) = __floats2half2_rn(r.z, r.w);
    }
}

// -------------------- launch --------------------
extern "C" void kernel_launch(void* const* d_in, const int* in_sizes, int n_in,
                              void* d_out, int out_size)
{
    const float* x     = (const float*)d_in[0];
    const int*   xlen  = (const int*)  d_in[1];
    const float* Wp    = (const float*)d_in[2];
    const float* bp    = (const float*)d_in[3];
    const float* ln1_s = (const float*)d_in[4];
    const float* ln1_b = (const float*)d_in[5];
    const float* Wq    = (const float*)d_in[6];
    const float* bq    = (const float*)d_in[7];
    const float* Wk    = (const float*)d_in[8];
    const float* bk    = (const float*)d_in[9];
    const float* Wv    = (const float*)d_in[10];
    const float* bv    = (const float*)d_in[11];
    const float* Wo    = (const float*)d_in[12];
    const float* bo    = (const float*)d_in[13];
    const float* ln2_s = (const float*)d_in[14];
    const float* ln2_b = (const float*)d_in[15];
    const float* W1    = (const float*)d_in[16];
    const float* b1    = (const float*)d_in[17];
    const float* W2    = (const float*)d_in[18];
    const float* b2    = (const float*)d_in[19];
    const float* lnf_s = (const float*)d_in[20];
    const float* lnf_b = (const float*)d_in[21];
    float* out = (float*)d_out;

    float *h, *q, *k, *v, *vmean, *rc, *rs;
    hf *xhi, *yhi, *chi, *fhi, *w;
    cudaGetSymbolAddress((void**)&h,    g_h);
    cudaGetSymbolAddress((void**)&q,    g_q);
    cudaGetSymbolAddress((void**)&k,    g_k);
    cudaGetSymbolAddress((void**)&v,    g_v);
    cudaGetSymbolAddress((void**)&vmean,g_vmean);
    cudaGetSymbolAddress((void**)&rc,   g_rcos);
    cudaGetSymbolAddress((void**)&rs,   g_rsin);
    cudaGetSymbolAddress((void**)&xhi,  g_xhi);
    cudaGetSymbolAddress((void**)&yhi,  g_yhi);
    cudaGetSymbolAddress((void**)&chi,  g_chi);
    cudaGetSymbolAddress((void**)&fhi,  g_fhi);
    cudaGetSymbolAddress((void**)&w,    g_w);

    cudaFuncSetAttribute((const void*)mma_gemm<EP_PROJ, 1>,  cudaFuncAttributeMaxDynamicSharedMemorySize, GEMM_SMEM);
    cudaFuncSetAttribute((const void*)mma_gemm<EP_QKV, 1>,   cudaFuncAttributeMaxDynamicSharedMemorySize, GEMM_SMEM);
    cudaFuncSetAttribute((const void*)mma_gemm<EP_SILU, 1>,  cudaFuncAttributeMaxDynamicSharedMemorySize, GEMM_SMEM);
    cudaFuncSetAttribute((const void*)mma_gemm<EP_RESID, 1>, cudaFuncAttributeMaxDynamicSharedMemorySize, GEMM_SMEM);

    const dim3 blk(256);

    conv_w<<<2048, blk>>>(x, xhi);
    conv_w<<<512, blk>>>(Wp, w + WP_OFF);
    rope_table_kernel<<<256, blk>>>(rc, rs);
    conv_w_qkv<<<3072, blk>>>(Wq, Wk, Wv, w);
    conv_w3<<<9216, blk>>>(Wo, W1, W2, w);

    mma_gemm<EP_PROJ, 1><<<dim3(8, 32), blk, GEMM_SMEM>>>(
        2048, 1024, xhi, nullptr, w + WP_OFF,
        bp, nullptr, nullptr, h, nullptr, nullptr, xlen, nullptr, nullptr);

    for (int l = 0; l < L_; l++) {
        const size_t oD  = (size_t)l * D_;
        const size_t oF  = (size_t)l * F_;
        const uint32_t oQKV = QKV_OFF + (uint32_t)l * 3145728u;
        const uint32_t oWO  = WO_OFF  + (uint32_t)l * 1048576u;
        const uint32_t oW1  = W1_OFF  + (uint32_t)l * 4194304u;
        const uint32_t oW2  = W2_OFF  + (uint32_t)l * 4194304u;

        layernorm_kernel<true><<<NTOK, blk>>>(h, nullptr, yhi, ln1_s + oD, ln1_b + oD);

        mma_gemm<EP_QKV, 1><<<dim3(24, 32), blk, GEMM_SMEM>>>(
            1024, 3072, yhi, nullptr, w + oQKV,
            bq + oD, bk + oD, bv + oD, q, (hf*)k, (hf*)v, nullptr, rc, rs);

        vmean_kernel<<<B_ * H_, 1024>>>(v, vmean);
        attn_kernel<<<(B_ * H_ * S_) / 32, 256>>>(q, k, v, vmean, chi, xlen);

        mma_gemm<EP_RESID, 1><<<dim3(8, 32), blk, GEMM_SMEM>>>(
            1024, 1024, chi, nullptr, w + oWO,
            bo + oD, nullptr, nullptr, h, nullptr, nullptr, nullptr, nullptr, nullptr);

        layernorm_kernel<true><<<NTOK, blk>>>(h, nullptr, yhi, ln2_s + oD, ln2_b + oD);

        mma_gemm<EP_SILU, 1><<<dim3(32, 32), blk, GEMM_SMEM>>>(
            1024, 4096, yhi, nullptr, w + oW1,
            b1 + oF, nullptr, nullptr, nullptr, fhi, nullptr, nullptr, nullptr, nullptr);

        mma_gemm<EP_RESID, 1><<<dim3(8, 32), blk, GEMM_SMEM>>>(
            4096, 1024, fhi, nullptr, w + oW2,
            b2 + oD, nullptr, nullptr, h, nullptr, nullptr, nullptr, nullptr, nullptr);
    }

    layernorm_kernel<false><<<NTOK, blk>>>(h, out, nullptr, lnf_s, lnf_b);
}

// round 14
// speedup vs baseline: 6.2405x; 1.0508x over previous
#include <cuda_runtime.h>
#include <cuda_fp16.h>
#include <math.h>
#include <stdint.h>

// Problem constants
#define B_   4
#define S_   1024
#define D_   1024
#define F_   4096
#define H_   8
#define DH_  128
#define L_   4
#define NTOK (B_ * S_)          // 4096
#define WIN_ 100
#define LFW_ 20

typedef __half  hf;
typedef __half2 hf2;

// -------------------- scratch --------------------
__device__ float g_h [NTOK * D_];
__device__ float g_q [NTOK * D_];
__device__ float g_k [NTOK * D_];
__device__ float g_v [NTOK * D_];
__device__ float g_vmean[B_ * H_ * DH_];
__device__ float g_rcos[S_ * 64];
__device__ float g_rsin[S_ * 64];

// fp16 activation buffers
__device__ hf g_xhi[NTOK * 2048];
__device__ hf g_yhi[NTOK * D_];
__device__ hf g_chi[NTOK * D_];
__device__ hf g_fhi[NTOK * F_];

// converted weights (single fp16), offsets in elements
#define WP_OFF   0u
#define QKV_OFF  2097152u
#define WO_OFF   (QKV_OFF + 4u * 3145728u)
#define W1_OFF   (WO_OFF + 4u * 1048576u)
#define W2_OFF   (W1_OFF + 4u * 4194304u)
#define WTOT     (W2_OFF + 4u * 4194304u)
__device__ hf g_w[WTOT];

// ==================== helpers ====================
__device__ __forceinline__ uint32_t smem_u32(const void* p) {
    uint32_t a;
    asm("{ .reg .u64 t; cvta.to.shared.u64 t, %1; cvt.u32.u64 %0, t; }" : "=r"(a) : "l"(p));
    return a;
}
__device__ __forceinline__ void cp16(uint32_t saddr, const void* gaddr) {
    asm volatile("cp.async.cg.shared.global [%0], [%1], 16;" :: "r"(saddr), "l"(gaddr));
}
__device__ __forceinline__ void cp_commit() {
    asm volatile("cp.async.commit_group;" ::: "memory");
}
__device__ __forceinline__ void ldsm4(uint32_t& r0, uint32_t& r1, uint32_t& r2, uint32_t& r3,
                                      uint32_t addr) {
    asm volatile("ldmatrix.sync.aligned.m8n8.x4.shared.b16 {%0,%1,%2,%3}, [%4];"
                 : "=r"(r0), "=r"(r1), "=r"(r2), "=r"(r3) : "r"(addr));
}
__device__ __forceinline__ void ldsm4t(uint32_t& r0, uint32_t& r1, uint32_t& r2, uint32_t& r3,
                                       uint32_t addr) {
    asm volatile("ldmatrix.sync.aligned.m8n8.x4.trans.shared.b16 {%0,%1,%2,%3}, [%4];"
                 : "=r"(r0), "=r"(r1), "=r"(r2), "=r"(r3) : "r"(addr));
}
__device__ __forceinline__ void mma16816(float* d, const uint32_t* a, const uint32_t* b) {
    asm volatile(
        "mma.sync.aligned.m16n8k16.row.col.f32.f16.f16.f32 "
        "{%0,%1,%2,%3}, {%4,%5,%6,%7}, {%8,%9}, {%0,%1,%2,%3};"
        : "+f"(d[0]), "+f"(d[1]), "+f"(d[2]), "+f"(d[3])
        : "r"(a[0]), "r"(a[1]), "r"(a[2]), "r"(a[3]), "r"(b[0]), "r"(b[1]));
}

// ==================== merged converter + rope table ====================
__device__ __forceinline__ void conv_plain_range(const float* in, hf* w, int blk0, int blk)
{
    float4 v[4];
    const int base = (blk - blk0) * 1024 + threadIdx.x;
#pragma unroll
    for (int r = 0; r < 4; r++) v[r] = ((const float4*)in)[base + r * 256];
#pragma unroll
    for (int r = 0; r < 4; r++) {
        int i = base + r * 256;
        ((hf2*)w)[2 * i]     = __floats2half2_rn(v[r].x, v[r].y);
        ((hf2*)w)[2 * i + 1] = __floats2half2_rn(v[r].z, v[r].w);
    }
}
// grid = 2048 (x) + 512 (Wp) + 3072 (QKV) + 9216 (Wo/W1/W2) + 256 (rope) = 15104
__global__ void __launch_bounds__(256)
conv_all(const float* __restrict__ x,   const float* __restrict__ Wp,
         const float* __restrict__ Wq,  const float* __restrict__ Wk,
         const float* __restrict__ Wv,  const float* __restrict__ Wo,
         const float* __restrict__ W1,  const float* __restrict__ W2,
         hf* __restrict__ xhi, hf* __restrict__ w,
         float* __restrict__ rc, float* __restrict__ rs)
{
    const int blk = blockIdx.x;
    if (blk < 2048) {
        conv_plain_range(x, xhi, 0, blk);
    } else if (blk < 2560) {
        conv_plain_range(Wp, w + WP_OFF, 2048, blk);
    } else if (blk < 5632) {
        const int sub = blk - 2560;
        const float* in = (sub < 1024) ? Wq : (sub < 2048) ? Wk : Wv;
        const int coff = (sub < 1024) ? 0 : (sub < 2048) ? 1024 : 2048;
        const int sub0 = (sub < 1024) ? 0 : (sub < 2048) ? 1024 : 2048;
        float4 v[4];
        const int base = (sub - sub0) * 1024 + threadIdx.x;
#pragma unroll
        for (int r = 0; r < 4; r++) v[r] = ((const float4*)in)[base + r * 256];
#pragma unroll
        for (int r = 0; r < 4; r++) {
            int i = base + r * 256;
            int row = i >> 8, c4 = i & 255;
            size_t o2 = ((size_t)row * 3072 + coff + c4 * 4) >> 1;
            ((hf2*)(w + QKV_OFF))[o2]     = __floats2half2_rn(v[r].x, v[r].y);
            ((hf2*)(w + QKV_OFF))[o2 + 1] = __floats2half2_rn(v[r].z, v[r].w);
        }
    } else if (blk < 14848) {
        const int sub = blk - 5632;
        if (sub < 1024)      conv_plain_range(Wo, w + WO_OFF, 0,    sub);
        else if (sub < 5120) conv_plain_range(W1, w + W1_OFF, 1024, sub);
        else                 conv_plain_range(W2, w + W2_OFF, 5120, sub);
    } else {
        const int idx = (blk - 14848) * 256 + threadIdx.x;   // 0..65535
        const int p = idx & 63;
        const int s = idx >> 6;
        float inv_freq = expf(-(float)p * (9.210340371976184f / 64.f));
        float ang = (float)s * inv_freq;
        float sn, cs;
        sincosf(ang, &sn, &cs);
        rc[idx] = cs;
        rs[idx] = sn;
    }
}

// ==================== pipelined fp16 GEMM ====================
#define EP_PROJ  1
#define EP_QKV   2
#define EP_RESID 3
#define EP_SILU  4

#define A_PITCH 144
#define B_PITCH 272
#define OFF_AH 0
#define OFF_AL 18432
#define OFF_B  36864
#define STAGE_B 54272
#define GEMM_SMEM (2 * STAGE_B)   // 108544

template <int NT>
__device__ __forceinline__ void stage_load(
    uint32_t stb, const hf* Ah, const hf* Al, const hf* Bw,
    int k0, int bm, int bn, int K, int NN, int tid)
{
#pragma unroll
    for (int t = 0; t < 4; t++) {
        const int idx = t * 256 + tid;
        const int row = idx >> 3, seg = idx & 7;
        const size_t go = (size_t)(bm + row) * K + k0 + seg * 8;
        const uint32_t so = stb + (uint32_t)row * A_PITCH + seg * 16;
        cp16(so + OFF_AH, Ah + go);
        if (NT == 2) cp16(so + OFF_AL, Al + go);
    }
#pragma unroll
    for (int t = 0; t < 4; t++) {
        const int idx = t * 256 + tid;
        const int row = idx >> 4, seg = idx & 15;
        const size_t go = (size_t)(k0 + row) * NN + bn + seg * 8;
        const uint32_t so = stb + (uint32_t)row * B_PITCH + seg * 16;
        cp16(so + OFF_B, Bw + go);
    }
}

template <int MODE, int NT>
__global__ void __launch_bounds__(256, 2)
mma_gemm(int K, int NN,
         const hf* __restrict__ Ah, const hf* __restrict__ Al,
         const hf* __restrict__ Bw,
         const float* __restrict__ bias, const float* __restrict__ bias2,
         const float* __restrict__ bias3,
         float* __restrict__ out, hf* __restrict__ outHi, hf* __restrict__ outLo,
         const int* __restrict__ x_lengths,
         const float* __restrict__ rc, const float* __restrict__ rs)
{
    extern __shared__ char sm[];
    const uint32_t sb = smem_u32(sm);
    const int tid  = threadIdx.x;
    const int wid  = tid >> 5;
    const int lane = tid & 31;
    const int bn = blockIdx.x * 128;
    const int bm = blockIdx.y * 128;
    const int wm = wid & 1;
    const int wn = wid >> 1;

    float acc[4][4][4];
#pragma unroll
    for (int i = 0; i < 4; i++)
#pragma unroll
        for (int j = 0; j < 4; j++)
#pragma unroll
            for (int r = 0; r < 4; r++) acc[i][j][r] = 0.f;

    const int quad = lane >> 3;
    const int qr   = lane & 7;
    const uint32_t aOffH = OFF_AH + (uint32_t)(wm * 64 + (quad & 1) * 8 + qr) * A_PITCH + (quad >> 1) * 16;
    const uint32_t bOff  = OFF_B + (uint32_t)((quad & 1) * 8 + qr) * B_PITCH
                         + (uint32_t)(wn * 32 + (quad >> 1) * 8) * 2;

    const int nch = K >> 6;

    stage_load<NT>(sb, Ah, Al, Bw, 0, bm, bn, K, NN, tid);
    cp_commit();
    if (nch > 1) {
        stage_load<NT>(sb + STAGE_B, Ah, Al, Bw, 64, bm, bn, K, NN, tid);
        cp_commit();
    }

    for (int c = 0; c < nch; c++) {
        if (c < nch - 1) asm volatile("cp.async.wait_group 1;" ::: "memory");
        else             asm volatile("cp.async.wait_group 0;" ::: "memory");
        __syncthreads();

        const uint32_t stb = sb + (uint32_t)(c & 1) * STAGE_B;

#pragma unroll
        for (int ks = 0; ks < 4; ks++) {
            uint32_t aH[4][4], aL[4][4], bF[4][2];
#pragma unroll
            for (int mi = 0; mi < 4; mi++) {
                const uint32_t ad = stb + aOffH + (uint32_t)mi * (16 * A_PITCH) + ks * 32;
                ldsm4(aH[mi][0], aH[mi][1], aH[mi][2], aH[mi][3], ad);
                if (NT == 2)
                    ldsm4(aL[mi][0], aL[mi][1], aL[mi][2], aL[mi][3], ad + (OFF_AL - OFF_AH));
            }
#pragma unroll
            for (int bp = 0; bp < 2; bp++) {
                const uint32_t ad = stb + bOff + (uint32_t)ks * (16 * B_PITCH) + bp * 32;
                uint32_t r0, r1, r2, r3;
                ldsm4t(r0, r1, r2, r3, ad);
                bF[2 * bp][0] = r0; bF[2 * bp][1] = r1;
                bF[2 * bp + 1][0] = r2; bF[2 * bp + 1][1] = r3;
            }
#pragma unroll
            for (int mi = 0; mi < 4; mi++)
#pragma unroll
                for (int ni = 0; ni < 4; ni++) {
                    mma16816(acc[mi][ni], aH[mi], bF[ni]);
                    if (NT == 2) mma16816(acc[mi][ni], aL[mi], bF[ni]);
                }
        }
        __syncthreads();

        if (c + 2 < nch) {
            stage_load<NT>(stb, Ah, Al, Bw, (c + 2) << 6, bm, bn, K, NN, tid);
            cp_commit();
        }
    }

    // ---- epilogue ----
    const int grp = lane >> 2;
    const int qc  = (lane & 3) * 2;

    if (MODE == EP_QKV) {
        float* sf = (float*)sm;   // 128 x 132 floats
#pragma unroll
        for (int mi = 0; mi < 4; mi++) {
#pragma unroll
            for (int ni = 0; ni < 4; ni++) {
                const int n = bn + wn * 32 + ni * 8 + qc;
                const int sel0 = n >> 10;
                const float* bp = (sel0 == 0) ? bias : (sel0 == 1) ? bias2 : bias3;
                float2 bsv = *(const float2*)(bp + (n & 1023));
                const int nl = wn * 32 + ni * 8 + qc;
#pragma unroll
                for (int half = 0; half < 2; half++) {
                    const int ml = wm * 64 + mi * 16 + grp + half * 8;
                    float2 v;
                    v.x = acc[mi][ni][2 * half + 0] + bsv.x;
                    v.y = acc[mi][ni][2 * half + 1] + bsv.y;
                    *(float2*)&sf[ml * 132 + nl] = v;
                }
            }
        }
        __syncthreads();

        const int sel = bn >> 10;
        const int hh  = (bn & 1023) >> 7;
        float* dst = (sel == 0) ? out : (sel == 1) ? (float*)outHi : (float*)outLo;
#pragma unroll
        for (int e = 0; e < 16; e++) {
            const int lin = e * 256 + tid;
            const int row = lin >> 5;
            const int dh0 = (lin & 31) * 4;
            const int sg  = bm + row;
            const int b = sg >> 10, s = sg & 1023;
            float4 xv = *(float4*)&sf[row * 132 + dh0];
            float4 o;
            if (sel == 2) {
                o = xv;
            } else {
                const int p = dh0 & 63;
                float4 pr = *(float4*)&sf[row * 132 + (dh0 ^ 64)];
                float4 cs = *(const float4*)(rc + (s << 6) + p);
                float4 sn = *(const float4*)(rs + (s << 6) + p);
                if (dh0 < 64) {
                    o.x = xv.x * cs.x - pr.x * sn.x;
                    o.y = xv.y * cs.y - pr.y * sn.y;
                    o.z = xv.z * cs.z - pr.z * sn.z;
                    o.w = xv.w * cs.w - pr.w * sn.w;
                } else {
                    o.x = pr.x * sn.x + xv.x * cs.x;
                    o.y = pr.y * sn.y + xv.y * cs.y;
                    o.z = pr.z * sn.z + xv.z * cs.z;
                    o.w = pr.w * sn.w + xv.w * cs.w;
                }
            }
            *(float4*)(dst + ((size_t)((b << 3) | hh) * 1024 + s) * 128 + dh0) = o;
        }
        return;
    }

#pragma unroll
    for (int mi = 0; mi < 4; mi++) {
        const int m0 = bm + wm * 64 + mi * 16 + grp;
#pragma unroll
        for (int ni = 0; ni < 4; ni++) {
            const int n = bn + wn * 32 + ni * 8 + qc;
            float2 bsv = *(const float2*)(bias + n);
            float2 v01, v23;
            v01.x = acc[mi][ni][0] + bsv.x;
            v01.y = acc[mi][ni][1] + bsv.y;
            v23.x = acc[mi][ni][2] + bsv.x;
            v23.y = acc[mi][ni][3] + bsv.y;
#pragma unroll
            for (int half = 0; half < 2; half++) {
                const int m = m0 + half * 8;
                float2 v = half ? v23 : v01;
                if (MODE == EP_PROJ) {
                    const int b = m >> 10, s = m & 1023;
                    const int len = x_lengths[b] >> 2;
                    if (s >= len) { v.x = 0.f; v.y = 0.f; }
                    *(float2*)(out + (size_t)m * NN + n) = v;
                } else if (MODE == EP_RESID) {
                    float2 o = *(float2*)(out + (size_t)m * NN + n);
                    o.x += v.x; o.y += v.y;
                    *(float2*)(out + (size_t)m * NN + n) = o;
                } else { // EP_SILU
                    v.x = v.x / (1.f + __expf(-v.x));
                    v.y = v.y / (1.f + __expf(-v.y));
                    const size_t o2 = ((size_t)m * NN + n) >> 1;
                    ((hf2*)outHi)[o2] = __floats2half2_rn(v.x, v.y);
                }
            }
        }
    }
}

// -------------------- LayerNorm --------------------
template <bool HFOUT>
__global__ void __launch_bounds__(256)
layernorm_kernel(const float* __restrict__ in, float* __restrict__ out,
                 hf* __restrict__ outHi,
                 const float* __restrict__ scale, const float* __restrict__ bias)
{
    __shared__ float sh1[8];
    __shared__ float sh2[8];
    const int row = blockIdx.x;
    const int t = threadIdx.x;
    const int lane = t & 31, w = t >> 5;
    const float* xr = in + (size_t)row * 1024;

    float4 vals = *(const float4*)(xr + 4 * t);
    float s = vals.x + vals.y + vals.z + vals.w;
#pragma unroll
    for (int o = 16; o; o >>= 1) s += __shfl_xor_sync(0xffffffffu, s, o);
    if (lane == 0) sh1[w] = s;
    __syncthreads();
    float tot = (t < 8) ? sh1[t] : 0.f;
    if (w == 0) {
#pragma unroll
        for (int o = 16; o; o >>= 1) tot += __shfl_xor_sync(0xffffffffu, tot, o);
        if (lane == 0) sh1[0] = tot;
    }
    __syncthreads();
    const float mean = sh1[0] * (1.f / 1024.f);

    float dx = vals.x - mean, dy = vals.y - mean, dz = vals.z - mean, dw = vals.w - mean;
    float vs = dx * dx + dy * dy + dz * dz + dw * dw;
#pragma unroll
    for (int o = 16; o; o >>= 1) vs += __shfl_xor_sync(0xffffffffu, vs, o);
    if (lane == 0) sh2[w] = vs;
    __syncthreads();
    float vtot = (t < 8) ? sh2[t] : 0.f;
    if (w == 0) {
#pragma unroll
        for (int o = 16; o; o >>= 1) vtot += __shfl_xor_sync(0xffffffffu, vtot, o);
        if (lane == 0) sh2[0] = vtot;
    }
    __syncthreads();
    const float var = sh2[0] * (1.f / 1024.f);
    const float inv = rsqrtf(var + 1e-5f);

    float4 sc = *(const float4*)(scale + 4 * t);
    float4 bi = *(const float4*)(bias + 4 * t);
    float r0 = dx * inv * sc.x + bi.x;
    float r1 = dy * inv * sc.y + bi.y;
    float r2 = dz * inv * sc.z + bi.z;
    float r3 = dw * inv * sc.w + bi.w;
    if (HFOUT) {
        hf2* dst = (hf2*)(outHi + (size_t)row * 1024 + 4 * t);
        dst[0] = __floats2half2_rn(r0, r1);
        dst[1] = __floats2half2_rn(r2, r3);
    } else {
        float4 o = {r0, r1, r2, r3};
        *(float4*)(out + (size_t)row * 1024 + 4 * t) = o;
    }
}

// -------------------- V mean --------------------
__global__ void __launch_bounds__(1024)
vmean_kernel(const float* __restrict__ v, float* __restrict__ vmean)
{
    __shared__ float partial[8][128];
    const int bh = blockIdx.x;
    const int d  = threadIdx.x & 127;
    const int sl = threadIdx.x >> 7;
    const float* base = v + (size_t)bh * S_ * DH_ + (size_t)sl * 128 * DH_ + d;
    float s = 0.f;
#pragma unroll 4
    for (int j = 0; j < 128; j++) s += base[j * DH_];
    partial[sl][d] = s;
    __syncthreads();
    if (sl == 0) {
        float t = 0.f;
#pragma unroll
        for (int r = 0; r < 8; r++) t += partial[r][d];
        vmean[bh * DH_ + d] = t * (1.f / (float)S_);
    }
}

// -------------------- windowed attention: 4 q/warp, folded, batched LDG -----
__device__ __forceinline__ float dot_fold(const float4* qv, float4 kv,
                                          int b8, int b16) {
    float s0 = qv[0].x * kv.x + qv[0].y * kv.y + qv[0].z * kv.z + qv[0].w * kv.w;
    float s1 = qv[1].x * kv.x + qv[1].y * kv.y + qv[1].z * kv.z + qv[1].w * kv.w;
    float s2 = qv[2].x * kv.x + qv[2].y * kv.y + qv[2].z * kv.z + qv[2].w * kv.w;
    float s3 = qv[3].x * kv.x + qv[3].y * kv.y + qv[3].z * kv.z + qv[3].w * kv.w;
    s0 += __shfl_xor_sync(0xffffffffu, s0, 16);
    s1 += __shfl_xor_sync(0xffffffffu, s1, 16);
    s2 += __shfl_xor_sync(0xffffffffu, s2, 16);
    s3 += __shfl_xor_sync(0xffffffffu, s3, 16);
    float cA = b16 ? s1 : s0;
    float cB = b16 ? s3 : s2;
    cA += __shfl_xor_sync(0xffffffffu, cA, 8);
    cB += __shfl_xor_sync(0xffffffffu, cB, 8);
    float d = b8 ? cB : cA;
    d += __shfl_xor_sync(0xffffffffu, d, 4);
    d += __shfl_xor_sync(0xffffffffu, d, 2);
    d += __shfl_xor_sync(0xffffffffu, d, 1);
    return d;
}

__global__ void __launch_bounds__(256)
attn_kernel(const float* __restrict__ q, const float* __restrict__ k,
            const float* __restrict__ v, const float* __restrict__ vmean,
            hf* __restrict__ ctxHi, const int* __restrict__ x_lengths)
{
    const int g    = blockIdx.x * 8 + (threadIdx.x >> 5);
    const int lane = threadIdx.x & 31;
    const int i0 = (g & 255) * 4;
    const int hh = (g >> 8) & 7;
    const int b  = g >> 11;

    const int len = x_lengths[b] >> 2;
    const size_t head = ((size_t)(b * 8 + hh)) * 1024;
    const float scale = 0.08838834764831845f;

    int jloq[4], jhq[4];
    bool msk[4];
    int lo = 0x7fffffff, hi = -1;
    bool anyLive = false, anyMasked = false;
#pragma unroll
    for (int qq = 0; qq < 4; qq++) {
        const int i = i0 + qq;
        int jl = i - (WIN_ - 1); if (jl < 0) jl = 0;
        int jh_ = i + LFW_;      if (jh_ > S_ - 1) jh_ = S_ - 1;
        if (len - 1 < jh_) jh_ = len - 1;
        jloq[qq] = jl; jhq[qq] = jh_;
        msk[qq] = (jh_ < jl);
        if (msk[qq]) anyMasked = true;
        else { anyLive = true; if (jl < lo) lo = jl; if (jh_ > hi) hi = jh_; }
    }

    float4 vmv = {0.f, 0.f, 0.f, 0.f};
    if (anyMasked)
        vmv = *(const float4*)(vmean + (b * 8 + hh) * 128 + lane * 4);

    if (!anyLive) {
#pragma unroll
        for (int qq = 0; qq < 4; qq++) {
            const size_t ob = ((size_t)(b * 1024 + i0 + qq)) * 1024 + hh * 128 + lane * 4;
            *(hf2*)(ctxHi + ob)     = __floats2half2_rn(vmv.x, vmv.y);
            *(hf2*)(ctxHi + ob + 2) = __floats2half2_rn(vmv.z, vmv.w);
        }
        return;
    }

    float4 qv[4];
#pragma unroll
    for (int qq = 0; qq < 4; qq++)
        qv[qq] = *(const float4*)(q + (head + i0 + qq) * 128 + lane * 4);

    const int pp  = lane & 7;
    const int b8  = lane & 8;
    const int b16 = lane & 16;
    const int jlo_own = b16 ? (b8 ? jloq[3] : jloq[1]) : (b8 ? jloq[2] : jloq[0]);
    const int jhi_own = b16 ? (b8 ? jhq[3] : jhq[1]) : (b8 ? jhq[2] : jhq[0]);

    float sc[4][4];
#pragma unroll
    for (int jb = 0; jb < 4; jb++)
#pragma unroll
        for (int r = 0; r < 4; r++) sc[jb][r] = -1e30f;

    // ---- phase 1: scores (batched full 8-blocks + scalar tail) ----
#pragma unroll
    for (int jb = 0; jb < 4; jb++) {
        const int jbase = lo + jb * 32;
        if (jbase > hi) break;
#pragma unroll
        for (int r = 0; r < 4; r++) {
            const int rbase = jbase + 8 * r;
            if (rbase > hi) break;
            if (rbase + 7 <= hi) {
                float4 kvb[8];
#pragma unroll
                for (int p = 0; p < 8; p++)
                    kvb[p] = *(const float4*)(k + (head + rbase + p) * 128 + lane * 4);
#pragma unroll
                for (int p = 0; p < 8; p++) {
                    float d = dot_fold(qv, kvb[p], b8, b16);
                    if (p == pp) sc[jb][r] = d * scale;
                }
            } else {
                for (int p = 0; p <= hi - rbase; p++) {
                    float4 kv = *(const float4*)(k + (head + rbase + p) * 128 + lane * 4);
                    float d = dot_fold(qv, kv, b8, b16);
                    if (p == pp) sc[jb][r] = d * scale;
                }
            }
        }
    }

    // ---- group-local softmax ----
    float m = -1e30f;
#pragma unroll
    for (int jb = 0; jb < 4; jb++)
#pragma unroll
        for (int r = 0; r < 4; r++) {
            const int j = lo + jb * 32 + 8 * r + pp;
            const bool ok = (j >= jlo_own) && (j <= jhi_own);
            const float val = ok ? sc[jb][r] : -1e30f;
            sc[jb][r] = val;
            m = fmaxf(m, val);
        }
    m = fmaxf(m, __shfl_xor_sync(0xffffffffu, m, 4));
    m = fmaxf(m, __shfl_xor_sync(0xffffffffu, m, 2));
    m = fmaxf(m, __shfl_xor_sync(0xffffffffu, m, 1));

    float l = 0.f;
#pragma unroll
    for (int jb = 0; jb < 4; jb++)
#pragma unroll
        for (int r = 0; r < 4; r++) {
            const float pe = (sc[jb][r] > -1e29f) ? __expf(sc[jb][r] - m) : 0.f;
            sc[jb][r] = pe;
            l += pe;
        }
    l += __shfl_xor_sync(0xffffffffu, l, 4);
    l += __shfl_xor_sync(0xffffffffu, l, 2);
    l += __shfl_xor_sync(0xffffffffu, l, 1);
    const float linv = 1.f / l;

    float invl[4];
    invl[0] = __shfl_sync(0xffffffffu, linv, 0);
    invl[1] = __shfl_sync(0xffffffffu, linv, 16);
    invl[2] = __shfl_sync(0xffffffffu, linv, 8);
    invl[3] = __shfl_sync(0xffffffffu, linv, 24);

    // ---- phase 2: P @ V (batched full 8-blocks + scalar tail) ----
    float4 acc[4];
#pragma unroll
    for (int qq = 0; qq < 4; qq++) acc[qq] = make_float4(0.f, 0.f, 0.f, 0.f);

#pragma unroll
    for (int jb = 0; jb < 4; jb++) {
        const int jbase = lo + jb * 32;
        if (jbase > hi) break;
#pragma unroll
        for (int r = 0; r < 4; r++) {
            const int rbase = jbase + 8 * r;
            if (rbase > hi) break;
            if (rbase + 7 <= hi) {
                float4 vvb[8];
#pragma unroll
                for (int p = 0; p < 8; p++)
                    vvb[p] = *(const float4*)(v + (head + rbase + p) * 128 + lane * 4);
#pragma unroll
                for (int p = 0; p < 8; p++) {
                    const float w0 = __shfl_sync(0xffffffffu, sc[jb][r], p);
                    const float w1 = __shfl_sync(0xffffffffu, sc[jb][r], 16 + p);
                    const float w2 = __shfl_sync(0xffffffffu, sc[jb][r], 8 + p);
                    const float w3 = __shfl_sync(0xffffffffu, sc[jb][r], 24 + p);
                    acc[0].x += w0 * vvb[p].x; acc[0].y += w0 * vvb[p].y;
                    acc[0].z += w0 * vvb[p].z; acc[0].w += w0 * vvb[p].w;
                    acc[1].x += w1 * vvb[p].x; acc[1].y += w1 * vvb[p].y;
                    acc[1].z += w1 * vvb[p].z; acc[1].w += w1 * vvb[p].w;
                    acc[2].x += w2 * vvb[p].x; acc[2].y += w2 * vvb[p].y;
                    acc[2].z += w2 * vvb[p].z; acc[2].w += w2 * vvb[p].w;
                    acc[3].x += w3 * vvb[p].x; acc[3].y += w3 * vvb[p].y;
                    acc[3].z += w3 * vvb[p].z; acc[3].w += w3 * vvb[p].w;
                }
            } else {
                for (int p = 0; p <= hi - rbase; p++) {
                    float4 vv = *(const float4*)(v + (head + rbase + p) * 128 + lane * 4);
                    const float w0 = __shfl_sync(0xffffffffu, sc[jb][r], p);
                    const float w1 = __shfl_sync(0xffffffffu, sc[jb][r], 16 + p);
                    const float w2 = __shfl_sync(0xffffffffu, sc[jb][r], 8 + p);
                    const float w3 = __shfl_sync(0xffffffffu, sc[jb][r], 24 + p);
                    acc[0].x += w0 * vv.x; acc[0].y += w0 * vv.y;
                    acc[0].z += w0 * vv.z; acc[0].w += w0 * vv.w;
                    acc[1].x += w1 * vv.x; acc[1].y += w1 * vv.y;
                    acc[1].z += w1 * vv.z; acc[1].w += w1 * vv.w;
                    acc[2].x += w2 * vv.x; acc[2].y += w2 * vv.y;
                    acc[2].z += w2 * vv.z; acc[2].w += w2 * vv.w;
                    acc[3].x += w3 * vv.x; acc[3].y += w3 * vv.y;
                    acc[3].z += w3 * vv.z; acc[3].w += w3 * vv.w;
                }
            }
        }
    }

#pragma unroll
    for (int qq = 0; qq < 4; qq++) {
        const size_t ob = ((size_t)(b * 1024 + i0 + qq)) * 1024 + hh * 128 + lane * 4;
        float4 r;
        if (msk[qq]) r = vmv;
        else {
            const float il = invl[qq];
            r.x = acc[qq].x * il; r.y = acc[qq].y * il;
            r.z = acc[qq].z * il; r.w = acc[qq].w * il;
        }
        *(hf2*)(ctxHi + ob)     = __floats2half2_rn(r.x, r.y);
        *(hf2*)(ctxHi + ob + 2) = __floats2half2_rn(r.z, r.w);
    }
}

// -------------------- launch --------------------
extern "C" void kernel_launch(void* const* d_in, const int* in_sizes, int n_in,
                              void* d_out, int out_size)
{
    const float* x     = (const float*)d_in[0];
    const int*   xlen  = (const int*)  d_in[1];
    const float* Wp    = (const float*)d_in[2];
    const float* bp    = (const float*)d_in[3];
    const float* ln1_s = (const float*)d_in[4];
    const float* ln1_b = (const float*)d_in[5];
    const float* Wq    = (const float*)d_in[6];
    const float* bq    = (const float*)d_in[7];
    const float* Wk    = (const float*)d_in[8];
    const float* bk    = (const float*)d_in[9];
    const float* Wv    = (const float*)d_in[10];
    const float* bv    = (const float*)d_in[11];
    const float* Wo    = (const float*)d_in[12];
    const float* bo    = (const float*)d_in[13];
    const float* ln2_s = (const float*)d_in[14];
    const float* ln2_b = (const float*)d_in[15];
    const float* W1    = (const float*)d_in[16];
    const float* b1    = (const float*)d_in[17];
    const float* W2    = (const float*)d_in[18];
    const float* b2    = (const float*)d_in[19];
    const float* lnf_s = (const float*)d_in[20];
    const float* lnf_b = (const float*)d_in[21];
    float* out = (float*)d_out;

    float *h, *q, *k, *v, *vmean, *rc, *rs;
    hf *xhi, *yhi, *chi, *fhi, *w;
    cudaGetSymbolAddress((void**)&h,    g_h);
    cudaGetSymbolAddress((void**)&q,    g_q);
    cudaGetSymbolAddress((void**)&k,    g_k);
    cudaGetSymbolAddress((void**)&v,    g_v);
    cudaGetSymbolAddress((void**)&vmean,g_vmean);
    cudaGetSymbolAddress((void**)&rc,   g_rcos);
    cudaGetSymbolAddress((void**)&rs,   g_rsin);
    cudaGetSymbolAddress((void**)&xhi,  g_xhi);
    cudaGetSymbolAddress((void**)&yhi,  g_yhi);
    cudaGetSymbolAddress((void**)&chi,  g_chi);
    cudaGetSymbolAddress((void**)&fhi,  g_fhi);
    cudaGetSymbolAddress((void**)&w,    g_w);

    cudaFuncSetAttribute((const void*)mma_gemm<EP_PROJ, 1>,  cudaFuncAttributeMaxDynamicSharedMemorySize, GEMM_SMEM);
    cudaFuncSetAttribute((const void*)mma_gemm<EP_QKV, 1>,   cudaFuncAttributeMaxDynamicSharedMemorySize, GEMM_SMEM);
    cudaFuncSetAttribute((const void*)mma_gemm<EP_SILU, 1>,  cudaFuncAttributeMaxDynamicSharedMemorySize, GEMM_SMEM);
    cudaFuncSetAttribute((const void*)mma_gemm<EP_RESID, 1>, cudaFuncAttributeMaxDynamicSharedMemorySize, GEMM_SMEM);

    const dim3 blk(256);

    // single merged converter + rope table
    conv_all<<<15104, blk>>>(x, Wp, Wq, Wk, Wv, Wo, W1, W2, xhi, w, rc, rs);

    mma_gemm<EP_PROJ, 1><<<dim3(8, 32), blk, GEMM_SMEM>>>(
        2048, 1024, xhi, nullptr, w + WP_OFF,
        bp, nullptr, nullptr, h, nullptr, nullptr, xlen, nullptr, nullptr);

    for (int l = 0; l < L_; l++) {
        const size_t oD  = (size_t)l * D_;
        const size_t oF  = (size_t)l * F_;
        const uint32_t oQKV = QKV_OFF + (uint32_t)l * 3145728u;
        const uint32_t oWO  = WO_OFF  + (uint32_t)l * 1048576u;
        const uint32_t oW1  = W1_OFF  + (uint32_t)l * 4194304u;
        const uint32_t oW2  = W2_OFF  + (uint32_t)l * 4194304u;

        layernorm_kernel<true><<<NTOK, blk>>>(h, nullptr, yhi, ln1_s + oD, ln1_b + oD);

        mma_gemm<EP_QKV, 1><<<dim3(24, 32), blk, GEMM_SMEM>>>(
            1024, 3072, yhi, nullptr, w + oQKV,
            bq + oD, bk + oD, bv + oD, q, (hf*)k, (hf*)v, nullptr, rc, rs);

        vmean_kernel<<<B_ * H_, 1024>>>(v, vmean);
        attn_kernel<<<(B_ * H_ * S_) / 32, 256>>>(q, k, v, vmean, chi, xlen);

        mma_gemm<EP_RESID, 1><<<dim3(8, 32), blk, GEMM_SMEM>>>(
            1024, 1024, chi, nullptr, w + oWO,
            bo + oD, nullptr, nullptr, h, nullptr, nullptr, nullptr, nullptr, nullptr);

        layernorm_kernel<true><<<NTOK, blk>>>(h, nullptr, yhi, ln2_s + oD, ln2_b + oD);

        mma_gemm<EP_SILU, 1><<<dim3(32, 32), blk, GEMM_SMEM>>>(
            1024, 4096, yhi, nullptr, w + oW1,
            b1 + oF, nullptr, nullptr, nullptr, fhi, nullptr, nullptr, nullptr, nullptr);

        mma_gemm<EP_RESID, 1><<<dim3(8, 32), blk, GEMM_SMEM>>>(
            4096, 1024, fhi, nullptr, w + oW2,
            b2 + oD, nullptr, nullptr, h, nullptr, nullptr, nullptr, nullptr, nullptr);
    }

    layernorm_kernel<false><<<NTOK, blk>>>(h, out, nullptr, lnf_s, lnf_b);
}